// round 7
// baseline (speedup 1.0000x reference)
#include <cuda_runtime.h>
#include <cuda_bf16.h>
#include <cuda_fp16.h>
#include <cstdint>

#define NELEM 4194304          // 32*512*32*8 == 4*512*8*256
#define WSZ   2359296          // 512*4608 weight elements per conv

// ---------------------------------------------------------------------------
// device scratch
// ---------------------------------------------------------------------------
__device__ __half g_Bh[4*WSZ];          // weights fp16 hi [conv][co][t*512+ci]
__device__ __half g_Bl[4*WSZ];          // weights fp16 lo * 4096
__device__ __half g_xh[3*NELEM];        // qkv inputs fp16 hi, pixel-major
__device__ __half g_xl[3*NELEM];        // lo * 4096
__device__ __half g_sah[NELEM];         // conv_o input fp16 hi [b][p][ci]
__device__ __half g_sal[NELEM];         // lo * 4096
__device__ float  g_y2[NELEM];          // conv(v) out (32,512,32,8)
__device__ __nv_bfloat16 g_Qh[NELEM], g_Ql[NELEM];   // [n][d][c] bf16 hi/lo
__device__ __nv_bfloat16 g_Kh[NELEM], g_Kl[NELEM];
__device__ __nv_bfloat16 g_Vth[NELEM], g_Vtl[NELEM]; // transposed [n][c][dk]
__device__ __nv_bfloat16 g_ath[2*NELEM], g_atl[2*NELEM]; // attn bf16 hi/lo
__device__ float g_On[NELEM];           // attn @ V  [n][qd][c]

// ---------------------------------------------------------------------------
// helpers
// ---------------------------------------------------------------------------
__device__ __forceinline__ uint32_t smem_u32(const void* p) {
    uint32_t a;
    asm("{ .reg .u64 t; cvta.to.shared.u64 t, %1; cvt.u32.u64 %0, t; }" : "=r"(a) : "l"(p));
    return a;
}
#define SWZ(o) ((o) ^ (((o) >> 3) & 0x70))
#define CPA(dst, src, sz) \
    asm volatile("cp.async.cg.shared.global [%0], [%1], 16, %2;" \
        :: "r"(dst), "l"(src), "r"(sz) : "memory")
#define CPA_COMMIT() asm volatile("cp.async.commit_group;" ::: "memory")
#define CPA_WAIT1()  asm volatile("cp.async.wait_group 1;" ::: "memory")
#define CPA_WAIT0()  asm volatile("cp.async.wait_group 0;" ::: "memory")
#define LDM4(r, addr) \
    asm volatile("ldmatrix.sync.aligned.m8n8.x4.shared.b16 {%0,%1,%2,%3}, [%4];" \
        : "=r"((r)[0]), "=r"((r)[1]), "=r"((r)[2]), "=r"((r)[3]) : "r"(addr))
#define MMA_BF16(d, a, b0, b1) \
    asm volatile("mma.sync.aligned.m16n8k16.row.col.f32.bf16.bf16.f32 " \
        "{%0,%1,%2,%3}, {%4,%5,%6,%7}, {%8,%9}, {%0,%1,%2,%3};" \
        : "+f"((d)[0]), "+f"((d)[1]), "+f"((d)[2]), "+f"((d)[3]) \
        : "r"((a)[0]), "r"((a)[1]), "r"((a)[2]), "r"((a)[3]), "r"(b0), "r"(b1))
#define MMA_F16(d, a, b0, b1) \
    asm volatile("mma.sync.aligned.m16n8k16.row.col.f32.f16.f16.f32 " \
        "{%0,%1,%2,%3}, {%4,%5,%6,%7}, {%8,%9}, {%0,%1,%2,%3};" \
        : "+f"((d)[0]), "+f"((d)[1]), "+f"((d)[2]), "+f"((d)[3]) \
        : "r"((a)[0]), "r"((a)[1]), "r"((a)[2]), "r"((a)[3]), "r"(b0), "r"(b1))
#define MMA_F16C(d, a, b0, b1) \
    asm volatile("mma.sync.aligned.m16n8k16.row.col.f16.f16.f16.f16 " \
        "{%0,%1}, {%2,%3,%4,%5}, {%6,%7}, {%0,%1};" \
        : "+r"((d)[0]), "+r"((d)[1]) \
        : "r"((a)[0]), "r"((a)[1]), "r"((a)[2]), "r"((a)[3]), "r"(b0), "r"(b1))

// K32 chunks; packed layout: two 64B K-rows per 128B line.
// stage (32KB): Ah 0, Al 8K, Bh 16K, Bl 24K. 3 stages = 96KB -> 2 CTAs/SM.
#define STAGE 32768u
#define SMEM_BYTES 98304
#define PROW(r) ((uint32_t)((((r) >> 1) << 7) | (((r) & 1) << 6)))
#define CINV 2.44140625e-4f    // 1/4096

// ---------------------------------------------------------------------------
// conv K32 chunk: main = Ah*Bh (f32 acc); corr = Ah*Bl' + Al'*Bh (f16 acc)
// ---------------------------------------------------------------------------
__device__ __forceinline__ void mma_conv32(uint32_t bs, uint32_t a_rowb,
                                           uint32_t b_rowb, float (&acc)[16][4],
                                           uint32_t (&cacc)[16][2])
{
#pragma unroll
    for (int s = 0; s < 2; ++s) {
        uint32_t ah[4][4], bb[2][4], bl[2][4], al[4][4];
#pragma unroll
        for (int i = 0; i < 4; ++i)
            LDM4(ah[i], bs + SWZ(a_rowb + i * 1024 + s * 32));
#pragma unroll
        for (int j = 0; j < 2; ++j)
            LDM4(bb[j], bs + 16384u + SWZ(b_rowb + j * 1024 + s * 32));
#pragma unroll
        for (int i = 0; i < 4; ++i)
#pragma unroll
            for (int jj = 0; jj < 4; ++jj)
                MMA_F16(acc[i * 4 + jj], ah[i],
                        bb[jj >> 1][(jj & 1) * 2], bb[jj >> 1][(jj & 1) * 2 + 1]);
#pragma unroll
        for (int j = 0; j < 2; ++j)
            LDM4(bl[j], bs + 24576u + SWZ(b_rowb + j * 1024 + s * 32));
#pragma unroll
        for (int i = 0; i < 4; ++i)
#pragma unroll
            for (int jj = 0; jj < 4; ++jj)
                MMA_F16C(cacc[i * 4 + jj], ah[i],
                         bl[jj >> 1][(jj & 1) * 2], bl[jj >> 1][(jj & 1) * 2 + 1]);
#pragma unroll
        for (int i = 0; i < 4; ++i)
            LDM4(al[i], bs + 8192u + SWZ(a_rowb + i * 1024 + s * 32));
#pragma unroll
        for (int i = 0; i < 4; ++i)
#pragma unroll
            for (int jj = 0; jj < 4; ++jj)
                MMA_F16C(cacc[i * 4 + jj], al[i],
                         bb[jj >> 1][(jj & 1) * 2], bb[jj >> 1][(jj & 1) * 2 + 1]);
    }
}

// bf16 3-term chunk (attention GEMMs)
__device__ __forceinline__ void mma_compute32(uint32_t bs, uint32_t a_rowb,
                                              uint32_t b_rowb, float (&acc)[16][4])
{
#pragma unroll
    for (int s = 0; s < 2; ++s) {
        uint32_t ah[4][4], bb[2][4], blf[2][4];
#pragma unroll
        for (int i = 0; i < 4; ++i)
            LDM4(ah[i], bs + SWZ(a_rowb + i * 1024 + s * 32));
#pragma unroll
        for (int j = 0; j < 2; ++j)
            LDM4(bb[j], bs + 16384u + SWZ(b_rowb + j * 1024 + s * 32));
#pragma unroll
        for (int i = 0; i < 4; ++i)
#pragma unroll
            for (int jj = 0; jj < 4; ++jj)
                MMA_BF16(acc[i * 4 + jj], ah[i],
                         bb[jj >> 1][(jj & 1) * 2], bb[jj >> 1][(jj & 1) * 2 + 1]);
#pragma unroll
        for (int j = 0; j < 2; ++j)
            LDM4(blf[j], bs + 24576u + SWZ(b_rowb + j * 1024 + s * 32));
#pragma unroll
        for (int i = 0; i < 4; ++i)
#pragma unroll
            for (int jj = 0; jj < 4; ++jj)
                MMA_BF16(acc[i * 4 + jj], ah[i],
                         blf[jj >> 1][(jj & 1) * 2], blf[jj >> 1][(jj & 1) * 2 + 1]);
#pragma unroll
        for (int i = 0; i < 4; ++i)
            LDM4(ah[i], bs + 8192u + SWZ(a_rowb + i * 1024 + s * 32));
#pragma unroll
        for (int i = 0; i < 4; ++i)
#pragma unroll
            for (int jj = 0; jj < 4; ++jj)
                MMA_BF16(acc[i * 4 + jj], ah[i],
                         bb[jj >> 1][(jj & 1) * 2], bb[jj >> 1][(jj & 1) * 2 + 1]);
    }
}

// ---------------------------------------------------------------------------
// pre-pass: weights -> fp16 hi/lo' in [co][t*512+ci] layout
// ---------------------------------------------------------------------------
__global__ void prep_w(const float* __restrict__ Wq, const float* __restrict__ Wk,
                       const float* __restrict__ Wv, const float* __restrict__ Wo)
{
    int g = blockIdx.x * 256 + threadIdx.x;
    int conv = g / WSZ;
    int j = g - conv * WSZ;
    const float* W = (conv == 0) ? Wq : (conv == 1) ? Wk : (conv == 2) ? Wv : Wo;
    float v = W[j];
    int co  = j / 4608;
    int rem = j - co * 4608;
    int ci  = rem / 9;
    int t   = rem - ci * 9;
    __half h = __float2half(v);
    __half l = __float2half((v - __half2float(h)) * 4096.f);
    size_t o = (size_t)conv * WSZ + (size_t)co * 4608 + t * 512 + ci;
    g_Bh[o] = h;
    g_Bl[o] = l;
}

// ---------------------------------------------------------------------------
// pre-pass: q/k/v -> pixel-major fp16 hi/lo'
// ---------------------------------------------------------------------------
__global__ void prep_x(const float* __restrict__ q, const float* __restrict__ k,
                       const float* __restrict__ v, int zoff)
{
    __shared__ float tile[32][33];
    int zz = blockIdx.z + zoff;
    int z = zz >> 5;
    int n = zz & 31;
    const float* src = (z == 0) ? q : (z == 1) ? k : v;
    const float* xin = src + (size_t)n * 512 * 256;
    __half* oh = g_xh + (size_t)z * NELEM + (size_t)n * 256 * 512;
    __half* ol = g_xl + (size_t)z * NELEM + (size_t)n * 256 * 512;
    int p0 = blockIdx.x * 32;
    int c0 = blockIdx.y * 32;
    int tx = threadIdx.x, ty = threadIdx.y;
#pragma unroll
    for (int j = 0; j < 4; ++j)
        tile[ty + 8 * j][tx] = xin[(size_t)(c0 + ty + 8 * j) * 256 + p0 + tx];
    __syncthreads();
#pragma unroll
    for (int j = 0; j < 4; ++j) {
        float val = tile[tx][ty + 8 * j];
        __half h = __float2half(val);
        size_t o = (size_t)(p0 + ty + 8 * j) * 512 + c0 + tx;
        oh[o] = h;
        ol[o] = __float2half((val - __half2float(h)) * 4096.f);
    }
}

// ---------------------------------------------------------------------------
// fp16 pipelined implicit-GEMM conv. M=128 pix x N=128 co, warp 64x32.
// oh/ol != null: epilogue writes remapped bf16 hi/lo (Q or K). else writes y fp32.
// ---------------------------------------------------------------------------
__device__ __forceinline__ void conv_mma_pipe(
    const __half* __restrict__ xh, const __half* __restrict__ xl,
    const __half* __restrict__ bh, const __half* __restrict__ bl,
    const float* __restrict__ bias,
    __nv_bfloat16* __restrict__ oh, __nv_bfloat16* __restrict__ ol,
    float* __restrict__ y,
    int H, int W, int logW, int logPIX)
{
    extern __shared__ char smem[];
    uint32_t sb = smem_u32(smem);
    int tid = threadIdx.x, wid = tid >> 5, lane = tid & 31;
    const int HW = 1 << logPIX;
    int p0    = blockIdx.x * 128;
    int nimg  = p0 >> logPIX;
    int pbase = p0 & (HW - 1);
    int co0   = blockIdx.y * 128;
    int wm = wid & 1, wn = wid >> 1;

    int lr = tid >> 1, lh = tid & 1;
    int ap = pbase + lr;
    int ayr = ap >> logW, axr = ap & (W - 1);
    uint32_t stb = PROW(lr) + lh * 32u;
    const __half* arow_h = xh + (size_t)nimg * HW * 512 + lh * 16;
    const __half* arow_l = xl + (size_t)nimg * HW * 512 + lh * 16;
    const __half* brow_h = bh + (size_t)(co0 + lr) * 4608 + lh * 16;
    const __half* brow_l = bl + (size_t)(co0 + lr) * 4608 + lh * 16;

    int arow = wm * 64 + (lane & 15);
    uint32_t a_rowb = PROW(arow) + ((lane & 16) ? 16u : 0u);
    int brow = wn * 32 + (lane & 7) + ((lane & 16) ? 8 : 0);
    uint32_t b_rowb = PROW(brow) + ((lane & 8) ? 16u : 0u);

    float acc[16][4];
    uint32_t cacc[16][2];
#pragma unroll
    for (int i = 0; i < 16; ++i) {
#pragma unroll
        for (int j = 0; j < 4; ++j) acc[i][j] = 0.f;
        cacc[i][0] = 0u; cacc[i][1] = 0u;
    }

    auto prefetch = [&](int itn, int stg) {
        int t = itn >> 4, ci0 = (itn & 15) << 5;
        int q3 = (t * 11) >> 5;
        int dy = q3 - 1, dx = t - q3 * 3 - 1;
        int yy = ayr + dy, xx = axr + dx;
        bool ok = ((unsigned)yy < (unsigned)H) && ((unsigned)xx < (unsigned)W);
        int pps = ok ? ((yy << logW) + xx) : 0;
        const char* sAh = (const char*)(arow_h + (size_t)pps * 512 + ci0);
        const char* sAl = (const char*)(arow_l + (size_t)pps * 512 + ci0);
        const char* sBh = (const char*)(brow_h + t * 512 + ci0);
        const char* sBl = (const char*)(brow_l + t * 512 + ci0);
        uint32_t bs = sb + (uint32_t)stg * STAGE;
        uint32_t asz = ok ? 16u : 0u;
        uint32_t s0 = SWZ(stb), s1 = SWZ(stb + 16u);
        CPA(bs + s0,          sAh,      asz);
        CPA(bs + s1,          sAh + 16, asz);
        CPA(bs + 8192u + s0,  sAl,      asz);
        CPA(bs + 8192u + s1,  sAl + 16, asz);
        CPA(bs + 16384u + s0, sBh,      16u);
        CPA(bs + 16384u + s1, sBh + 16, 16u);
        CPA(bs + 24576u + s0, sBl,      16u);
        CPA(bs + 24576u + s1, sBl + 16, 16u);
        CPA_COMMIT();
    };

    prefetch(0, 0);
    prefetch(1, 1);
    int stg = 0;
    for (int it = 0; it < 144; ++it) {
        if (it < 143) CPA_WAIT1(); else CPA_WAIT0();
        __syncthreads();
        if (it + 2 < 144) {
            int nst = stg + 2; if (nst >= 3) nst -= 3;
            prefetch(it + 2, nst);
        }
        mma_conv32(sb + (uint32_t)stg * STAGE, a_rowb, b_rowb, acc, cacc);
        if (++stg == 3) stg = 0;
    }
    __syncthreads();

    // merge main + corr/4096, stage via SMEM (128 x 130 fp32)
    float* sf = (float*)smem;
#pragma unroll
    for (int i = 0; i < 4; ++i) {
        int row = wm * 64 + i * 16 + (lane >> 2);
#pragma unroll
        for (int jj = 0; jj < 4; ++jj) {
            int t = i * 4 + jj;
            int col = wn * 32 + jj * 8 + (lane & 3) * 2;
            float2 c01 = __half22float2(*(__half2*)&cacc[t][0]);
            float2 c23 = __half22float2(*(__half2*)&cacc[t][1]);
            *(float2*)&sf[row * 130 + col] =
                make_float2(acc[t][0] + c01.x * CINV, acc[t][1] + c01.y * CINV);
            *(float2*)&sf[(row + 8) * 130 + col] =
                make_float2(acc[t][2] + c23.x * CINV, acc[t][3] + c23.y * CINV);
        }
    }
    __syncthreads();

    if (oh) {
        // fused remap: (nimg, co, pp) -> [n][d][c] bf16 hi/lo
        int hh = nimg >> 2;
#pragma unroll 4
        for (int i = 0; i < 64; ++i) {
            int idx = i * 256 + tid;
            int cl = idx >> 7, pl = idx & 127;
            int co = co0 + cl;
            int pp = pbase + pl;
            float val = sf[pl * 130 + cl] + bias[co];
            int nn = (nimg & 3) * 8 + (co >> 6);
            int d  = (co & 63) * 8 + (pp >> 5);
            int c  = hh * 32 + (pp & 31);
            size_t o = ((size_t)nn * 512 + d) * 256 + c;
            __nv_bfloat16 vh = __float2bfloat16(val);
            oh[o] = vh;
            ol[o] = __float2bfloat16(val - __bfloat162float(vh));
        }
    } else {
        int pl = tid & 127, co2 = tid >> 7;
        float* yb = y + (size_t)nimg * 512 * HW + pbase + pl;
#pragma unroll 4
        for (int c = 0; c < 64; ++c) {
            int cl = c * 2 + co2;
            yb[(size_t)(co0 + cl) * HW] = sf[pl * 130 + cl] + bias[co0 + cl];
        }
    }
}

__global__ __launch_bounds__(256, 2) void conv_qkv_mma(
    const float* __restrict__ bq, const float* __restrict__ bk, const float* __restrict__ bv)
{
    int z = blockIdx.z;
    const float* bias = (z == 0) ? bq : (z == 1) ? bk : bv;
    __nv_bfloat16* oh = (z == 0) ? g_Qh : (z == 1) ? g_Kh : nullptr;
    __nv_bfloat16* ol = (z == 0) ? g_Ql : (z == 1) ? g_Kl : nullptr;
    conv_mma_pipe(g_xh + (size_t)z * NELEM, g_xl + (size_t)z * NELEM,
                  g_Bh + (size_t)z * WSZ, g_Bl + (size_t)z * WSZ,
                  bias, oh, ol, g_y2, 32, 8, 3, 8);
}

__global__ __launch_bounds__(256, 2) void conv_o_mma(const float* __restrict__ bo,
                                                     float* __restrict__ out)
{
    conv_mma_pipe(g_sah, g_sal, g_Bh + 3ull * WSZ, g_Bl + 3ull * WSZ,
                  bo, nullptr, nullptr, out, 8, 256, 8, 11);
}

// ---------------------------------------------------------------------------
// bf16 3-term pipelined GEMM: C(MxN) = A(MxK) * B(NxK)^T  (attention)
// ---------------------------------------------------------------------------
__device__ __forceinline__ void gemm_mma_pipe(
    const __nv_bfloat16* __restrict__ Ah, const __nv_bfloat16* __restrict__ Al,
    const __nv_bfloat16* __restrict__ Bh, const __nv_bfloat16* __restrict__ Bl,
    int Kdim, int nchunk, float* __restrict__ C, int ldc)
{
    extern __shared__ char smem[];
    uint32_t sb = smem_u32(smem);
    int tid = threadIdx.x, wid = tid >> 5, lane = tid & 31;
    int m0 = blockIdx.y * 128, n0 = blockIdx.x * 128;
    int wm = wid & 1, wn = wid >> 1;

    int lr = tid >> 1, lh = tid & 1;
    uint32_t stb = PROW(lr) + lh * 32u;
    const char* srcA_h = (const char*)(Ah + (size_t)(m0 + lr) * Kdim + lh * 16);
    const char* srcA_l = (const char*)(Al + (size_t)(m0 + lr) * Kdim + lh * 16);
    const char* srcB_h = (const char*)(Bh + (size_t)(n0 + lr) * Kdim + lh * 16);
    const char* srcB_l = (const char*)(Bl + (size_t)(n0 + lr) * Kdim + lh * 16);

    int arow = wm * 64 + (lane & 15);
    uint32_t a_rowb = PROW(arow) + ((lane & 16) ? 16u : 0u);
    int brow = wn * 32 + (lane & 7) + ((lane & 16) ? 8 : 0);
    uint32_t b_rowb = PROW(brow) + ((lane & 8) ? 16u : 0u);

    float acc[16][4];
#pragma unroll
    for (int i = 0; i < 16; ++i)
#pragma unroll
        for (int j = 0; j < 4; ++j) acc[i][j] = 0.f;

    auto prefetch = [&](int itn, int stg) {
        int cb = itn * 64;
        uint32_t bs = sb + (uint32_t)stg * STAGE;
        uint32_t s0 = SWZ(stb), s1 = SWZ(stb + 16u);
        CPA(bs + s0,          srcA_h + cb,      16u);
        CPA(bs + s1,          srcA_h + cb + 16, 16u);
        CPA(bs + 8192u + s0,  srcA_l + cb,      16u);
        CPA(bs + 8192u + s1,  srcA_l + cb + 16, 16u);
        CPA(bs + 16384u + s0, srcB_h + cb,      16u);
        CPA(bs + 16384u + s1, srcB_h + cb + 16, 16u);
        CPA(bs + 24576u + s0, srcB_l + cb,      16u);
        CPA(bs + 24576u + s1, srcB_l + cb + 16, 16u);
        CPA_COMMIT();
    };

    prefetch(0, 0);
    prefetch(1, 1);
    int stg = 0;
    for (int it = 0; it < nchunk; ++it) {
        if (it < nchunk - 1) CPA_WAIT1(); else CPA_WAIT0();
        __syncthreads();
        if (it + 2 < nchunk) {
            int nst = stg + 2; if (nst >= 3) nst -= 3;
            prefetch(it + 2, nst);
        }
        mma_compute32(sb + (uint32_t)stg * STAGE, a_rowb, b_rowb, acc);
        if (++stg == 3) stg = 0;
    }

#pragma unroll
    for (int i = 0; i < 4; ++i) {
        int row = m0 + wm * 64 + i * 16 + (lane >> 2);
#pragma unroll
        for (int jj = 0; jj < 4; ++jj) {
            int col = n0 + wn * 32 + jj * 8 + (lane & 3) * 2;
            float* d = acc[i * 4 + jj];
            *(float2*)&C[(size_t)row * ldc + col]       = make_float2(d[0], d[1]);
            *(float2*)&C[(size_t)(row + 8) * ldc + col] = make_float2(d[2], d[3]);
        }
    }
}

__global__ __launch_bounds__(256, 2) void gemm_scores(float* __restrict__ attn)
{
    int nb = blockIdx.z;
    gemm_mma_pipe(g_Qh + (size_t)nb * 131072, g_Ql + (size_t)nb * 131072,
                  g_Kh + (size_t)nb * 131072, g_Kl + (size_t)nb * 131072,
                  256, 8, attn + (size_t)nb * 262144, 512);
}

__global__ __launch_bounds__(256, 2) void gemm_nnout()
{
    int nb = blockIdx.z;
    gemm_mma_pipe(g_ath + (size_t)nb * 262144, g_atl + (size_t)nb * 262144,
                  g_Vth + (size_t)nb * 131072, g_Vtl + (size_t)nb * 131072,
                  512, 16, g_On + (size_t)nb * 131072, 256);
}

// ---------------------------------------------------------------------------
// V transpose remap: g_y2 -> Vt bf16 hi/lo [n][c][dk]
// ---------------------------------------------------------------------------
__global__ void remap_V()
{
    int e = blockIdx.x * 256 + threadIdx.x;
    int n = e >> 17, c = (e >> 9) & 255, dk = e & 511;
    int h = c >> 5, r = c & 31;
    float v = g_y2[(h * 4 + (n >> 3)) * 131072 + ((n & 7) * 64 + (dk >> 3)) * 256
                   + (dk & 7) * 32 + r];
    __nv_bfloat16 hh = __float2bfloat16(v);
    g_Vth[e] = hh;
    g_Vtl[e] = __float2bfloat16(v - __bfloat162float(hh));
}

// ---------------------------------------------------------------------------
// softmax over 512-wide rows, in place; also emit bf16 hi/lo
// ---------------------------------------------------------------------------
__global__ void softmax_rows(float* __restrict__ attn)
{
    size_t base = (size_t)blockIdx.x * 512;
    float* p = attn + base;
    int tid = threadIdx.x;
    float v0 = p[tid], v1 = p[tid + 256];
    float m = fmaxf(v0, v1);
#pragma unroll
    for (int o = 16; o; o >>= 1) m = fmaxf(m, __shfl_xor_sync(~0u, m, o));
    __shared__ float sm[8], ss[8];
    if ((tid & 31) == 0) sm[tid >> 5] = m;
    __syncthreads();
    if (tid < 8) {
        float mm = sm[tid];
#pragma unroll
        for (int o = 4; o; o >>= 1) mm = fmaxf(mm, __shfl_xor_sync(0xffu, mm, o));
        if (tid == 0) sm[0] = mm;
    }
    __syncthreads();
    float M = sm[0];
    float e0 = expf(v0 - M), e1 = expf(v1 - M);
    float s = e0 + e1;
#pragma unroll
    for (int o = 16; o; o >>= 1) s += __shfl_xor_sync(~0u, s, o);
    if ((tid & 31) == 0) ss[tid >> 5] = s;
    __syncthreads();
    if (tid < 8) {
        float t2 = ss[tid];
#pragma unroll
        for (int o = 4; o; o >>= 1) t2 += __shfl_xor_sync(0xffu, t2, o);
        if (tid == 0) ss[0] = t2;
    }
    __syncthreads();
    float inv = 1.f / ss[0];
    float a0 = e0 * inv, a1 = e1 * inv;
    p[tid] = a0;
    p[tid + 256] = a1;
    __nv_bfloat16 h0 = __float2bfloat16(a0), h1 = __float2bfloat16(a1);
    g_ath[base + tid]       = h0;
    g_atl[base + tid]       = __float2bfloat16(a0 - __bfloat162float(h0));
    g_ath[base + tid + 256] = h1;
    g_atl[base + tid + 256] = __float2bfloat16(a1 - __bfloat162float(h1));
}

// ---------------------------------------------------------------------------
// scatter O into conv_o input, pixel-major fp16 hi/lo' [b][p][ci]
// ---------------------------------------------------------------------------
__global__ void remap_sa_f16()
{
    int e = blockIdx.x * 256 + threadIdx.x;
    int b  = e >> 20;
    int p  = (e >> 9) & 2047;
    int d2 = e & 511;
    int s  = p >> 8;
    int rh = p & 255;
    int r2 = rh >> 3, h2 = rh & 7;
    int n  = b * 8 + s;
    int qd = r2 * 16 + h2 * 2 + (d2 >> 8);
    int rr = (d2 & 255) >> 3;
    int hh = d2 & 7;
    float v = g_On[n * 131072 + qd * 256 + hh * 32 + rr];
    __half h = __float2half(v);
    g_sah[e] = h;
    g_sal[e] = __float2half((v - __half2float(h)) * 4096.f);
}

// ---------------------------------------------------------------------------
extern "C" void kernel_launch(void* const* d_in, const int* in_sizes, int n_in,
                              void* d_out, int out_size)
{
    const float* q  = (const float*)d_in[0];
    const float* k  = (const float*)d_in[1];
    const float* v  = (const float*)d_in[2];
    const float* Wq = (const float*)d_in[3];
    const float* bq = (const float*)d_in[4];
    const float* Wk = (const float*)d_in[5];
    const float* bk = (const float*)d_in[6];
    const float* Wv = (const float*)d_in[7];
    const float* bv = (const float*)d_in[8];
    const float* Wo = (const float*)d_in[9];
    const float* bo = (const float*)d_in[10];

    float* y_out    = (float*)d_out;            // (4,512,8,32,8) = 4194304
    float* attn_out = y_out + NELEM;            // (1,32,512,512) = 8388608

    cudaFuncSetAttribute(conv_qkv_mma, cudaFuncAttributeMaxDynamicSharedMemorySize, SMEM_BYTES);
    cudaFuncSetAttribute(conv_o_mma,   cudaFuncAttributeMaxDynamicSharedMemorySize, SMEM_BYTES);
    cudaFuncSetAttribute(gemm_scores,  cudaFuncAttributeMaxDynamicSharedMemorySize, SMEM_BYTES);
    cudaFuncSetAttribute(gemm_nnout,   cudaFuncAttributeMaxDynamicSharedMemorySize, SMEM_BYTES);

    // launch order arranged so the ncu capture (launch index 3) hits conv_qkv_mma
    prep_w<<<4 * WSZ / 256, 256>>>(Wq, Wk, Wv, Wo);                 // 0
    prep_x<<<dim3(8, 16, 64), dim3(32, 8)>>>(q, k, v, 0);           // 1
    prep_x<<<dim3(8, 16, 32), dim3(32, 8)>>>(q, k, v, 64);          // 2
    conv_qkv_mma<<<dim3(64, 4, 3), 256, SMEM_BYTES>>>(bq, bk, bv);  // 3  <- profiled
    remap_V<<<NELEM / 256, 256>>>();                                // 4
    gemm_scores<<<dim3(4, 4, 32), 256, SMEM_BYTES>>>(attn_out);     // 5
    softmax_rows<<<32 * 512, 256>>>(attn_out);                      // 6
    gemm_nnout<<<dim3(2, 4, 32), 256, SMEM_BYTES>>>();              // 7
    remap_sa_f16<<<NELEM / 256, 256>>>();                           // 8
    conv_o_mma<<<dim3(64, 4, 1), 256, SMEM_BYTES>>>(bo, y_out);     // 9
}

// round 8
// speedup vs baseline: 1.1304x; 1.1304x over previous
#include <cuda_runtime.h>
#include <cuda_bf16.h>
#include <cstdint>

#define NELEM 4194304          // 32*512*32*8 == 4*512*8*256
#define WSZ   2359296          // 512*4608 weight elements per conv

// ---------------------------------------------------------------------------
// device scratch
// ---------------------------------------------------------------------------
__device__ __nv_bfloat16 g_Bh[4*WSZ];   // weights hi  [conv][co][t*512+ci]
__device__ __nv_bfloat16 g_Bl[4*WSZ];   // weights lo
__device__ __nv_bfloat16 g_xh[3*NELEM]; // qkv inputs hi, pixel-major [z][n][p][ci]
__device__ __nv_bfloat16 g_xl[3*NELEM];
__device__ __nv_bfloat16 g_sah[NELEM];  // conv_o input hi [b][p][ci]
__device__ __nv_bfloat16 g_sal[NELEM];
__device__ float g_y2[NELEM];           // conv(v) out (32,512,32,8)
__device__ __nv_bfloat16 g_Qh[NELEM], g_Ql[NELEM];   // [n][d][c], c=h*32+r
__device__ __nv_bfloat16 g_Kh[NELEM], g_Kl[NELEM];
__device__ __nv_bfloat16 g_Vth[NELEM], g_Vtl[NELEM]; // transposed: [n][c][dk]
__device__ __nv_bfloat16 g_ath[2*NELEM], g_atl[2*NELEM]; // attn hi/lo
__device__ float g_On[NELEM];           // attn @ V  [n][qd][c]

// ---------------------------------------------------------------------------
// helpers
// ---------------------------------------------------------------------------
__device__ __forceinline__ uint32_t smem_u32(const void* p) {
    uint32_t a;
    asm("{ .reg .u64 t; cvta.to.shared.u64 t, %1; cvt.u32.u64 %0, t; }" : "=r"(a) : "l"(p));
    return a;
}
#define SWZ(o) ((o) ^ (((o) >> 3) & 0x70))
#define CPA(dst, src, sz) \
    asm volatile("cp.async.cg.shared.global [%0], [%1], 16, %2;" \
        :: "r"(dst), "l"(src), "r"(sz) : "memory")
#define CPA_COMMIT() asm volatile("cp.async.commit_group;" ::: "memory")
#define CPA_WAIT1()  asm volatile("cp.async.wait_group 1;" ::: "memory")
#define CPA_WAIT0()  asm volatile("cp.async.wait_group 0;" ::: "memory")
#define LDM4(r, addr) \
    asm volatile("ldmatrix.sync.aligned.m8n8.x4.shared.b16 {%0,%1,%2,%3}, [%4];" \
        : "=r"((r)[0]), "=r"((r)[1]), "=r"((r)[2]), "=r"((r)[3]) : "r"(addr))
#define MMA_BF16(d, a, b0, b1) \
    asm volatile("mma.sync.aligned.m16n8k16.row.col.f32.bf16.bf16.f32 " \
        "{%0,%1,%2,%3}, {%4,%5,%6,%7}, {%8,%9}, {%0,%1,%2,%3};" \
        : "+f"((d)[0]), "+f"((d)[1]), "+f"((d)[2]), "+f"((d)[3]) \
        : "r"((a)[0]), "r"((a)[1]), "r"((a)[2]), "r"((a)[3]), "r"(b0), "r"(b1))

// K32 chunk; packed layout: two 64B K-rows per 128B line.
// stage (32KB): Ah 0, Al 8K, Bh 16K, Bl 24K. 3 stages = 96KB -> 2 CTAs/SM.
#define STAGE 32768u
#define SMEM_BYTES 98304
#define PROW(r) ((uint32_t)((((r) >> 1) << 7) | (((r) & 1) << 6)))

// ---------------------------------------------------------------------------
// compute one K32 chunk, warp tile 64x32: D += Ah*Bh + Ah*Bl + Al*Bh
// ---------------------------------------------------------------------------
__device__ __forceinline__ void mma_compute32(uint32_t bs, uint32_t a_rowb,
                                              uint32_t b_rowb, float (&acc)[16][4])
{
#pragma unroll
    for (int s = 0; s < 2; ++s) {
        uint32_t ah[4][4], bb[2][4], blf[2][4];
#pragma unroll
        for (int i = 0; i < 4; ++i)
            LDM4(ah[i], bs + SWZ(a_rowb + i * 1024 + s * 32));
#pragma unroll
        for (int j = 0; j < 2; ++j)
            LDM4(bb[j], bs + 16384u + SWZ(b_rowb + j * 1024 + s * 32));
#pragma unroll
        for (int i = 0; i < 4; ++i)
#pragma unroll
            for (int jj = 0; jj < 4; ++jj)
                MMA_BF16(acc[i * 4 + jj], ah[i],
                         bb[jj >> 1][(jj & 1) * 2], bb[jj >> 1][(jj & 1) * 2 + 1]);
#pragma unroll
        for (int j = 0; j < 2; ++j)
            LDM4(blf[j], bs + 24576u + SWZ(b_rowb + j * 1024 + s * 32));
#pragma unroll
        for (int i = 0; i < 4; ++i)
#pragma unroll
            for (int jj = 0; jj < 4; ++jj)
                MMA_BF16(acc[i * 4 + jj], ah[i],
                         blf[jj >> 1][(jj & 1) * 2], blf[jj >> 1][(jj & 1) * 2 + 1]);
#pragma unroll
        for (int i = 0; i < 4; ++i)
            LDM4(ah[i], bs + 8192u + SWZ(a_rowb + i * 1024 + s * 32));
#pragma unroll
        for (int i = 0; i < 4; ++i)
#pragma unroll
            for (int jj = 0; jj < 4; ++jj)
                MMA_BF16(acc[i * 4 + jj], ah[i],
                         bb[jj >> 1][(jj & 1) * 2], bb[jj >> 1][(jj & 1) * 2 + 1]);
    }
}

// ---------------------------------------------------------------------------
// pre-pass: weights -> bf16 hi/lo in [co][t*512+ci] layout
// ---------------------------------------------------------------------------
__global__ void prep_w(const float* __restrict__ Wq, const float* __restrict__ Wk,
                       const float* __restrict__ Wv, const float* __restrict__ Wo)
{
    int g = blockIdx.x * 256 + threadIdx.x;
    int conv = g / WSZ;
    int j = g - conv * WSZ;
    const float* W = (conv == 0) ? Wq : (conv == 1) ? Wk : (conv == 2) ? Wv : Wo;
    float v = W[j];
    int co  = j / 4608;
    int rem = j - co * 4608;
    int ci  = rem / 9;
    int t   = rem - ci * 9;
    __nv_bfloat16 h = __float2bfloat16(v);
    __nv_bfloat16 l = __float2bfloat16(v - __bfloat162float(h));
    size_t o = (size_t)conv * WSZ + (size_t)co * 4608 + t * 512 + ci;
    g_Bh[o] = h;
    g_Bl[o] = l;
}

// ---------------------------------------------------------------------------
// pre-pass: q/k/v (32 imgs, 512 ch, 256 pix) -> pixel-major bf16 hi/lo
// ---------------------------------------------------------------------------
__global__ void prep_x(const float* __restrict__ q, const float* __restrict__ k,
                       const float* __restrict__ v, int zoff)
{
    __shared__ float tile[32][33];
    int zz = blockIdx.z + zoff;
    int z = zz >> 5;
    int n = zz & 31;
    const float* src = (z == 0) ? q : (z == 1) ? k : v;
    const float* xin = src + (size_t)n * 512 * 256;
    __nv_bfloat16* oh = g_xh + (size_t)z * NELEM + (size_t)n * 256 * 512;
    __nv_bfloat16* ol = g_xl + (size_t)z * NELEM + (size_t)n * 256 * 512;
    int p0 = blockIdx.x * 32;
    int c0 = blockIdx.y * 32;
    int tx = threadIdx.x, ty = threadIdx.y;
#pragma unroll
    for (int j = 0; j < 4; ++j)
        tile[ty + 8 * j][tx] = xin[(size_t)(c0 + ty + 8 * j) * 256 + p0 + tx];
    __syncthreads();
#pragma unroll
    for (int j = 0; j < 4; ++j) {
        float val = tile[tx][ty + 8 * j];
        __nv_bfloat16 h = __float2bfloat16(val);
        size_t o = (size_t)(p0 + ty + 8 * j) * 512 + c0 + tx;
        oh[o] = h;
        ol[o] = __float2bfloat16(val - __bfloat162float(h));
    }
}

// ---------------------------------------------------------------------------
// 3-stage cp.async pipelined implicit-GEMM conv. M=128 pix x N=128 co.
// 8 warps (2 x 4), warp tile 64x32. K in 144 chunks of 32 (tap-major).
// 2 CTAs/SM. If oh != null: epilogue writes remapped bf16 hi/lo (Q or K path,
// coalesced by construction). Else: fp32 [co][pix] output.
// ---------------------------------------------------------------------------
__device__ __forceinline__ void conv_mma_pipe(
    const __nv_bfloat16* __restrict__ xh, const __nv_bfloat16* __restrict__ xl,
    const __nv_bfloat16* __restrict__ bh, const __nv_bfloat16* __restrict__ bl,
    const float* __restrict__ bias,
    __nv_bfloat16* __restrict__ oh, __nv_bfloat16* __restrict__ ol,
    float* __restrict__ y,
    int H, int W, int logW, int logPIX)
{
    extern __shared__ char smem[];
    uint32_t sb = smem_u32(smem);
    int tid = threadIdx.x, wid = tid >> 5, lane = tid & 31;
    const int HW = 1 << logPIX;
    int p0    = blockIdx.x * 128;
    int nimg  = p0 >> logPIX;
    int pbase = p0 & (HW - 1);
    int co0   = blockIdx.y * 128;
    int wm = wid & 1, wn = wid >> 1;

    // loader: thread -> (row = tid>>1, 32B half = tid&1)
    int lr = tid >> 1, lh = tid & 1;
    int ap = pbase + lr;
    int ayr = ap >> logW, axr = ap & (W - 1);
    uint32_t stb = PROW(lr) + lh * 32u;                 // packed store base
    const __nv_bfloat16* arow_h = xh + (size_t)nimg * HW * 512 + lh * 16;
    const __nv_bfloat16* arow_l = xl + (size_t)nimg * HW * 512 + lh * 16;
    const __nv_bfloat16* brow_h = bh + (size_t)(co0 + lr) * 4608 + lh * 16;
    const __nv_bfloat16* brow_l = bl + (size_t)(co0 + lr) * 4608 + lh * 16;

    // ldmatrix lane geometry (packed rows)
    int arow = wm * 64 + (lane & 15);
    uint32_t a_rowb = PROW(arow) + ((lane & 16) ? 16u : 0u);
    int brow = wn * 32 + (lane & 7) + ((lane & 16) ? 8 : 0);
    uint32_t b_rowb = PROW(brow) + ((lane & 8) ? 16u : 0u);

    float acc[16][4];
#pragma unroll
    for (int i = 0; i < 16; ++i)
#pragma unroll
        for (int j = 0; j < 4; ++j) acc[i][j] = 0.f;

    auto prefetch = [&](int itn, int stg) {
        int t = itn >> 4, ci0 = (itn & 15) << 5;        // 16 K32 chunks per tap
        int q3 = (t * 11) >> 5;                         // t/3 for t in [0,9)
        int dy = q3 - 1, dx = t - q3 * 3 - 1;
        int yy = ayr + dy, xx = axr + dx;
        bool ok = ((unsigned)yy < (unsigned)H) && ((unsigned)xx < (unsigned)W);
        int pps = ok ? ((yy << logW) + xx) : 0;
        const char* sAh = (const char*)(arow_h + (size_t)pps * 512 + ci0);
        const char* sAl = (const char*)(arow_l + (size_t)pps * 512 + ci0);
        const char* sBh = (const char*)(brow_h + t * 512 + ci0);
        const char* sBl = (const char*)(brow_l + t * 512 + ci0);
        uint32_t bs = sb + (uint32_t)stg * STAGE;
        uint32_t asz = ok ? 16u : 0u;
        uint32_t s0 = SWZ(stb), s1 = SWZ(stb + 16u);
        CPA(bs + s0,           sAh,      asz);
        CPA(bs + s1,           sAh + 16, asz);
        CPA(bs + 8192u + s0,   sAl,      asz);
        CPA(bs + 8192u + s1,   sAl + 16, asz);
        CPA(bs + 16384u + s0,  sBh,      16u);
        CPA(bs + 16384u + s1,  sBh + 16, 16u);
        CPA(bs + 24576u + s0,  sBl,      16u);
        CPA(bs + 24576u + s1,  sBl + 16, 16u);
        CPA_COMMIT();
    };

    prefetch(0, 0);
    prefetch(1, 1);
    int stg = 0;
    for (int it = 0; it < 144; ++it) {
        if (it < 143) CPA_WAIT1(); else CPA_WAIT0();
        __syncthreads();
        if (it + 2 < 144) {
            int nst = stg + 2; if (nst >= 3) nst -= 3;
            prefetch(it + 2, nst);
        }
        mma_compute32(sb + (uint32_t)stg * STAGE, a_rowb, b_rowb, acc);
        if (++stg == 3) stg = 0;
    }
    __syncthreads();

    // epilogue: stage via SMEM (128 x 130 fp32)
    float* sf = (float*)smem;
#pragma unroll
    for (int i = 0; i < 4; ++i) {
        int row = wm * 64 + i * 16 + (lane >> 2);
#pragma unroll
        for (int jj = 0; jj < 4; ++jj) {
            int col = wn * 32 + jj * 8 + (lane & 3) * 2;
            float* d = acc[i * 4 + jj];
            *(float2*)&sf[row * 130 + col]       = make_float2(d[0], d[1]);
            *(float2*)&sf[(row + 8) * 130 + col] = make_float2(d[2], d[3]);
        }
    }
    __syncthreads();

    if (oh) {
        // fused Q/K remap: (nimg, co, pp) -> [n][d][c] bf16 hi/lo (coalesced in c)
        int hh2 = nimg >> 2;
#pragma unroll 4
        for (int i = 0; i < 64; ++i) {
            int idx = i * 256 + tid;
            int cl = idx >> 7, pl = idx & 127;
            int co = co0 + cl;
            int pp = pbase + pl;
            float val = sf[pl * 130 + cl] + bias[co];
            int nn = (nimg & 3) * 8 + (co >> 6);
            int d  = (co & 63) * 8 + (pp >> 5);
            int c  = hh2 * 32 + (pp & 31);
            size_t o = ((size_t)nn * 512 + d) * 256 + c;
            __nv_bfloat16 vh = __float2bfloat16(val);
            oh[o] = vh;
            ol[o] = __float2bfloat16(val - __bfloat162float(vh));
        }
    } else {
        int pl = tid & 127, co2 = tid >> 7;
        float* yb = y + (size_t)nimg * 512 * HW + pbase + pl;
#pragma unroll 4
        for (int c = 0; c < 64; ++c) {
            int cl = c * 2 + co2;
            yb[(size_t)(co0 + cl) * HW] = sf[pl * 130 + cl] + bias[co0 + cl];
        }
    }
}

__global__ __launch_bounds__(256, 2) void conv_qkv_mma(
    const float* __restrict__ bq, const float* __restrict__ bk, const float* __restrict__ bv)
{
    int z = blockIdx.z;
    const float* bias = (z == 0) ? bq : (z == 1) ? bk : bv;
    __nv_bfloat16* oh = (z == 0) ? g_Qh : (z == 1) ? g_Kh : nullptr;
    __nv_bfloat16* ol = (z == 0) ? g_Ql : (z == 1) ? g_Kl : nullptr;
    conv_mma_pipe(g_xh + (size_t)z * NELEM, g_xl + (size_t)z * NELEM,
                  g_Bh + (size_t)z * WSZ, g_Bl + (size_t)z * WSZ,
                  bias, oh, ol, g_y2, 32, 8, 3, 8);
}

__global__ __launch_bounds__(256, 2) void conv_o_mma(const float* __restrict__ bo,
                                                     float* __restrict__ out)
{
    conv_mma_pipe(g_sah, g_sal, g_Bh + 3ull * WSZ, g_Bl + 3ull * WSZ,
                  bo, nullptr, nullptr, out, 8, 256, 8, 11);
}

// ---------------------------------------------------------------------------
// 3-stage cp.async pipelined GEMM: C(MxN) = A(MxK) * B(NxK)^T, hi/lo bf16
// CTA tile 128x128, warp tile 64x32, K32 chunks, 2 CTAs/SM.
// ---------------------------------------------------------------------------
__device__ __forceinline__ void gemm_mma_pipe(
    const __nv_bfloat16* __restrict__ Ah, const __nv_bfloat16* __restrict__ Al,
    const __nv_bfloat16* __restrict__ Bh, const __nv_bfloat16* __restrict__ Bl,
    int Kdim, int nchunk, float* __restrict__ C, int ldc)
{
    extern __shared__ char smem[];
    uint32_t sb = smem_u32(smem);
    int tid = threadIdx.x, wid = tid >> 5, lane = tid & 31;
    int m0 = blockIdx.y * 128, n0 = blockIdx.x * 128;
    int wm = wid & 1, wn = wid >> 1;

    int lr = tid >> 1, lh = tid & 1;
    uint32_t stb = PROW(lr) + lh * 32u;
    const char* srcA_h = (const char*)(Ah + (size_t)(m0 + lr) * Kdim + lh * 16);
    const char* srcA_l = (const char*)(Al + (size_t)(m0 + lr) * Kdim + lh * 16);
    const char* srcB_h = (const char*)(Bh + (size_t)(n0 + lr) * Kdim + lh * 16);
    const char* srcB_l = (const char*)(Bl + (size_t)(n0 + lr) * Kdim + lh * 16);

    int arow = wm * 64 + (lane & 15);
    uint32_t a_rowb = PROW(arow) + ((lane & 16) ? 16u : 0u);
    int brow = wn * 32 + (lane & 7) + ((lane & 16) ? 8 : 0);
    uint32_t b_rowb = PROW(brow) + ((lane & 8) ? 16u : 0u);

    float acc[16][4];
#pragma unroll
    for (int i = 0; i < 16; ++i)
#pragma unroll
        for (int j = 0; j < 4; ++j) acc[i][j] = 0.f;

    auto prefetch = [&](int itn, int stg) {
        int cb = itn * 64;                  // bytes along K (32 bf16)
        uint32_t bs = sb + (uint32_t)stg * STAGE;
        uint32_t s0 = SWZ(stb), s1 = SWZ(stb + 16u);
        CPA(bs + s0,          srcA_h + cb,      16u);
        CPA(bs + s1,          srcA_h + cb + 16, 16u);
        CPA(bs + 8192u + s0,  srcA_l + cb,      16u);
        CPA(bs + 8192u + s1,  srcA_l + cb + 16, 16u);
        CPA(bs + 16384u + s0, srcB_h + cb,      16u);
        CPA(bs + 16384u + s1, srcB_h + cb + 16, 16u);
        CPA(bs + 24576u + s0, srcB_l + cb,      16u);
        CPA(bs + 24576u + s1, srcB_l + cb + 16, 16u);
        CPA_COMMIT();
    };

    prefetch(0, 0);
    prefetch(1, 1);
    int stg = 0;
    for (int it = 0; it < nchunk; ++it) {
        if (it < nchunk - 1) CPA_WAIT1(); else CPA_WAIT0();
        __syncthreads();
        if (it + 2 < nchunk) {
            int nst = stg + 2; if (nst >= 3) nst -= 3;
            prefetch(it + 2, nst);
        }
        mma_compute32(sb + (uint32_t)stg * STAGE, a_rowb, b_rowb, acc);
        if (++stg == 3) stg = 0;
    }

#pragma unroll
    for (int i = 0; i < 4; ++i) {
        int row = m0 + wm * 64 + i * 16 + (lane >> 2);
#pragma unroll
        for (int jj = 0; jj < 4; ++jj) {
            int col = n0 + wn * 32 + jj * 8 + (lane & 3) * 2;
            float* d = acc[i * 4 + jj];
            *(float2*)&C[(size_t)row * ldc + col]       = make_float2(d[0], d[1]);
            *(float2*)&C[(size_t)(row + 8) * ldc + col] = make_float2(d[2], d[3]);
        }
    }
}

__global__ __launch_bounds__(256, 2) void gemm_scores(float* __restrict__ attn)
{
    int nb = blockIdx.z;
    gemm_mma_pipe(g_Qh + (size_t)nb * 131072, g_Ql + (size_t)nb * 131072,
                  g_Kh + (size_t)nb * 131072, g_Kl + (size_t)nb * 131072,
                  256, 8, attn + (size_t)nb * 262144, 512);
}

__global__ __launch_bounds__(256, 2) void gemm_nnout()
{
    int nb = blockIdx.z;
    gemm_mma_pipe(g_ath + (size_t)nb * 262144, g_atl + (size_t)nb * 262144,
                  g_Vth + (size_t)nb * 131072, g_Vtl + (size_t)nb * 131072,
                  512, 16, g_On + (size_t)nb * 131072, 256);
}

// ---------------------------------------------------------------------------
// V transpose remap: g_y2 -> Vt bf16 hi/lo [n][c][dk]
// ---------------------------------------------------------------------------
__global__ void remap_V()
{
    int e = blockIdx.x * 256 + threadIdx.x;
    int n = e >> 17, c = (e >> 9) & 255, dk = e & 511;
    int h = c >> 5, r = c & 31;
    float v = g_y2[(h * 4 + (n >> 3)) * 131072 + ((n & 7) * 64 + (dk >> 3)) * 256
                   + (dk & 7) * 32 + r];
    __nv_bfloat16 hh = __float2bfloat16(v);
    g_Vth[e] = hh;
    g_Vtl[e] = __float2bfloat16(v - __bfloat162float(hh));
}

// ---------------------------------------------------------------------------
// softmax over 512-wide rows, in place; also emit bf16 hi/lo
// ---------------------------------------------------------------------------
__global__ void softmax_rows(float* __restrict__ attn)
{
    size_t base = (size_t)blockIdx.x * 512;
    float* p = attn + base;
    int tid = threadIdx.x;
    float v0 = p[tid], v1 = p[tid + 256];
    float m = fmaxf(v0, v1);
#pragma unroll
    for (int o = 16; o; o >>= 1) m = fmaxf(m, __shfl_xor_sync(~0u, m, o));
    __shared__ float sm[8], ss[8];
    if ((tid & 31) == 0) sm[tid >> 5] = m;
    __syncthreads();
    if (tid < 8) {
        float mm = sm[tid];
#pragma unroll
        for (int o = 4; o; o >>= 1) mm = fmaxf(mm, __shfl_xor_sync(0xffu, mm, o));
        if (tid == 0) sm[0] = mm;
    }
    __syncthreads();
    float M = sm[0];
    float e0 = expf(v0 - M), e1 = expf(v1 - M);
    float s = e0 + e1;
#pragma unroll
    for (int o = 16; o; o >>= 1) s += __shfl_xor_sync(~0u, s, o);
    if ((tid & 31) == 0) ss[tid >> 5] = s;
    __syncthreads();
    if (tid < 8) {
        float t2 = ss[tid];
#pragma unroll
        for (int o = 4; o; o >>= 1) t2 += __shfl_xor_sync(0xffu, t2, o);
        if (tid == 0) ss[0] = t2;
    }
    __syncthreads();
    float inv = 1.f / ss[0];
    float a0 = e0 * inv, a1 = e1 * inv;
    p[tid] = a0;
    p[tid + 256] = a1;
    __nv_bfloat16 h0 = __float2bfloat16(a0), h1 = __float2bfloat16(a1);
    g_ath[base + tid]       = h0;
    g_atl[base + tid]       = __float2bfloat16(a0 - __bfloat162float(h0));
    g_ath[base + tid + 256] = h1;
    g_atl[base + tid + 256] = __float2bfloat16(a1 - __bfloat162float(h1));
}

// ---------------------------------------------------------------------------
// scatter O into conv_o input, pixel-major bf16 hi/lo [b][p][ci]
// ---------------------------------------------------------------------------
__global__ void remap_sa_bf16()
{
    int e = blockIdx.x * 256 + threadIdx.x;
    int b  = e >> 20;
    int p  = (e >> 9) & 2047;
    int d2 = e & 511;
    int s  = p >> 8;
    int rh = p & 255;
    int r2 = rh >> 3, h2 = rh & 7;
    int n  = b * 8 + s;
    int qd = r2 * 16 + h2 * 2 + (d2 >> 8);
    int rr = (d2 & 255) >> 3;
    int hh = d2 & 7;
    float v = g_On[n * 131072 + qd * 256 + hh * 32 + rr];
    __nv_bfloat16 h = __float2bfloat16(v);
    g_sah[e] = h;
    g_sal[e] = __float2bfloat16(v - __bfloat162float(h));
}

// ---------------------------------------------------------------------------
extern "C" void kernel_launch(void* const* d_in, const int* in_sizes, int n_in,
                              void* d_out, int out_size)
{
    const float* q  = (const float*)d_in[0];
    const float* k  = (const float*)d_in[1];
    const float* v  = (const float*)d_in[2];
    const float* Wq = (const float*)d_in[3];
    const float* bq = (const float*)d_in[4];
    const float* Wk = (const float*)d_in[5];
    const float* bk = (const float*)d_in[6];
    const float* Wv = (const float*)d_in[7];
    const float* bv = (const float*)d_in[8];
    const float* Wo = (const float*)d_in[9];
    const float* bo = (const float*)d_in[10];

    float* y_out    = (float*)d_out;            // (4,512,8,32,8) = 4194304
    float* attn_out = y_out + NELEM;            // (1,32,512,512) = 8388608

    cudaFuncSetAttribute(conv_qkv_mma, cudaFuncAttributeMaxDynamicSharedMemorySize, SMEM_BYTES);
    cudaFuncSetAttribute(conv_o_mma,   cudaFuncAttributeMaxDynamicSharedMemorySize, SMEM_BYTES);
    cudaFuncSetAttribute(gemm_scores,  cudaFuncAttributeMaxDynamicSharedMemorySize, SMEM_BYTES);
    cudaFuncSetAttribute(gemm_nnout,   cudaFuncAttributeMaxDynamicSharedMemorySize, SMEM_BYTES);

    // launch order arranged so the ncu capture (launch index 3) hits conv_qkv_mma
    prep_w<<<4 * WSZ / 256, 256>>>(Wq, Wk, Wv, Wo);                 // 0
    prep_x<<<dim3(8, 16, 64), dim3(32, 8)>>>(q, k, v, 0);           // 1
    prep_x<<<dim3(8, 16, 32), dim3(32, 8)>>>(q, k, v, 64);          // 2
    conv_qkv_mma<<<dim3(64, 4, 3), 256, SMEM_BYTES>>>(bq, bk, bv);  // 3  <- profiled
    remap_V<<<NELEM / 256, 256>>>();                                // 4
    gemm_scores<<<dim3(4, 4, 32), 256, SMEM_BYTES>>>(attn_out);     // 5
    softmax_rows<<<32 * 512, 256>>>(attn_out);                      // 6
    gemm_nnout<<<dim3(2, 4, 32), 256, SMEM_BYTES>>>();              // 7
    remap_sa_bf16<<<NELEM / 256, 256>>>();                          // 8
    conv_o_mma<<<dim3(64, 4, 1), 256, SMEM_BYTES>>>(bo, y_out);     // 9
}

// round 9
// speedup vs baseline: 1.1808x; 1.0446x over previous
#include <cuda_runtime.h>
#include <cuda_bf16.h>
#include <cstdint>

#define NELEM 4194304          // 32*512*32*8 == 4*512*8*256
#define WSZ   2359296          // 512*4608 weight elements per conv

// ---------------------------------------------------------------------------
// device scratch
// ---------------------------------------------------------------------------
__device__ __nv_bfloat16 g_Bh[4*WSZ];   // weights hi  [conv][co][t*512+ci]
__device__ __nv_bfloat16 g_Bl[4*WSZ];   // weights lo
__device__ __nv_bfloat16 g_xh[3*NELEM]; // qkv inputs hi, pixel-major [z][n][p][ci]
__device__ __nv_bfloat16 g_xl[3*NELEM];
__device__ __nv_bfloat16 g_sah[NELEM];  // conv_o input hi [b][p][ci]
__device__ __nv_bfloat16 g_sal[NELEM];
__device__ float g_y2[NELEM];           // conv(v) out (32,512,32,8)
__device__ __nv_bfloat16 g_Qh[NELEM], g_Ql[NELEM];   // [n][d][c], c=h*32+r
__device__ __nv_bfloat16 g_Kh[NELEM], g_Kl[NELEM];
__device__ __nv_bfloat16 g_Vth[NELEM], g_Vtl[NELEM]; // transposed: [n][c][dk]
__device__ __nv_bfloat16 g_ath[2*NELEM], g_atl[2*NELEM]; // attn hi/lo
__device__ float g_On[NELEM];           // attn @ V  [n][qd][c]

// ---------------------------------------------------------------------------
// helpers
// ---------------------------------------------------------------------------
__device__ __forceinline__ uint32_t smem_u32(const void* p) {
    uint32_t a;
    asm("{ .reg .u64 t; cvta.to.shared.u64 t, %1; cvt.u32.u64 %0, t; }" : "=r"(a) : "l"(p));
    return a;
}
#define SWZ(o) ((o) ^ (((o) >> 3) & 0x70))
#define CPA(dst, src, sz) \
    asm volatile("cp.async.cg.shared.global [%0], [%1], 16, %2;" \
        :: "r"(dst), "l"(src), "r"(sz) : "memory")
#define CPA_COMMIT() asm volatile("cp.async.commit_group;" ::: "memory")
#define CPA_WAIT1()  asm volatile("cp.async.wait_group 1;" ::: "memory")
#define CPA_WAIT0()  asm volatile("cp.async.wait_group 0;" ::: "memory")
#define LDM4(r, addr) \
    asm volatile("ldmatrix.sync.aligned.m8n8.x4.shared.b16 {%0,%1,%2,%3}, [%4];" \
        : "=r"((r)[0]), "=r"((r)[1]), "=r"((r)[2]), "=r"((r)[3]) : "r"(addr))
#define MMA_BF16(d, a, b0, b1) \
    asm volatile("mma.sync.aligned.m16n8k16.row.col.f32.bf16.bf16.f32 " \
        "{%0,%1,%2,%3}, {%4,%5,%6,%7}, {%8,%9}, {%0,%1,%2,%3};" \
        : "+f"((d)[0]), "+f"((d)[1]), "+f"((d)[2]), "+f"((d)[3]) \
        : "r"((a)[0]), "r"((a)[1]), "r"((a)[2]), "r"((a)[3]), "r"(b0), "r"(b1))
#define WAITP(addr, ph) do { \
    asm volatile("{\n\t.reg .pred P;\n\tWL%=:\n\t" \
        "mbarrier.try_wait.parity.acquire.cta.shared::cta.b64 P, [%0], %1, 0x989680;\n\t" \
        "@P bra.uni WD%=;\n\tbra.uni WL%=;\n\tWD%=:\n\t}" \
        :: "r"(addr), "r"(ph) : "memory"); \
} while (0)

// K32 chunk; packed layout: two 64B K-rows per 128B line.
// stage (32KB): Ah 0, Al 8K, Bh 16K, Bl 24K. 3 stages = 96KB.
// conv adds mbarriers at smem tail (96KB..96KB+48B): full[s]@s*16, empty[s]@s*16+8
#define STAGE 32768u
#define MBAR_BASE 98304u
#define SMEM_BYTES_CONV 98368
#define SMEM_BYTES_GEMM 98304
#define PROW(r) ((uint32_t)((((r) >> 1) << 7) | (((r) & 1) << 6)))

// ---------------------------------------------------------------------------
// compute one K32 chunk, warp tile 64x32: D += Ah*Bh + Ah*Bl + Al*Bh
// ---------------------------------------------------------------------------
__device__ __forceinline__ void mma_compute32(uint32_t bs, uint32_t a_rowb,
                                              uint32_t b_rowb, float (&acc)[16][4])
{
#pragma unroll
    for (int s = 0; s < 2; ++s) {
        uint32_t ah[4][4], bb[2][4], blf[2][4];
#pragma unroll
        for (int i = 0; i < 4; ++i)
            LDM4(ah[i], bs + SWZ(a_rowb + i * 1024 + s * 32));
#pragma unroll
        for (int j = 0; j < 2; ++j)
            LDM4(bb[j], bs + 16384u + SWZ(b_rowb + j * 1024 + s * 32));
#pragma unroll
        for (int i = 0; i < 4; ++i)
#pragma unroll
            for (int jj = 0; jj < 4; ++jj)
                MMA_BF16(acc[i * 4 + jj], ah[i],
                         bb[jj >> 1][(jj & 1) * 2], bb[jj >> 1][(jj & 1) * 2 + 1]);
#pragma unroll
        for (int j = 0; j < 2; ++j)
            LDM4(blf[j], bs + 24576u + SWZ(b_rowb + j * 1024 + s * 32));
#pragma unroll
        for (int i = 0; i < 4; ++i)
#pragma unroll
            for (int jj = 0; jj < 4; ++jj)
                MMA_BF16(acc[i * 4 + jj], ah[i],
                         blf[jj >> 1][(jj & 1) * 2], blf[jj >> 1][(jj & 1) * 2 + 1]);
#pragma unroll
        for (int i = 0; i < 4; ++i)
            LDM4(ah[i], bs + 8192u + SWZ(a_rowb + i * 1024 + s * 32));
#pragma unroll
        for (int i = 0; i < 4; ++i)
#pragma unroll
            for (int jj = 0; jj < 4; ++jj)
                MMA_BF16(acc[i * 4 + jj], ah[i],
                         bb[jj >> 1][(jj & 1) * 2], bb[jj >> 1][(jj & 1) * 2 + 1]);
    }
}

// ---------------------------------------------------------------------------
// pre-pass: weights -> bf16 hi/lo in [co][t*512+ci] layout
// ---------------------------------------------------------------------------
__global__ void prep_w(const float* __restrict__ Wq, const float* __restrict__ Wk,
                       const float* __restrict__ Wv, const float* __restrict__ Wo)
{
    int g = blockIdx.x * 256 + threadIdx.x;
    int conv = g / WSZ;
    int j = g - conv * WSZ;
    const float* W = (conv == 0) ? Wq : (conv == 1) ? Wk : (conv == 2) ? Wv : Wo;
    float v = W[j];
    int co  = j / 4608;
    int rem = j - co * 4608;
    int ci  = rem / 9;
    int t   = rem - ci * 9;
    __nv_bfloat16 h = __float2bfloat16(v);
    __nv_bfloat16 l = __float2bfloat16(v - __bfloat162float(h));
    size_t o = (size_t)conv * WSZ + (size_t)co * 4608 + t * 512 + ci;
    g_Bh[o] = h;
    g_Bl[o] = l;
}

// ---------------------------------------------------------------------------
// pre-pass: q/k/v (32 imgs, 512 ch, 256 pix) -> pixel-major bf16 hi/lo
// ---------------------------------------------------------------------------
__global__ void prep_x(const float* __restrict__ q, const float* __restrict__ k,
                       const float* __restrict__ v, int zoff)
{
    __shared__ float tile[32][33];
    int zz = blockIdx.z + zoff;
    int z = zz >> 5;
    int n = zz & 31;
    const float* src = (z == 0) ? q : (z == 1) ? k : v;
    const float* xin = src + (size_t)n * 512 * 256;
    __nv_bfloat16* oh = g_xh + (size_t)z * NELEM + (size_t)n * 256 * 512;
    __nv_bfloat16* ol = g_xl + (size_t)z * NELEM + (size_t)n * 256 * 512;
    int p0 = blockIdx.x * 32;
    int c0 = blockIdx.y * 32;
    int tx = threadIdx.x, ty = threadIdx.y;
#pragma unroll
    for (int j = 0; j < 4; ++j)
        tile[ty + 8 * j][tx] = xin[(size_t)(c0 + ty + 8 * j) * 256 + p0 + tx];
    __syncthreads();
#pragma unroll
    for (int j = 0; j < 4; ++j) {
        float val = tile[tx][ty + 8 * j];
        __nv_bfloat16 h = __float2bfloat16(val);
        size_t o = (size_t)(p0 + ty + 8 * j) * 512 + c0 + tx;
        oh[o] = h;
        ol[o] = __float2bfloat16(val - __bfloat162float(h));
    }
}

// ---------------------------------------------------------------------------
// mbarrier-pipelined implicit-GEMM conv. M=128 pix x N=128 co, warp 64x32.
// 3 stages, full/empty mbarriers (count=256) replace the syncthreads convoy:
// warps slip independently; release/acquire orders LDS reads vs overwrites.
// ---------------------------------------------------------------------------
__device__ __forceinline__ void conv_mma_pipe(
    const __nv_bfloat16* __restrict__ xh, const __nv_bfloat16* __restrict__ xl,
    const __nv_bfloat16* __restrict__ bh, const __nv_bfloat16* __restrict__ bl,
    const float* __restrict__ bias,
    __nv_bfloat16* __restrict__ oh, __nv_bfloat16* __restrict__ ol,
    float* __restrict__ y,
    int H, int W, int logW, int logPIX)
{
    extern __shared__ char smem[];
    uint32_t sb = smem_u32(smem);
    int tid = threadIdx.x, wid = tid >> 5, lane = tid & 31;
    const int HW = 1 << logPIX;
    int p0    = blockIdx.x * 128;
    int nimg  = p0 >> logPIX;
    int pbase = p0 & (HW - 1);
    int co0   = blockIdx.y * 128;
    int wm = wid & 1, wn = wid >> 1;

    // loader: thread -> (row = tid>>1, 32B half = tid&1)
    int lr = tid >> 1, lh = tid & 1;
    int ap = pbase + lr;
    int ayr = ap >> logW, axr = ap & (W - 1);
    uint32_t stb = PROW(lr) + lh * 32u;                 // packed store base
    const __nv_bfloat16* arow_h = xh + (size_t)nimg * HW * 512 + lh * 16;
    const __nv_bfloat16* arow_l = xl + (size_t)nimg * HW * 512 + lh * 16;
    const __nv_bfloat16* brow_h = bh + (size_t)(co0 + lr) * 4608 + lh * 16;
    const __nv_bfloat16* brow_l = bl + (size_t)(co0 + lr) * 4608 + lh * 16;

    // ldmatrix lane geometry (packed rows)
    int arow = wm * 64 + (lane & 15);
    uint32_t a_rowb = PROW(arow) + ((lane & 16) ? 16u : 0u);
    int brow = wn * 32 + (lane & 7) + ((lane & 16) ? 8 : 0);
    uint32_t b_rowb = PROW(brow) + ((lane & 8) ? 16u : 0u);

    // mbarrier init: full[s] @ MBAR_BASE+s*16, empty[s] @ +8
    if (tid == 0) {
#pragma unroll
        for (int s = 0; s < 3; ++s) {
            asm volatile("mbarrier.init.shared.b64 [%0], %1;"
                         :: "r"(sb + MBAR_BASE + s * 16u), "r"(256) : "memory");
            asm volatile("mbarrier.init.shared.b64 [%0], %1;"
                         :: "r"(sb + MBAR_BASE + s * 16u + 8u), "r"(256) : "memory");
        }
    }
    __syncthreads();

    float acc[16][4];
#pragma unroll
    for (int i = 0; i < 16; ++i)
#pragma unroll
        for (int j = 0; j < 4; ++j) acc[i][j] = 0.f;

    int ps = 0, pph = 1;       // producer cursor (phase starts 1: first wait passes)
    int cs = 0, cph = 0;       // consumer cursor

    auto produce = [&](int itn) {
        uint32_t fmb = sb + MBAR_BASE + (uint32_t)ps * 16u;
        WAITP(fmb + 8u, pph);                           // wait empty[ps]
        int t = itn >> 4, ci0 = (itn & 15) << 5;        // 16 K32 chunks per tap
        int q3 = (t * 11) >> 5;                         // t/3 for t in [0,9)
        int dy = q3 - 1, dx = t - q3 * 3 - 1;
        int yy = ayr + dy, xx = axr + dx;
        bool ok = ((unsigned)yy < (unsigned)H) && ((unsigned)xx < (unsigned)W);
        int pps = ok ? ((yy << logW) + xx) : 0;
        const char* sAh = (const char*)(arow_h + (size_t)pps * 512 + ci0);
        const char* sAl = (const char*)(arow_l + (size_t)pps * 512 + ci0);
        const char* sBh = (const char*)(brow_h + t * 512 + ci0);
        const char* sBl = (const char*)(brow_l + t * 512 + ci0);
        uint32_t bs = sb + (uint32_t)ps * STAGE;
        uint32_t asz = ok ? 16u : 0u;
        uint32_t s0 = SWZ(stb), s1 = SWZ(stb + 16u);
        CPA(bs + s0,           sAh,      asz);
        CPA(bs + s1,           sAh + 16, asz);
        CPA(bs + 8192u + s0,   sAl,      asz);
        CPA(bs + 8192u + s1,   sAl + 16, asz);
        CPA(bs + 16384u + s0,  sBh,      16u);
        CPA(bs + 16384u + s1,  sBh + 16, 16u);
        CPA(bs + 24576u + s0,  sBl,      16u);
        CPA(bs + 24576u + s1,  sBl + 16, 16u);
        asm volatile("cp.async.mbarrier.arrive.noinc.shared::cta.b64 [%0];"
                     :: "r"(fmb) : "memory");
        if (++ps == 3) { ps = 0; pph ^= 1; }
    };

    produce(0);
    produce(1);
    for (int it = 0; it < 144; ++it) {
        if (it + 2 < 144) produce(it + 2);
        uint32_t fmb = sb + MBAR_BASE + (uint32_t)cs * 16u;
        WAITP(fmb, cph);                                // wait full[cs]
        mma_compute32(sb + (uint32_t)cs * STAGE, a_rowb, b_rowb, acc);
        asm volatile("mbarrier.arrive.shared::cta.b64 _, [%0];"
                     :: "r"(fmb + 8u) : "memory");      // arrive empty[cs]
        if (++cs == 3) { cs = 0; cph ^= 1; }
    }
    __syncthreads();

    // epilogue: stage via SMEM (128 x 130 fp32)
    float* sf = (float*)smem;
#pragma unroll
    for (int i = 0; i < 4; ++i) {
        int row = wm * 64 + i * 16 + (lane >> 2);
#pragma unroll
        for (int jj = 0; jj < 4; ++jj) {
            int col = wn * 32 + jj * 8 + (lane & 3) * 2;
            float* d = acc[i * 4 + jj];
            *(float2*)&sf[row * 130 + col]       = make_float2(d[0], d[1]);
            *(float2*)&sf[(row + 8) * 130 + col] = make_float2(d[2], d[3]);
        }
    }
    __syncthreads();

    if (oh) {
        // fused Q/K remap: (nimg, co, pp) -> [n][d][c] bf16 hi/lo (coalesced in c)
        int hh2 = nimg >> 2;
#pragma unroll 4
        for (int i = 0; i < 64; ++i) {
            int idx = i * 256 + tid;
            int cl = idx >> 7, pl = idx & 127;
            int co = co0 + cl;
            int pp = pbase + pl;
            float val = sf[pl * 130 + cl] + bias[co];
            int nn = (nimg & 3) * 8 + (co >> 6);
            int d  = (co & 63) * 8 + (pp >> 5);
            int c  = hh2 * 32 + (pp & 31);
            size_t o = ((size_t)nn * 512 + d) * 256 + c;
            __nv_bfloat16 vh = __float2bfloat16(val);
            oh[o] = vh;
            ol[o] = __float2bfloat16(val - __bfloat162float(vh));
        }
    } else {
        int pl = tid & 127, co2 = tid >> 7;
        float* yb = y + (size_t)nimg * 512 * HW + pbase + pl;
#pragma unroll 4
        for (int c = 0; c < 64; ++c) {
            int cl = c * 2 + co2;
            yb[(size_t)(co0 + cl) * HW] = sf[pl * 130 + cl] + bias[co0 + cl];
        }
    }
}

__global__ __launch_bounds__(256, 2) void conv_qkv_mma(
    const float* __restrict__ bq, const float* __restrict__ bk, const float* __restrict__ bv)
{
    int z = blockIdx.z;
    const float* bias = (z == 0) ? bq : (z == 1) ? bk : bv;
    __nv_bfloat16* oh = (z == 0) ? g_Qh : (z == 1) ? g_Kh : nullptr;
    __nv_bfloat16* ol = (z == 0) ? g_Ql : (z == 1) ? g_Kl : nullptr;
    conv_mma_pipe(g_xh + (size_t)z * NELEM, g_xl + (size_t)z * NELEM,
                  g_Bh + (size_t)z * WSZ, g_Bl + (size_t)z * WSZ,
                  bias, oh, ol, g_y2, 32, 8, 3, 8);
}

__global__ __launch_bounds__(256, 2) void conv_o_mma(const float* __restrict__ bo,
                                                     float* __restrict__ out)
{
    conv_mma_pipe(g_sah, g_sal, g_Bh + 3ull * WSZ, g_Bl + 3ull * WSZ,
                  bo, nullptr, nullptr, out, 8, 256, 8, 11);
}

// ---------------------------------------------------------------------------
// 3-stage cp.async pipelined GEMM: C(MxN) = A(MxK) * B(NxK)^T, hi/lo bf16
// CTA tile 128x128, warp tile 64x32, K32 chunks, 2 CTAs/SM. (sync path)
// ---------------------------------------------------------------------------
__device__ __forceinline__ void gemm_mma_pipe(
    const __nv_bfloat16* __restrict__ Ah, const __nv_bfloat16* __restrict__ Al,
    const __nv_bfloat16* __restrict__ Bh, const __nv_bfloat16* __restrict__ Bl,
    int Kdim, int nchunk, float* __restrict__ C, int ldc)
{
    extern __shared__ char smem[];
    uint32_t sb = smem_u32(smem);
    int tid = threadIdx.x, wid = tid >> 5, lane = tid & 31;
    int m0 = blockIdx.y * 128, n0 = blockIdx.x * 128;
    int wm = wid & 1, wn = wid >> 1;

    int lr = tid >> 1, lh = tid & 1;
    uint32_t stb = PROW(lr) + lh * 32u;
    const char* srcA_h = (const char*)(Ah + (size_t)(m0 + lr) * Kdim + lh * 16);
    const char* srcA_l = (const char*)(Al + (size_t)(m0 + lr) * Kdim + lh * 16);
    const char* srcB_h = (const char*)(Bh + (size_t)(n0 + lr) * Kdim + lh * 16);
    const char* srcB_l = (const char*)(Bl + (size_t)(n0 + lr) * Kdim + lh * 16);

    int arow = wm * 64 + (lane & 15);
    uint32_t a_rowb = PROW(arow) + ((lane & 16) ? 16u : 0u);
    int brow = wn * 32 + (lane & 7) + ((lane & 16) ? 8 : 0);
    uint32_t b_rowb = PROW(brow) + ((lane & 8) ? 16u : 0u);

    float acc[16][4];
#pragma unroll
    for (int i = 0; i < 16; ++i)
#pragma unroll
        for (int j = 0; j < 4; ++j) acc[i][j] = 0.f;

    auto prefetch = [&](int itn, int stg) {
        int cb = itn * 64;                  // bytes along K (32 bf16)
        uint32_t bs = sb + (uint32_t)stg * STAGE;
        uint32_t s0 = SWZ(stb), s1 = SWZ(stb + 16u);
        CPA(bs + s0,          srcA_h + cb,      16u);
        CPA(bs + s1,          srcA_h + cb + 16, 16u);
        CPA(bs + 8192u + s0,  srcA_l + cb,      16u);
        CPA(bs + 8192u + s1,  srcA_l + cb + 16, 16u);
        CPA(bs + 16384u + s0, srcB_h + cb,      16u);
        CPA(bs + 16384u + s1, srcB_h + cb + 16, 16u);
        CPA(bs + 24576u + s0, srcB_l + cb,      16u);
        CPA(bs + 24576u + s1, srcB_l + cb + 16, 16u);
        CPA_COMMIT();
    };

    prefetch(0, 0);
    prefetch(1, 1);
    int stg = 0;
    for (int it = 0; it < nchunk; ++it) {
        if (it < nchunk - 1) CPA_WAIT1(); else CPA_WAIT0();
        __syncthreads();
        if (it + 2 < nchunk) {
            int nst = stg + 2; if (nst >= 3) nst -= 3;
            prefetch(it + 2, nst);
        }
        mma_compute32(sb + (uint32_t)stg * STAGE, a_rowb, b_rowb, acc);
        if (++stg == 3) stg = 0;
    }

#pragma unroll
    for (int i = 0; i < 4; ++i) {
        int row = m0 + wm * 64 + i * 16 + (lane >> 2);
#pragma unroll
        for (int jj = 0; jj < 4; ++jj) {
            int col = n0 + wn * 32 + jj * 8 + (lane & 3) * 2;
            float* d = acc[i * 4 + jj];
            *(float2*)&C[(size_t)row * ldc + col]       = make_float2(d[0], d[1]);
            *(float2*)&C[(size_t)(row + 8) * ldc + col] = make_float2(d[2], d[3]);
        }
    }
}

__global__ __launch_bounds__(256, 2) void gemm_scores(float* __restrict__ attn)
{
    int nb = blockIdx.z;
    gemm_mma_pipe(g_Qh + (size_t)nb * 131072, g_Ql + (size_t)nb * 131072,
                  g_Kh + (size_t)nb * 131072, g_Kl + (size_t)nb * 131072,
                  256, 8, attn + (size_t)nb * 262144, 512);
}

__global__ __launch_bounds__(256, 2) void gemm_nnout()
{
    int nb = blockIdx.z;
    gemm_mma_pipe(g_ath + (size_t)nb * 262144, g_atl + (size_t)nb * 262144,
                  g_Vth + (size_t)nb * 131072, g_Vtl + (size_t)nb * 131072,
                  512, 16, g_On + (size_t)nb * 131072, 256);
}

// ---------------------------------------------------------------------------
// V transpose remap: g_y2 -> Vt bf16 hi/lo [n][c][dk]
// ---------------------------------------------------------------------------
__global__ void remap_V()
{
    int e = blockIdx.x * 256 + threadIdx.x;
    int n = e >> 17, c = (e >> 9) & 255, dk = e & 511;
    int h = c >> 5, r = c & 31;
    float v = g_y2[(h * 4 + (n >> 3)) * 131072 + ((n & 7) * 64 + (dk >> 3)) * 256
                   + (dk & 7) * 32 + r];
    __nv_bfloat16 hh = __float2bfloat16(v);
    g_Vth[e] = hh;
    g_Vtl[e] = __float2bfloat16(v - __bfloat162float(hh));
}

// ---------------------------------------------------------------------------
// softmax over 512-wide rows, in place; also emit bf16 hi/lo
// ---------------------------------------------------------------------------
__global__ void softmax_rows(float* __restrict__ attn)
{
    size_t base = (size_t)blockIdx.x * 512;
    float* p = attn + base;
    int tid = threadIdx.x;
    float v0 = p[tid], v1 = p[tid + 256];
    float m = fmaxf(v0, v1);
#pragma unroll
    for (int o = 16; o; o >>= 1) m = fmaxf(m, __shfl_xor_sync(~0u, m, o));
    __shared__ float sm[8], ss[8];
    if ((tid & 31) == 0) sm[tid >> 5] = m;
    __syncthreads();
    if (tid < 8) {
        float mm = sm[tid];
#pragma unroll
        for (int o = 4; o; o >>= 1) mm = fmaxf(mm, __shfl_xor_sync(0xffu, mm, o));
        if (tid == 0) sm[0] = mm;
    }
    __syncthreads();
    float M = sm[0];
    float e0 = expf(v0 - M), e1 = expf(v1 - M);
    float s = e0 + e1;
#pragma unroll
    for (int o = 16; o; o >>= 1) s += __shfl_xor_sync(~0u, s, o);
    if ((tid & 31) == 0) ss[tid >> 5] = s;
    __syncthreads();
    if (tid < 8) {
        float t2 = ss[tid];
#pragma unroll
        for (int o = 4; o; o >>= 1) t2 += __shfl_xor_sync(0xffu, t2, o);
        if (tid == 0) ss[0] = t2;
    }
    __syncthreads();
    float inv = 1.f / ss[0];
    float a0 = e0 * inv, a1 = e1 * inv;
    p[tid] = a0;
    p[tid + 256] = a1;
    __nv_bfloat16 h0 = __float2bfloat16(a0), h1 = __float2bfloat16(a1);
    g_ath[base + tid]       = h0;
    g_atl[base + tid]       = __float2bfloat16(a0 - __bfloat162float(h0));
    g_ath[base + tid + 256] = h1;
    g_atl[base + tid + 256] = __float2bfloat16(a1 - __bfloat162float(h1));
}

// ---------------------------------------------------------------------------
// scatter O into conv_o input, pixel-major bf16 hi/lo [b][p][ci]
// ---------------------------------------------------------------------------
__global__ void remap_sa_bf16()
{
    int e = blockIdx.x * 256 + threadIdx.x;
    int b  = e >> 20;
    int p  = (e >> 9) & 2047;
    int d2 = e & 511;
    int s  = p >> 8;
    int rh = p & 255;
    int r2 = rh >> 3, h2 = rh & 7;
    int n  = b * 8 + s;
    int qd = r2 * 16 + h2 * 2 + (d2 >> 8);
    int rr = (d2 & 255) >> 3;
    int hh = d2 & 7;
    float v = g_On[n * 131072 + qd * 256 + hh * 32 + rr];
    __nv_bfloat16 h = __float2bfloat16(v);
    g_sah[e] = h;
    g_sal[e] = __float2bfloat16(v - __bfloat162float(h));
}

// ---------------------------------------------------------------------------
extern "C" void kernel_launch(void* const* d_in, const int* in_sizes, int n_in,
                              void* d_out, int out_size)
{
    const float* q  = (const float*)d_in[0];
    const float* k  = (const float*)d_in[1];
    const float* v  = (const float*)d_in[2];
    const float* Wq = (const float*)d_in[3];
    const float* bq = (const float*)d_in[4];
    const float* Wk = (const float*)d_in[5];
    const float* bk = (const float*)d_in[6];
    const float* Wv = (const float*)d_in[7];
    const float* bv = (const float*)d_in[8];
    const float* Wo = (const float*)d_in[9];
    const float* bo = (const float*)d_in[10];

    float* y_out    = (float*)d_out;            // (4,512,8,32,8) = 4194304
    float* attn_out = y_out + NELEM;            // (1,32,512,512) = 8388608

    cudaFuncSetAttribute(conv_qkv_mma, cudaFuncAttributeMaxDynamicSharedMemorySize, SMEM_BYTES_CONV);
    cudaFuncSetAttribute(conv_o_mma,   cudaFuncAttributeMaxDynamicSharedMemorySize, SMEM_BYTES_CONV);
    cudaFuncSetAttribute(gemm_scores,  cudaFuncAttributeMaxDynamicSharedMemorySize, SMEM_BYTES_GEMM);
    cudaFuncSetAttribute(gemm_nnout,   cudaFuncAttributeMaxDynamicSharedMemorySize, SMEM_BYTES_GEMM);

    // launch order arranged so the ncu capture (launch index 3) hits conv_qkv_mma
    prep_w<<<4 * WSZ / 256, 256>>>(Wq, Wk, Wv, Wo);                      // 0
    prep_x<<<dim3(8, 16, 64), dim3(32, 8)>>>(q, k, v, 0);                // 1
    prep_x<<<dim3(8, 16, 32), dim3(32, 8)>>>(q, k, v, 64);               // 2
    conv_qkv_mma<<<dim3(64, 4, 3), 256, SMEM_BYTES_CONV>>>(bq, bk, bv);  // 3  <- profiled
    remap_V<<<NELEM / 256, 256>>>();                                     // 4
    gemm_scores<<<dim3(4, 4, 32), 256, SMEM_BYTES_GEMM>>>(attn_out);     // 5
    softmax_rows<<<32 * 512, 256>>>(attn_out);                           // 6
    gemm_nnout<<<dim3(2, 4, 32), 256, SMEM_BYTES_GEMM>>>();              // 7
    remap_sa_bf16<<<NELEM / 256, 256>>>();                               // 8
    conv_o_mma<<<dim3(64, 4, 1), 256, SMEM_BYTES_CONV>>>(bo, y_out);     // 9
}

// round 10
// speedup vs baseline: 2.2272x; 1.8863x over previous
#include <cuda_runtime.h>
#include <cuda_bf16.h>
#include <cstdint>

#define NELEM 4194304          // 32*512*256 == 4*512*2048
#define UPSZ  262144           // 512*512 (one U plane)
#define VPSZ  1048576          // 2048*512 (one V / M plane)

// ---------------------------------------------------------------------------
// device scratch
// ---------------------------------------------------------------------------
__device__ float g_xf[3*NELEM];          // qkv inputs fp32 pixel-major [z][n][pix][ci]
__device__ float g_saf[NELEM];           // conv_o input fp32 pixel-major [b][pix][ci]
__device__ __nv_bfloat16 g_Uh[64*UPSZ];  // wino weights [conv*16+pos][co][ci]
__device__ __nv_bfloat16 g_Ul[64*UPSZ];
__device__ __nv_bfloat16 g_Vh[48*VPSZ];  // wino inputs  [plane][tile][ci]
__device__ __nv_bfloat16 g_Vl[48*VPSZ];
__device__ float g_M[48*VPSZ];           // GEMM out     [plane][co][tile]
__device__ float g_y0[NELEM];            // conv outputs (32,512,256) fp32
__device__ float g_y1[NELEM];
__device__ float g_y2[NELEM];
__device__ __nv_bfloat16 g_Qh[NELEM], g_Ql[NELEM];   // [n][d][c], c=h*32+r
__device__ __nv_bfloat16 g_Kh[NELEM], g_Kl[NELEM];
__device__ __nv_bfloat16 g_Vth[NELEM], g_Vtl[NELEM]; // transposed: [n][c][dk]
__device__ __nv_bfloat16 g_ath[2*NELEM], g_atl[2*NELEM]; // attn hi/lo
__device__ float g_On[NELEM];            // attn @ V  [n][qd][c]

// ---------------------------------------------------------------------------
// helpers
// ---------------------------------------------------------------------------
__device__ __forceinline__ uint32_t smem_u32(const void* p) {
    uint32_t a;
    asm("{ .reg .u64 t; cvta.to.shared.u64 t, %1; cvt.u32.u64 %0, t; }" : "=r"(a) : "l"(p));
    return a;
}
#define SWZ(o) ((o) ^ (((o) >> 3) & 0x70))
#define CPA(dst, src, sz) \
    asm volatile("cp.async.cg.shared.global [%0], [%1], 16, %2;" \
        :: "r"(dst), "l"(src), "r"(sz) : "memory")
#define LDM4(r, addr) \
    asm volatile("ldmatrix.sync.aligned.m8n8.x4.shared.b16 {%0,%1,%2,%3}, [%4];" \
        : "=r"((r)[0]), "=r"((r)[1]), "=r"((r)[2]), "=r"((r)[3]) : "r"(addr))
#define MMA_BF16(d, a, b0, b1) \
    asm volatile("mma.sync.aligned.m16n8k16.row.col.f32.bf16.bf16.f32 " \
        "{%0,%1,%2,%3}, {%4,%5,%6,%7}, {%8,%9}, {%0,%1,%2,%3};" \
        : "+f"((d)[0]), "+f"((d)[1]), "+f"((d)[2]), "+f"((d)[3]) \
        : "r"((a)[0]), "r"((a)[1]), "r"((a)[2]), "r"((a)[3]), "r"(b0), "r"(b1))
#define WAITP(addr, ph) do { \
    asm volatile("{\n\t.reg .pred P;\n\tWL%=:\n\t" \
        "mbarrier.try_wait.parity.acquire.cta.shared::cta.b64 P, [%0], %1, 0x989680;\n\t" \
        "@P bra.uni WD%=;\n\tbra.uni WL%=;\n\tWD%=:\n\t}" \
        :: "r"(addr), "r"(ph) : "memory"); \
} while (0)

// K32 chunk; packed layout: two 64B K-rows per 128B line.
// stage (32KB): Ah 0, Al 8K, Bh 16K, Bl 24K. 3 stages + mbarriers at tail.
#define STAGE 32768u
#define MBAR_BASE 98304u
#define SMEM_BYTES 98368
#define PROW(r) ((uint32_t)((((r) >> 1) << 7) | (((r) & 1) << 6)))

// ---------------------------------------------------------------------------
// compute one K32 chunk, warp tile 64x32: D += Ah*Bh + Ah*Bl + Al*Bh
// ---------------------------------------------------------------------------
__device__ __forceinline__ void mma_compute32(uint32_t bs, uint32_t a_rowb,
                                              uint32_t b_rowb, float (&acc)[16][4])
{
#pragma unroll
    for (int s = 0; s < 2; ++s) {
        uint32_t ah[4][4], bb[2][4], blf[2][4];
#pragma unroll
        for (int i = 0; i < 4; ++i)
            LDM4(ah[i], bs + SWZ(a_rowb + i * 1024 + s * 32));
#pragma unroll
        for (int j = 0; j < 2; ++j)
            LDM4(bb[j], bs + 16384u + SWZ(b_rowb + j * 1024 + s * 32));
#pragma unroll
        for (int i = 0; i < 4; ++i)
#pragma unroll
            for (int jj = 0; jj < 4; ++jj)
                MMA_BF16(acc[i * 4 + jj], ah[i],
                         bb[jj >> 1][(jj & 1) * 2], bb[jj >> 1][(jj & 1) * 2 + 1]);
#pragma unroll
        for (int j = 0; j < 2; ++j)
            LDM4(blf[j], bs + 24576u + SWZ(b_rowb + j * 1024 + s * 32));
#pragma unroll
        for (int i = 0; i < 4; ++i)
#pragma unroll
            for (int jj = 0; jj < 4; ++jj)
                MMA_BF16(acc[i * 4 + jj], ah[i],
                         blf[jj >> 1][(jj & 1) * 2], blf[jj >> 1][(jj & 1) * 2 + 1]);
#pragma unroll
        for (int i = 0; i < 4; ++i)
            LDM4(ah[i], bs + 8192u + SWZ(a_rowb + i * 1024 + s * 32));
#pragma unroll
        for (int i = 0; i < 4; ++i)
#pragma unroll
            for (int jj = 0; jj < 4; ++jj)
                MMA_BF16(acc[i * 4 + jj], ah[i],
                         bb[jj >> 1][(jj & 1) * 2], bb[jj >> 1][(jj & 1) * 2 + 1]);
    }
}

// ---------------------------------------------------------------------------
// mbarrier-pipelined GEMM: C(MxN) = A(MxK) * B(NxK)^T, bf16 hi/lo 3-term.
// CTA tile 128x128, warp tile 64x32, K32 chunks, 3 stages, 2 CTAs/SM.
// ---------------------------------------------------------------------------
__device__ __forceinline__ void gemm_mb(
    const __nv_bfloat16* __restrict__ Ah, const __nv_bfloat16* __restrict__ Al,
    const __nv_bfloat16* __restrict__ Bh, const __nv_bfloat16* __restrict__ Bl,
    int Kdim, int nchunk, float* __restrict__ C, int ldc)
{
    extern __shared__ char smem[];
    uint32_t sb = smem_u32(smem);
    int tid = threadIdx.x, wid = tid >> 5, lane = tid & 31;
    int m0 = blockIdx.y * 128, n0 = blockIdx.x * 128;
    int wm = wid & 1, wn = wid >> 1;

    int lr = tid >> 1, lh = tid & 1;
    uint32_t stb = PROW(lr) + lh * 32u;
    const char* srcA_h = (const char*)(Ah + (size_t)(m0 + lr) * Kdim + lh * 16);
    const char* srcA_l = (const char*)(Al + (size_t)(m0 + lr) * Kdim + lh * 16);
    const char* srcB_h = (const char*)(Bh + (size_t)(n0 + lr) * Kdim + lh * 16);
    const char* srcB_l = (const char*)(Bl + (size_t)(n0 + lr) * Kdim + lh * 16);

    int arow = wm * 64 + (lane & 15);
    uint32_t a_rowb = PROW(arow) + ((lane & 16) ? 16u : 0u);
    int brow = wn * 32 + (lane & 7) + ((lane & 16) ? 8 : 0);
    uint32_t b_rowb = PROW(brow) + ((lane & 8) ? 16u : 0u);

    if (tid == 0) {
#pragma unroll
        for (int s = 0; s < 3; ++s) {
            asm volatile("mbarrier.init.shared.b64 [%0], %1;"
                         :: "r"(sb + MBAR_BASE + s * 16u), "r"(256) : "memory");
            asm volatile("mbarrier.init.shared.b64 [%0], %1;"
                         :: "r"(sb + MBAR_BASE + s * 16u + 8u), "r"(256) : "memory");
        }
    }
    __syncthreads();

    float acc[16][4];
#pragma unroll
    for (int i = 0; i < 16; ++i)
#pragma unroll
        for (int j = 0; j < 4; ++j) acc[i][j] = 0.f;

    int ps = 0, pph = 1;
    int cs = 0, cph = 0;

    auto produce = [&](int itn) {
        uint32_t fmb = sb + MBAR_BASE + (uint32_t)ps * 16u;
        WAITP(fmb + 8u, pph);
        int cb = itn * 64;                  // bytes along K (32 bf16)
        uint32_t bs = sb + (uint32_t)ps * STAGE;
        uint32_t s0 = SWZ(stb), s1 = SWZ(stb + 16u);
        CPA(bs + s0,          srcA_h + cb,      16u);
        CPA(bs + s1,          srcA_h + cb + 16, 16u);
        CPA(bs + 8192u + s0,  srcA_l + cb,      16u);
        CPA(bs + 8192u + s1,  srcA_l + cb + 16, 16u);
        CPA(bs + 16384u + s0, srcB_h + cb,      16u);
        CPA(bs + 16384u + s1, srcB_h + cb + 16, 16u);
        CPA(bs + 24576u + s0, srcB_l + cb,      16u);
        CPA(bs + 24576u + s1, srcB_l + cb + 16, 16u);
        asm volatile("cp.async.mbarrier.arrive.noinc.shared::cta.b64 [%0];"
                     :: "r"(fmb) : "memory");
        if (++ps == 3) { ps = 0; pph ^= 1; }
    };

    produce(0);
    produce(1);
    for (int it = 0; it < nchunk; ++it) {
        if (it + 2 < nchunk) produce(it + 2);
        uint32_t fmb = sb + MBAR_BASE + (uint32_t)cs * 16u;
        WAITP(fmb, cph);
        mma_compute32(sb + (uint32_t)cs * STAGE, a_rowb, b_rowb, acc);
        asm volatile("mbarrier.arrive.shared::cta.b64 _, [%0];"
                     :: "r"(fmb + 8u) : "memory");
        if (++cs == 3) { cs = 0; cph ^= 1; }
    }

#pragma unroll
    for (int i = 0; i < 4; ++i) {
        int row = m0 + wm * 64 + i * 16 + (lane >> 2);
#pragma unroll
        for (int jj = 0; jj < 4; ++jj) {
            int col = n0 + wn * 32 + jj * 8 + (lane & 3) * 2;
            float* d = acc[i * 4 + jj];
            *(float2*)&C[(size_t)row * ldc + col]       = make_float2(d[0], d[1]);
            *(float2*)&C[(size_t)(row + 8) * ldc + col] = make_float2(d[2], d[3]);
        }
    }
}

// ---------------------------------------------------------------------------
// Winograd weight transform: w 3x3 -> U 4x4 = G w G^T, bf16 hi/lo
// U layout [conv*16+pos][co][ci]
// ---------------------------------------------------------------------------
__global__ void prep_wU(const float* __restrict__ Wq, const float* __restrict__ Wk,
                        const float* __restrict__ Wv, const float* __restrict__ Wo)
{
    int g = blockIdx.x * 256 + threadIdx.x;     // 4*512*512
    int conv = g >> 18;
    int r = g & 262143;
    int co = r >> 9, ci = r & 511;
    const float* W = (conv == 0) ? Wq : (conv == 1) ? Wk : (conv == 2) ? Wv : Wo;
    const float* w = W + (size_t)co * 4608 + ci * 9;
    float T[4][3];
#pragma unroll
    for (int k = 0; k < 3; ++k) {
        float a = w[k], b = w[3 + k], c = w[6 + k];
        T[0][k] = a;
        T[1][k] = 0.5f * (a + b + c);
        T[2][k] = 0.5f * (a - b + c);
        T[3][k] = c;
    }
#pragma unroll
    for (int i = 0; i < 4; ++i) {
        float U0 = T[i][0];
        float U1 = 0.5f * (T[i][0] + T[i][1] + T[i][2]);
        float U2 = 0.5f * (T[i][0] - T[i][1] + T[i][2]);
        float U3 = T[i][2];
        float u[4] = {U0, U1, U2, U3};
#pragma unroll
        for (int j = 0; j < 4; ++j) {
            size_t o = ((size_t)(conv * 16 + i * 4 + j) * 512 + co) * 512 + ci;
            __nv_bfloat16 h = __float2bfloat16(u[j]);
            g_Uh[o] = h;
            g_Ul[o] = __float2bfloat16(u[j] - __bfloat162float(h));
        }
    }
}

// ---------------------------------------------------------------------------
// transpose q/k/v to fp32 pixel-major [z][n][pix][ci]
// ---------------------------------------------------------------------------
__global__ void prep_xf(const float* __restrict__ q, const float* __restrict__ k,
                        const float* __restrict__ v)
{
    __shared__ float tile[32][33];
    int zz = blockIdx.z;
    int z = zz >> 5, n = zz & 31;
    const float* src = (z == 0) ? q : (z == 1) ? k : v;
    const float* xin = src + (size_t)n * 131072;
    float* out = g_xf + (size_t)z * NELEM + (size_t)n * 131072;
    int p0 = blockIdx.x * 32, c0 = blockIdx.y * 32;
    int tx = threadIdx.x, ty = threadIdx.y;
#pragma unroll
    for (int j = 0; j < 4; ++j)
        tile[ty + 8 * j][tx] = xin[(size_t)(c0 + ty + 8 * j) * 256 + p0 + tx];
    __syncthreads();
#pragma unroll
    for (int j = 0; j < 4; ++j)
        out[(size_t)(p0 + ty + 8 * j) * 512 + c0 + tx] = tile[tx][ty + 8 * j];
}

// ---------------------------------------------------------------------------
// Winograd input transform core: d = B^T X B (4x4), hi/lo split, store V plane
// ---------------------------------------------------------------------------
__device__ __forceinline__ void wino_in_store(const float (&X)[4][4],
                                              int vbase, int m, int ci)
{
    float T[4][4];
#pragma unroll
    for (int c = 0; c < 4; ++c) {
        T[0][c] = X[0][c] - X[2][c];
        T[1][c] = X[1][c] + X[2][c];
        T[2][c] = X[2][c] - X[1][c];
        T[3][c] = X[1][c] - X[3][c];
    }
#pragma unroll
    for (int i = 0; i < 4; ++i) {
        float d0 = T[i][0] - T[i][2];
        float d1 = T[i][1] + T[i][2];
        float d2 = T[i][2] - T[i][1];
        float d3 = T[i][1] - T[i][3];
        float dd[4] = {d0, d1, d2, d3};
#pragma unroll
        for (int j = 0; j < 4; ++j) {
            size_t o = ((size_t)(vbase + i * 4 + j) * 2048 + m) * 512 + ci;
            __nv_bfloat16 h = __float2bfloat16(dd[j]);
            g_Vh[o] = h;
            g_Vl[o] = __float2bfloat16(dd[j] - __bfloat162float(h));
        }
    }
}

// qkv: H=32, W=8, tiles 16x4 per image, 32 images -> M=2048 per conv
__global__ void wino_in_qkv()
{
    int z = blockIdx.y;
    int e = blockIdx.x * 256 + threadIdx.x;     // 2048*512
    int ci = e & 511, m = e >> 9;
    int img = m >> 6, mr = m & 63;
    int ty = mr >> 2, tx = mr & 3;
    const float* src = g_xf + (size_t)z * NELEM + (size_t)img * 131072 + ci;
    int y0 = 2 * ty - 1, x0 = 2 * tx - 1;
    float X[4][4];
#pragma unroll
    for (int r = 0; r < 4; ++r) {
        int y = y0 + r;
#pragma unroll
        for (int c = 0; c < 4; ++c) {
            int x = x0 + c;
            bool ok = ((unsigned)y < 32u) && ((unsigned)x < 8u);
            X[r][c] = ok ? src[(size_t)(y * 8 + x) * 512] : 0.f;
        }
    }
    wino_in_store(X, z * 16, m, ci);
}

// conv_o: H=8, W=256, tiles 4x128 per image, 4 images -> M=2048
__global__ void wino_in_o()
{
    int e = blockIdx.x * 256 + threadIdx.x;     // 2048*512
    int ci = e & 511, m = e >> 9;
    int img = m >> 9, mr = m & 511;
    int ty = mr >> 7, tx = mr & 127;
    const float* src = g_saf + (size_t)img * 1048576 + ci;
    int y0 = 2 * ty - 1, x0 = 2 * tx - 1;
    float X[4][4];
#pragma unroll
    for (int r = 0; r < 4; ++r) {
        int y = y0 + r;
#pragma unroll
        for (int c = 0; c < 4; ++c) {
            int x = x0 + c;
            bool ok = ((unsigned)y < 8u) && ((unsigned)x < 256u);
            X[r][c] = ok ? src[(size_t)(y * 256 + x) * 512] : 0.f;
        }
    }
    wino_in_store(X, 0, m, ci);
}

// ---------------------------------------------------------------------------
// Winograd GEMM: per plane, C[co][tile] = U[co][ci] . V[tile][ci]^T
// ---------------------------------------------------------------------------
__global__ __launch_bounds__(256, 2) void gemm_wino(int ubase)
{
    int zp = blockIdx.z;
    const __nv_bfloat16* Ah = g_Uh + (size_t)(ubase + zp) * UPSZ;
    const __nv_bfloat16* Al = g_Ul + (size_t)(ubase + zp) * UPSZ;
    const __nv_bfloat16* Bh = g_Vh + (size_t)zp * VPSZ;
    const __nv_bfloat16* Bl = g_Vl + (size_t)zp * VPSZ;
    float* C = g_M + (size_t)zp * VPSZ;
    gemm_mb(Ah, Al, Bh, Bl, 512, 16, C, 2048);
}

// ---------------------------------------------------------------------------
// Winograd inverse transform -> y (qkv): Y = A^T m A + bias
// ---------------------------------------------------------------------------
__device__ __forceinline__ void wino_inv(const float (&mm)[16],
                                         float& Y00, float& Y01,
                                         float& Y10, float& Y11)
{
    float s0[4], s1[4];
#pragma unroll
    for (int k = 0; k < 4; ++k) {
        s0[k] = mm[k] + mm[4 + k] + mm[8 + k];
        s1[k] = mm[4 + k] - mm[8 + k] - mm[12 + k];
    }
    Y00 = s0[0] + s0[1] + s0[2];
    Y01 = s0[1] - s0[2] - s0[3];
    Y10 = s1[0] + s1[1] + s1[2];
    Y11 = s1[1] - s1[2] - s1[3];
}

__global__ void wino_out_y(const float* __restrict__ bq, const float* __restrict__ bk,
                           const float* __restrict__ bv)
{
    // grid 12288 = 3z * 32n * 128cg; block 256 = 4 co x 64 mlocal
    int blk = blockIdx.x;
    int z = blk >> 12;
    int r = blk & 4095;
    int n = r >> 7, cg = r & 127;
    int tid = threadIdx.x;
    int cl = tid >> 6, ml = tid & 63;
    int co = cg * 4 + cl;
    int m = n * 64 + ml;
    const float* bias = (z == 0) ? bq : (z == 1) ? bk : bv;
    float mm[16];
#pragma unroll
    for (int p = 0; p < 16; ++p)
        mm[p] = g_M[((size_t)(z * 16 + p) * 512 + co) * 2048 + m];
    float Y00, Y01, Y10, Y11;
    wino_inv(mm, Y00, Y01, Y10, Y11);
    float b = bias[co];
    int ty = ml >> 2, tx = ml & 3;
    float* y = (z == 0) ? g_y0 : (z == 1) ? g_y1 : g_y2;
    float* dst = y + ((size_t)n * 512 + co) * 256 + (2 * ty) * 8 + 2 * tx;
    *(float2*)&dst[0] = make_float2(Y00 + b, Y01 + b);
    *(float2*)&dst[8] = make_float2(Y10 + b, Y11 + b);
}

__global__ void wino_out_o(const float* __restrict__ bo, float* __restrict__ out)
{
    // grid 8192 = (b*4+ty)*512co ... block 128 = tx
    int tx = threadIdx.x;
    int co = blockIdx.x & 511;
    int bt = blockIdx.x >> 9;
    int b = bt >> 2, ty = bt & 3;
    int m = b * 512 + ty * 128 + tx;
    float mm[16];
#pragma unroll
    for (int p = 0; p < 16; ++p)
        mm[p] = g_M[((size_t)p * 512 + co) * 2048 + m];
    float Y00, Y01, Y10, Y11;
    wino_inv(mm, Y00, Y01, Y10, Y11);
    float bb = bo[co];
    float* dst = out + ((size_t)b * 512 + co) * 2048 + (2 * ty) * 256 + 2 * tx;
    *(float2*)&dst[0]   = make_float2(Y00 + bb, Y01 + bb);
    *(float2*)&dst[256] = make_float2(Y10 + bb, Y11 + bb);
}

// ---------------------------------------------------------------------------
// gather conv outputs into per-n bf16 hi/lo Q/K (row) and V (transposed)
// ---------------------------------------------------------------------------
__global__ void remap_qkvT()
{
    int t = blockIdx.x * 256 + threadIdx.x;
    int which = t >> 22;
    int e = t & (NELEM - 1);
    if (which == 2) {
        int n = e >> 17, c = (e >> 9) & 255, dk = e & 511;
        int h = c >> 5, r = c & 31;
        float v = g_y2[(h * 4 + (n >> 3)) * 131072 + ((n & 7) * 64 + (dk >> 3)) * 256
                       + (dk & 7) * 32 + r];
        __nv_bfloat16 hh = __float2bfloat16(v);
        g_Vth[e] = hh;
        g_Vtl[e] = __float2bfloat16(v - __bfloat162float(hh));
    } else {
        int n = e >> 17, d = (e >> 8) & 511, h = (e >> 5) & 7, r = e & 31;
        const float* src = which ? g_y1 : g_y0;
        float v = src[(h * 4 + (n >> 3)) * 131072 + ((n & 7) * 64 + (d >> 3)) * 256
                      + (d & 7) * 32 + r];
        __nv_bfloat16 hh = __float2bfloat16(v);
        __nv_bfloat16 ll = __float2bfloat16(v - __bfloat162float(hh));
        if (which) { g_Kh[e] = hh; g_Kl[e] = ll; }
        else       { g_Qh[e] = hh; g_Ql[e] = ll; }
    }
}

// ---------------------------------------------------------------------------
// attention GEMMs (mbarrier pipeline)
// ---------------------------------------------------------------------------
__global__ __launch_bounds__(256, 2) void gemm_scores(float* __restrict__ attn)
{
    int nb = blockIdx.z;
    gemm_mb(g_Qh + (size_t)nb * 131072, g_Ql + (size_t)nb * 131072,
            g_Kh + (size_t)nb * 131072, g_Kl + (size_t)nb * 131072,
            256, 8, attn + (size_t)nb * 262144, 512);
}

__global__ __launch_bounds__(256, 2) void gemm_nnout()
{
    int nb = blockIdx.z;
    gemm_mb(g_ath + (size_t)nb * 262144, g_atl + (size_t)nb * 262144,
            g_Vth + (size_t)nb * 131072, g_Vtl + (size_t)nb * 131072,
            512, 16, g_On + (size_t)nb * 131072, 256);
}

// ---------------------------------------------------------------------------
// softmax over 512-wide rows, in place; also emit bf16 hi/lo
// ---------------------------------------------------------------------------
__global__ void softmax_rows(float* __restrict__ attn)
{
    size_t base = (size_t)blockIdx.x * 512;
    float* p = attn + base;
    int tid = threadIdx.x;
    float v0 = p[tid], v1 = p[tid + 256];
    float m = fmaxf(v0, v1);
#pragma unroll
    for (int o = 16; o; o >>= 1) m = fmaxf(m, __shfl_xor_sync(~0u, m, o));
    __shared__ float sm[8], ss[8];
    if ((tid & 31) == 0) sm[tid >> 5] = m;
    __syncthreads();
    if (tid < 8) {
        float mm = sm[tid];
#pragma unroll
        for (int o = 4; o; o >>= 1) mm = fmaxf(mm, __shfl_xor_sync(0xffu, mm, o));
        if (tid == 0) sm[0] = mm;
    }
    __syncthreads();
    float M = sm[0];
    float e0 = expf(v0 - M), e1 = expf(v1 - M);
    float s = e0 + e1;
#pragma unroll
    for (int o = 16; o; o >>= 1) s += __shfl_xor_sync(~0u, s, o);
    if ((tid & 31) == 0) ss[tid >> 5] = s;
    __syncthreads();
    if (tid < 8) {
        float t2 = ss[tid];
#pragma unroll
        for (int o = 4; o; o >>= 1) t2 += __shfl_xor_sync(0xffu, t2, o);
        if (tid == 0) ss[0] = t2;
    }
    __syncthreads();
    float inv = 1.f / ss[0];
    float a0 = e0 * inv, a1 = e1 * inv;
    p[tid] = a0;
    p[tid + 256] = a1;
    __nv_bfloat16 h0 = __float2bfloat16(a0), h1 = __float2bfloat16(a1);
    g_ath[base + tid]       = h0;
    g_atl[base + tid]       = __float2bfloat16(a0 - __bfloat162float(h0));
    g_ath[base + tid + 256] = h1;
    g_atl[base + tid + 256] = __float2bfloat16(a1 - __bfloat162float(h1));
}

// ---------------------------------------------------------------------------
// scatter O into conv_o input, fp32 pixel-major [b][pix][ci]
// ---------------------------------------------------------------------------
__global__ void remap_saf()
{
    int e = blockIdx.x * 256 + threadIdx.x;
    int b  = e >> 20;
    int p  = (e >> 9) & 2047;
    int d2 = e & 511;
    int s  = p >> 8;
    int rh = p & 255;
    int r2 = rh >> 3, h2 = rh & 7;
    int n  = b * 8 + s;
    int qd = r2 * 16 + h2 * 2 + (d2 >> 8);
    int rr = (d2 & 255) >> 3;
    int hh = d2 & 7;
    g_saf[e] = g_On[n * 131072 + qd * 256 + hh * 32 + rr];
}

// ---------------------------------------------------------------------------
extern "C" void kernel_launch(void* const* d_in, const int* in_sizes, int n_in,
                              void* d_out, int out_size)
{
    const float* q  = (const float*)d_in[0];
    const float* k  = (const float*)d_in[1];
    const float* v  = (const float*)d_in[2];
    const float* Wq = (const float*)d_in[3];
    const float* bq = (const float*)d_in[4];
    const float* Wk = (const float*)d_in[5];
    const float* bk = (const float*)d_in[6];
    const float* Wv = (const float*)d_in[7];
    const float* bv = (const float*)d_in[8];
    const float* Wo = (const float*)d_in[9];
    const float* bo = (const float*)d_in[10];

    float* y_out    = (float*)d_out;            // (4,512,8,32,8) = 4194304
    float* attn_out = y_out + NELEM;            // (1,32,512,512) = 8388608

    cudaFuncSetAttribute(gemm_wino,   cudaFuncAttributeMaxDynamicSharedMemorySize, SMEM_BYTES);
    cudaFuncSetAttribute(gemm_scores, cudaFuncAttributeMaxDynamicSharedMemorySize, SMEM_BYTES);
    cudaFuncSetAttribute(gemm_nnout,  cudaFuncAttributeMaxDynamicSharedMemorySize, SMEM_BYTES);

    // launch order: index 3 = gemm_wino (qkv) -- the dominant kernel, profiled
    prep_wU<<<4096, 256>>>(Wq, Wk, Wv, Wo);                          // 0
    prep_xf<<<dim3(8, 16, 96), dim3(32, 8)>>>(q, k, v);              // 1
    wino_in_qkv<<<dim3(4096, 3), 256>>>();                           // 2
    gemm_wino<<<dim3(16, 4, 48), 256, SMEM_BYTES>>>(0);              // 3  <- profiled
    wino_out_y<<<12288, 256>>>(bq, bk, bv);                          // 4
    remap_qkvT<<<3 * NELEM / 256, 256>>>();                          // 5
    gemm_scores<<<dim3(4, 4, 32), 256, SMEM_BYTES>>>(attn_out);      // 6
    softmax_rows<<<32 * 512, 256>>>(attn_out);                       // 7
    gemm_nnout<<<dim3(2, 4, 32), 256, SMEM_BYTES>>>();               // 8
    remap_saf<<<NELEM / 256, 256>>>();                               // 9
    wino_in_o<<<4096, 256>>>();                                      // 10
    gemm_wino<<<dim3(16, 4, 16), 256, SMEM_BYTES>>>(48);             // 11
    wino_out_o<<<8192, 128>>>(bo, y_out);                            // 12
}

// round 11
// speedup vs baseline: 2.3199x; 1.0416x over previous
#include <cuda_runtime.h>
#include <cuda_bf16.h>
#include <cstdint>

#define NELEM 4194304          // 32*512*256 == 4*512*2048
#define UPSZ  262144           // 512*512 (one U plane)
#define VPSZ  1048576          // 2048*512 (one V / M plane)

// ---------------------------------------------------------------------------
// device scratch
// ---------------------------------------------------------------------------
__device__ float g_xf[3*NELEM];          // qkv inputs fp32 pixel-major [z][n][pix][ci]
__device__ float g_saf[NELEM];           // conv_o input fp32 pixel-major [b][pix][ci]
__device__ __nv_bfloat16 g_Uh[64*UPSZ];  // wino weights [conv*16+pos][co][ci]
__device__ __nv_bfloat16 g_Ul[64*UPSZ];
__device__ __nv_bfloat16 g_Vh[48*VPSZ];  // wino inputs  [plane][tile][ci]
__device__ __nv_bfloat16 g_Vl[48*VPSZ];
__device__ float g_M[48*VPSZ];           // GEMM out     [plane][co][tile]
__device__ float g_y2[NELEM];            // conv(v) output (32,512,256) fp32
__device__ __nv_bfloat16 g_Qh[NELEM], g_Ql[NELEM];   // [n][d][c], c=h*32+r
__device__ __nv_bfloat16 g_Kh[NELEM], g_Kl[NELEM];
__device__ __nv_bfloat16 g_Vth[NELEM], g_Vtl[NELEM]; // transposed: [n][c][dk]
__device__ __nv_bfloat16 g_ath[2*NELEM], g_atl[2*NELEM]; // attn hi/lo
__device__ float g_On[NELEM];            // attn @ V  [n][qd][c]

// ---------------------------------------------------------------------------
// helpers
// ---------------------------------------------------------------------------
__device__ __forceinline__ uint32_t smem_u32(const void* p) {
    uint32_t a;
    asm("{ .reg .u64 t; cvta.to.shared.u64 t, %1; cvt.u32.u64 %0, t; }" : "=r"(a) : "l"(p));
    return a;
}
#define SWZ(o) ((o) ^ (((o) >> 3) & 0x70))
#define CPA(dst, src, sz) \
    asm volatile("cp.async.cg.shared.global [%0], [%1], 16, %2;" \
        :: "r"(dst), "l"(src), "r"(sz) : "memory")
#define LDM4(r, addr) \
    asm volatile("ldmatrix.sync.aligned.m8n8.x4.shared.b16 {%0,%1,%2,%3}, [%4];" \
        : "=r"((r)[0]), "=r"((r)[1]), "=r"((r)[2]), "=r"((r)[3]) : "r"(addr))
#define MMA_BF16(d, a, b0, b1) \
    asm volatile("mma.sync.aligned.m16n8k16.row.col.f32.bf16.bf16.f32 " \
        "{%0,%1,%2,%3}, {%4,%5,%6,%7}, {%8,%9}, {%0,%1,%2,%3};" \
        : "+f"((d)[0]), "+f"((d)[1]), "+f"((d)[2]), "+f"((d)[3]) \
        : "r"((a)[0]), "r"((a)[1]), "r"((a)[2]), "r"((a)[3]), "r"(b0), "r"(b1))
#define WAITP(addr, ph) do { \
    asm volatile("{\n\t.reg .pred P;\n\tWL%=:\n\t" \
        "mbarrier.try_wait.parity.acquire.cta.shared::cta.b64 P, [%0], %1, 0x989680;\n\t" \
        "@P bra.uni WD%=;\n\tbra.uni WL%=;\n\tWD%=:\n\t}" \
        :: "r"(addr), "r"(ph) : "memory"); \
} while (0)

#define STAGE 32768u
#define MBAR_BASE 98304u
#define SMEM_BYTES 98368
#define PROW(r) ((uint32_t)((((r) >> 1) << 7) | (((r) & 1) << 6)))

// pack two fp32 -> bf16x2 hi and lo parts
__device__ __forceinline__ void split2(float v0, float v1, uint32_t& hp, uint32_t& lp) {
    __nv_bfloat16 h0 = __float2bfloat16(v0);
    __nv_bfloat16 h1 = __float2bfloat16(v1);
    __nv_bfloat16 l0 = __float2bfloat16(v0 - __bfloat162float(h0));
    __nv_bfloat16 l1 = __float2bfloat16(v1 - __bfloat162float(h1));
    hp = (uint32_t)*(uint16_t*)&h0 | ((uint32_t)*(uint16_t*)&h1 << 16);
    lp = (uint32_t)*(uint16_t*)&l0 | ((uint32_t)*(uint16_t*)&l1 << 16);
}

// ---------------------------------------------------------------------------
// compute one K32 chunk, warp tile 64x32: D += Ah*Bh + Ah*Bl + Al*Bh
// ---------------------------------------------------------------------------
__device__ __forceinline__ void mma_compute32(uint32_t bs, uint32_t a_rowb,
                                              uint32_t b_rowb, float (&acc)[16][4])
{
#pragma unroll
    for (int s = 0; s < 2; ++s) {
        uint32_t ah[4][4], bb[2][4], blf[2][4];
#pragma unroll
        for (int i = 0; i < 4; ++i)
            LDM4(ah[i], bs + SWZ(a_rowb + i * 1024 + s * 32));
#pragma unroll
        for (int j = 0; j < 2; ++j)
            LDM4(bb[j], bs + 16384u + SWZ(b_rowb + j * 1024 + s * 32));
#pragma unroll
        for (int i = 0; i < 4; ++i)
#pragma unroll
            for (int jj = 0; jj < 4; ++jj)
                MMA_BF16(acc[i * 4 + jj], ah[i],
                         bb[jj >> 1][(jj & 1) * 2], bb[jj >> 1][(jj & 1) * 2 + 1]);
#pragma unroll
        for (int j = 0; j < 2; ++j)
            LDM4(blf[j], bs + 24576u + SWZ(b_rowb + j * 1024 + s * 32));
#pragma unroll
        for (int i = 0; i < 4; ++i)
#pragma unroll
            for (int jj = 0; jj < 4; ++jj)
                MMA_BF16(acc[i * 4 + jj], ah[i],
                         blf[jj >> 1][(jj & 1) * 2], blf[jj >> 1][(jj & 1) * 2 + 1]);
#pragma unroll
        for (int i = 0; i < 4; ++i)
            LDM4(ah[i], bs + 8192u + SWZ(a_rowb + i * 1024 + s * 32));
#pragma unroll
        for (int i = 0; i < 4; ++i)
#pragma unroll
            for (int jj = 0; jj < 4; ++jj)
                MMA_BF16(acc[i * 4 + jj], ah[i],
                         bb[jj >> 1][(jj & 1) * 2], bb[jj >> 1][(jj & 1) * 2 + 1]);
    }
}

// ---------------------------------------------------------------------------
// mbarrier-pipelined GEMM: C(MxN) = A(MxK) * B(NxK)^T, bf16 hi/lo 3-term.
// ---------------------------------------------------------------------------
__device__ __forceinline__ void gemm_mb(
    const __nv_bfloat16* __restrict__ Ah, const __nv_bfloat16* __restrict__ Al,
    const __nv_bfloat16* __restrict__ Bh, const __nv_bfloat16* __restrict__ Bl,
    int Kdim, int nchunk, float* __restrict__ C, int ldc)
{
    extern __shared__ char smem[];
    uint32_t sb = smem_u32(smem);
    int tid = threadIdx.x, wid = tid >> 5, lane = tid & 31;
    int m0 = blockIdx.y * 128, n0 = blockIdx.x * 128;
    int wm = wid & 1, wn = wid >> 1;

    int lr = tid >> 1, lh = tid & 1;
    uint32_t stb = PROW(lr) + lh * 32u;
    const char* srcA_h = (const char*)(Ah + (size_t)(m0 + lr) * Kdim + lh * 16);
    const char* srcA_l = (const char*)(Al + (size_t)(m0 + lr) * Kdim + lh * 16);
    const char* srcB_h = (const char*)(Bh + (size_t)(n0 + lr) * Kdim + lh * 16);
    const char* srcB_l = (const char*)(Bl + (size_t)(n0 + lr) * Kdim + lh * 16);

    int arow = wm * 64 + (lane & 15);
    uint32_t a_rowb = PROW(arow) + ((lane & 16) ? 16u : 0u);
    int brow = wn * 32 + (lane & 7) + ((lane & 16) ? 8 : 0);
    uint32_t b_rowb = PROW(brow) + ((lane & 8) ? 16u : 0u);

    if (tid == 0) {
#pragma unroll
        for (int s = 0; s < 3; ++s) {
            asm volatile("mbarrier.init.shared.b64 [%0], %1;"
                         :: "r"(sb + MBAR_BASE + s * 16u), "r"(256) : "memory");
            asm volatile("mbarrier.init.shared.b64 [%0], %1;"
                         :: "r"(sb + MBAR_BASE + s * 16u + 8u), "r"(256) : "memory");
        }
    }
    __syncthreads();

    float acc[16][4];
#pragma unroll
    for (int i = 0; i < 16; ++i)
#pragma unroll
        for (int j = 0; j < 4; ++j) acc[i][j] = 0.f;

    int ps = 0, pph = 1;
    int cs = 0, cph = 0;

    auto produce = [&](int itn) {
        uint32_t fmb = sb + MBAR_BASE + (uint32_t)ps * 16u;
        WAITP(fmb + 8u, pph);
        int cb = itn * 64;
        uint32_t bs = sb + (uint32_t)ps * STAGE;
        uint32_t s0 = SWZ(stb), s1 = SWZ(stb + 16u);
        CPA(bs + s0,          srcA_h + cb,      16u);
        CPA(bs + s1,          srcA_h + cb + 16, 16u);
        CPA(bs + 8192u + s0,  srcA_l + cb,      16u);
        CPA(bs + 8192u + s1,  srcA_l + cb + 16, 16u);
        CPA(bs + 16384u + s0, srcB_h + cb,      16u);
        CPA(bs + 16384u + s1, srcB_h + cb + 16, 16u);
        CPA(bs + 24576u + s0, srcB_l + cb,      16u);
        CPA(bs + 24576u + s1, srcB_l + cb + 16, 16u);
        asm volatile("cp.async.mbarrier.arrive.noinc.shared::cta.b64 [%0];"
                     :: "r"(fmb) : "memory");
        if (++ps == 3) { ps = 0; pph ^= 1; }
    };

    produce(0);
    produce(1);
    for (int it = 0; it < nchunk; ++it) {
        if (it + 2 < nchunk) produce(it + 2);
        uint32_t fmb = sb + MBAR_BASE + (uint32_t)cs * 16u;
        WAITP(fmb, cph);
        mma_compute32(sb + (uint32_t)cs * STAGE, a_rowb, b_rowb, acc);
        asm volatile("mbarrier.arrive.shared::cta.b64 _, [%0];"
                     :: "r"(fmb + 8u) : "memory");
        if (++cs == 3) { cs = 0; cph ^= 1; }
    }

#pragma unroll
    for (int i = 0; i < 4; ++i) {
        int row = m0 + wm * 64 + i * 16 + (lane >> 2);
#pragma unroll
        for (int jj = 0; jj < 4; ++jj) {
            int col = n0 + wn * 32 + jj * 8 + (lane & 3) * 2;
            float* d = acc[i * 4 + jj];
            *(float2*)&C[(size_t)row * ldc + col]       = make_float2(d[0], d[1]);
            *(float2*)&C[(size_t)(row + 8) * ldc + col] = make_float2(d[2], d[3]);
        }
    }
}

// ---------------------------------------------------------------------------
// Winograd weight transform (ci-pair vectorized): U = G w G^T
// ---------------------------------------------------------------------------
__global__ void prep_wU(const float* __restrict__ Wq, const float* __restrict__ Wk,
                        const float* __restrict__ Wv, const float* __restrict__ Wo)
{
    int g = blockIdx.x * 256 + threadIdx.x;     // 4conv * 512co * 256cip
    int conv = g >> 17;
    int r = g & 131071;
    int co = r >> 8, ci = (r & 255) * 2;
    const float* W = (conv == 0) ? Wq : (conv == 1) ? Wk : (conv == 2) ? Wv : Wo;
    const float* w = W + (size_t)co * 4608 + ci * 9;
    float T0[4][3], T1[4][3];
#pragma unroll
    for (int k = 0; k < 3; ++k) {
        float a = w[k], b = w[3 + k], c = w[6 + k];
        T0[0][k] = a; T0[1][k] = 0.5f * (a + b + c);
        T0[2][k] = 0.5f * (a - b + c); T0[3][k] = c;
        float a1 = w[9 + k], b1 = w[12 + k], c1 = w[15 + k];
        T1[0][k] = a1; T1[1][k] = 0.5f * (a1 + b1 + c1);
        T1[2][k] = 0.5f * (a1 - b1 + c1); T1[3][k] = c1;
    }
#pragma unroll
    for (int i = 0; i < 4; ++i) {
        float u0[4] = {T0[i][0], 0.5f * (T0[i][0] + T0[i][1] + T0[i][2]),
                       0.5f * (T0[i][0] - T0[i][1] + T0[i][2]), T0[i][2]};
        float u1[4] = {T1[i][0], 0.5f * (T1[i][0] + T1[i][1] + T1[i][2]),
                       0.5f * (T1[i][0] - T1[i][1] + T1[i][2]), T1[i][2]};
#pragma unroll
        for (int j = 0; j < 4; ++j) {
            size_t o = ((size_t)(conv * 16 + i * 4 + j) * 512 + co) * 512 + ci;
            uint32_t hp, lp;
            split2(u0[j], u1[j], hp, lp);
            *(uint32_t*)&g_Uh[o] = hp;
            *(uint32_t*)&g_Ul[o] = lp;
        }
    }
}

// ---------------------------------------------------------------------------
// transpose q/k/v to fp32 pixel-major [z][n][pix][ci]
// ---------------------------------------------------------------------------
__global__ void prep_xf(const float* __restrict__ q, const float* __restrict__ k,
                        const float* __restrict__ v)
{
    __shared__ float tile[32][33];
    int zz = blockIdx.z;
    int z = zz >> 5, n = zz & 31;
    const float* src = (z == 0) ? q : (z == 1) ? k : v;
    const float* xin = src + (size_t)n * 131072;
    float* out = g_xf + (size_t)z * NELEM + (size_t)n * 131072;
    int p0 = blockIdx.x * 32, c0 = blockIdx.y * 32;
    int tx = threadIdx.x, ty = threadIdx.y;
#pragma unroll
    for (int j = 0; j < 4; ++j)
        tile[ty + 8 * j][tx] = xin[(size_t)(c0 + ty + 8 * j) * 256 + p0 + tx];
    __syncthreads();
#pragma unroll
    for (int j = 0; j < 4; ++j)
        out[(size_t)(p0 + ty + 8 * j) * 512 + c0 + tx] = tile[tx][ty + 8 * j];
}

// ---------------------------------------------------------------------------
// Winograd input transform (ci-pair vectorized): d = B^T X B, store V plane
// ---------------------------------------------------------------------------
__device__ __forceinline__ void wino_in_store2(const float2 (&X)[4][4],
                                               int vbase, int m, int ci)
{
    float2 T[4][4];
#pragma unroll
    for (int c = 0; c < 4; ++c) {
        T[0][c] = make_float2(X[0][c].x - X[2][c].x, X[0][c].y - X[2][c].y);
        T[1][c] = make_float2(X[1][c].x + X[2][c].x, X[1][c].y + X[2][c].y);
        T[2][c] = make_float2(X[2][c].x - X[1][c].x, X[2][c].y - X[1][c].y);
        T[3][c] = make_float2(X[1][c].x - X[3][c].x, X[1][c].y - X[3][c].y);
    }
#pragma unroll
    for (int i = 0; i < 4; ++i) {
        float2 dd[4];
        dd[0] = make_float2(T[i][0].x - T[i][2].x, T[i][0].y - T[i][2].y);
        dd[1] = make_float2(T[i][1].x + T[i][2].x, T[i][1].y + T[i][2].y);
        dd[2] = make_float2(T[i][2].x - T[i][1].x, T[i][2].y - T[i][1].y);
        dd[3] = make_float2(T[i][1].x - T[i][3].x, T[i][1].y - T[i][3].y);
#pragma unroll
        for (int j = 0; j < 4; ++j) {
            size_t o = ((size_t)(vbase + i * 4 + j) * 2048 + m) * 512 + ci;
            uint32_t hp, lp;
            split2(dd[j].x, dd[j].y, hp, lp);
            *(uint32_t*)&g_Vh[o] = hp;
            *(uint32_t*)&g_Vl[o] = lp;
        }
    }
}

// qkv: H=32, W=8, tiles 16x4 per image, 32 images -> M=2048 per conv
__global__ void wino_in_qkv()
{
    int z = blockIdx.y;
    int e = blockIdx.x * 256 + threadIdx.x;     // 2048 * 256
    int ci = (e & 255) * 2, m = e >> 8;
    int img = m >> 6, mr = m & 63;
    int ty = mr >> 2, tx = mr & 3;
    const float* src = g_xf + (size_t)z * NELEM + (size_t)img * 131072 + ci;
    int y0 = 2 * ty - 1, x0 = 2 * tx - 1;
    float2 X[4][4];
#pragma unroll
    for (int r = 0; r < 4; ++r) {
        int y = y0 + r;
#pragma unroll
        for (int c = 0; c < 4; ++c) {
            int x = x0 + c;
            bool ok = ((unsigned)y < 32u) && ((unsigned)x < 8u);
            X[r][c] = ok ? *(const float2*)&src[(size_t)(y * 8 + x) * 512]
                         : make_float2(0.f, 0.f);
        }
    }
    wino_in_store2(X, z * 16, m, ci);
}

// conv_o: H=8, W=256, tiles 4x128 per image, 4 images -> M=2048
__global__ void wino_in_o()
{
    int e = blockIdx.x * 256 + threadIdx.x;     // 2048 * 256
    int ci = (e & 255) * 2, m = e >> 8;
    int img = m >> 9, mr = m & 511;
    int ty = mr >> 7, tx = mr & 127;
    const float* src = g_saf + (size_t)img * 1048576 + ci;
    int y0 = 2 * ty - 1, x0 = 2 * tx - 1;
    float2 X[4][4];
#pragma unroll
    for (int r = 0; r < 4; ++r) {
        int y = y0 + r;
#pragma unroll
        for (int c = 0; c < 4; ++c) {
            int x = x0 + c;
            bool ok = ((unsigned)y < 8u) && ((unsigned)x < 256u);
            X[r][c] = ok ? *(const float2*)&src[(size_t)(y * 256 + x) * 512]
                         : make_float2(0.f, 0.f);
        }
    }
    wino_in_store2(X, 0, m, ci);
}

// ---------------------------------------------------------------------------
// Winograd GEMM: per plane, C[co][tile] = U[co][ci] . V[tile][ci]^T
// ---------------------------------------------------------------------------
__global__ __launch_bounds__(256, 2) void gemm_wino(int ubase)
{
    int zp = blockIdx.z;
    gemm_mb(g_Uh + (size_t)(ubase + zp) * UPSZ, g_Ul + (size_t)(ubase + zp) * UPSZ,
            g_Vh + (size_t)zp * VPSZ, g_Vl + (size_t)zp * VPSZ,
            512, 16, g_M + (size_t)zp * VPSZ, 2048);
}

// ---------------------------------------------------------------------------
// inverse transform: Y = A^T m A
// ---------------------------------------------------------------------------
__device__ __forceinline__ void wino_inv(const float (&mm)[16],
                                         float& Y00, float& Y01,
                                         float& Y10, float& Y11)
{
    float s0[4], s1[4];
#pragma unroll
    for (int k = 0; k < 4; ++k) {
        s0[k] = mm[k] + mm[4 + k] + mm[8 + k];
        s1[k] = mm[4 + k] - mm[8 + k] - mm[12 + k];
    }
    Y00 = s0[0] + s0[1] + s0[2];
    Y01 = s0[1] - s0[2] - s0[3];
    Y10 = s1[0] + s1[1] + s1[2];
    Y11 = s1[1] - s1[2] - s1[3];
}

// ---------------------------------------------------------------------------
// qkv inverse transform; z<2: fused remap -> Q/K bf16 hi/lo; z=2: fp32 y2
// ---------------------------------------------------------------------------
__global__ void wino_out_y(const float* __restrict__ bq, const float* __restrict__ bk,
                           const float* __restrict__ bv)
{
    int blk = blockIdx.x;          // 12288 = 3z * 32n * 128cg
    int z = blk >> 12;
    int r = blk & 4095;
    int n = r >> 7, cg = r & 127;
    int tid = threadIdx.x;
    int cl = tid >> 6, ml = tid & 63;
    int co = cg * 4 + cl;
    int m = n * 64 + ml;
    const float* bias = (z == 0) ? bq : (z == 1) ? bk : bv;
    float mm[16];
#pragma unroll
    for (int p = 0; p < 16; ++p)
        mm[p] = g_M[((size_t)(z * 16 + p) * 512 + co) * 2048 + m];
    float Y00, Y01, Y10, Y11;
    wino_inv(mm, Y00, Y01, Y10, Y11);
    float b = bias[co];
    float Yr[2][2] = {{Y00 + b, Y01 + b}, {Y10 + b, Y11 + b}};
    int ty = ml >> 2, tx = ml & 3;
    if (z == 2) {
        float* dst = g_y2 + ((size_t)n * 512 + co) * 256 + 16 * ty + 2 * tx;
        *(float2*)&dst[0] = make_float2(Yr[0][0], Yr[0][1]);
        *(float2*)&dst[8] = make_float2(Yr[1][0], Yr[1][1]);
    } else {
        __nv_bfloat16* oh = z ? g_Kh : g_Qh;
        __nv_bfloat16* ol = z ? g_Kl : g_Ql;
        int hh = n >> 2;
        int nn = (n & 3) * 8 + (co >> 6);
#pragma unroll
        for (int rr = 0; rr < 2; ++rr) {
            int pp = 16 * ty + 2 * tx + 8 * rr;
            int d  = (co & 63) * 8 + (pp >> 5);
            int c  = hh * 32 + (pp & 31);
            size_t o = ((size_t)nn * 512 + d) * 256 + c;
            uint32_t hp, lp;
            split2(Yr[rr][0], Yr[rr][1], hp, lp);
            *(uint32_t*)&oh[o] = hp;
            *(uint32_t*)&ol[o] = lp;
        }
    }
}

__global__ void wino_out_o(const float* __restrict__ bo, float* __restrict__ out)
{
    int tx = threadIdx.x;
    int co = blockIdx.x & 511;
    int bt = blockIdx.x >> 9;
    int b = bt >> 2, ty = bt & 3;
    int m = b * 512 + ty * 128 + tx;
    float mm[16];
#pragma unroll
    for (int p = 0; p < 16; ++p)
        mm[p] = g_M[((size_t)p * 512 + co) * 2048 + m];
    float Y00, Y01, Y10, Y11;
    wino_inv(mm, Y00, Y01, Y10, Y11);
    float bb = bo[co];
    float* dst = out + ((size_t)b * 512 + co) * 2048 + (2 * ty) * 256 + 2 * tx;
    *(float2*)&dst[0]   = make_float2(Y00 + bb, Y01 + bb);
    *(float2*)&dst[256] = make_float2(Y10 + bb, Y11 + bb);
}

// ---------------------------------------------------------------------------
// V transpose remap: g_y2 -> Vt bf16 hi/lo [n][c][dk]
// ---------------------------------------------------------------------------
__global__ void remap_V()
{
    int e = blockIdx.x * 256 + threadIdx.x;
    int n = e >> 17, c = (e >> 9) & 255, dk = e & 511;
    int h = c >> 5, r = c & 31;
    float v = g_y2[(h * 4 + (n >> 3)) * 131072 + ((n & 7) * 64 + (dk >> 3)) * 256
                   + (dk & 7) * 32 + r];
    __nv_bfloat16 hh = __float2bfloat16(v);
    g_Vth[e] = hh;
    g_Vtl[e] = __float2bfloat16(v - __bfloat162float(hh));
}

// ---------------------------------------------------------------------------
// attention GEMMs (mbarrier pipeline)
// ---------------------------------------------------------------------------
__global__ __launch_bounds__(256, 2) void gemm_scores(float* __restrict__ attn)
{
    int nb = blockIdx.z;
    gemm_mb(g_Qh + (size_t)nb * 131072, g_Ql + (size_t)nb * 131072,
            g_Kh + (size_t)nb * 131072, g_Kl + (size_t)nb * 131072,
            256, 8, attn + (size_t)nb * 262144, 512);
}

__global__ __launch_bounds__(256, 2) void gemm_nnout()
{
    int nb = blockIdx.z;
    gemm_mb(g_ath + (size_t)nb * 262144, g_atl + (size_t)nb * 262144,
            g_Vth + (size_t)nb * 131072, g_Vtl + (size_t)nb * 131072,
            512, 16, g_On + (size_t)nb * 131072, 256);
}

// ---------------------------------------------------------------------------
// softmax over 512-wide rows, in place; also emit bf16 hi/lo
// ---------------------------------------------------------------------------
__global__ void softmax_rows(float* __restrict__ attn)
{
    size_t base = (size_t)blockIdx.x * 512;
    float* p = attn + base;
    int tid = threadIdx.x;
    float v0 = p[tid], v1 = p[tid + 256];
    float m = fmaxf(v0, v1);
#pragma unroll
    for (int o = 16; o; o >>= 1) m = fmaxf(m, __shfl_xor_sync(~0u, m, o));
    __shared__ float sm[8], ss[8];
    if ((tid & 31) == 0) sm[tid >> 5] = m;
    __syncthreads();
    if (tid < 8) {
        float mm = sm[tid];
#pragma unroll
        for (int o = 4; o; o >>= 1) mm = fmaxf(mm, __shfl_xor_sync(0xffu, mm, o));
        if (tid == 0) sm[0] = mm;
    }
    __syncthreads();
    float M = sm[0];
    float e0 = expf(v0 - M), e1 = expf(v1 - M);
    float s = e0 + e1;
#pragma unroll
    for (int o = 16; o; o >>= 1) s += __shfl_xor_sync(~0u, s, o);
    if ((tid & 31) == 0) ss[tid >> 5] = s;
    __syncthreads();
    if (tid < 8) {
        float t2 = ss[tid];
#pragma unroll
        for (int o = 4; o; o >>= 1) t2 += __shfl_xor_sync(0xffu, t2, o);
        if (tid == 0) ss[0] = t2;
    }
    __syncthreads();
    float inv = 1.f / ss[0];
    float a0 = e0 * inv, a1 = e1 * inv;
    p[tid] = a0;
    p[tid + 256] = a1;
    __nv_bfloat16 h0 = __float2bfloat16(a0), h1 = __float2bfloat16(a1);
    g_ath[base + tid]       = h0;
    g_atl[base + tid]       = __float2bfloat16(a0 - __bfloat162float(h0));
    g_ath[base + tid + 256] = h1;
    g_atl[base + tid + 256] = __float2bfloat16(a1 - __bfloat162float(h1));
}

// ---------------------------------------------------------------------------
// scatter O into conv_o input, fp32 pixel-major [b][pix][ci]
// ---------------------------------------------------------------------------
__global__ void remap_saf()
{
    int e = blockIdx.x * 256 + threadIdx.x;
    int b  = e >> 20;
    int p  = (e >> 9) & 2047;
    int d2 = e & 511;
    int s  = p >> 8;
    int rh = p & 255;
    int r2 = rh >> 3, h2 = rh & 7;
    int n  = b * 8 + s;
    int qd = r2 * 16 + h2 * 2 + (d2 >> 8);
    int rr = (d2 & 255) >> 3;
    int hh = d2 & 7;
    g_saf[e] = g_On[n * 131072 + qd * 256 + hh * 32 + rr];
}

// ---------------------------------------------------------------------------
extern "C" void kernel_launch(void* const* d_in, const int* in_sizes, int n_in,
                              void* d_out, int out_size)
{
    const float* q  = (const float*)d_in[0];
    const float* k  = (const float*)d_in[1];
    const float* v  = (const float*)d_in[2];
    const float* Wq = (const float*)d_in[3];
    const float* bq = (const float*)d_in[4];
    const float* Wk = (const float*)d_in[5];
    const float* bk = (const float*)d_in[6];
    const float* Wv = (const float*)d_in[7];
    const float* bv = (const float*)d_in[8];
    const float* Wo = (const float*)d_in[9];
    const float* bo = (const float*)d_in[10];

    float* y_out    = (float*)d_out;            // (4,512,8,32,8) = 4194304
    float* attn_out = y_out + NELEM;            // (1,32,512,512) = 8388608

    cudaFuncSetAttribute(gemm_wino,   cudaFuncAttributeMaxDynamicSharedMemorySize, SMEM_BYTES);
    cudaFuncSetAttribute(gemm_scores, cudaFuncAttributeMaxDynamicSharedMemorySize, SMEM_BYTES);
    cudaFuncSetAttribute(gemm_nnout,  cudaFuncAttributeMaxDynamicSharedMemorySize, SMEM_BYTES);

    // launch order: index 3 = gemm_wino (qkv), the dominant kernel (profiled)
    prep_wU<<<2048, 256>>>(Wq, Wk, Wv, Wo);                          // 0
    prep_xf<<<dim3(8, 16, 96), dim3(32, 8)>>>(q, k, v);              // 1
    wino_in_qkv<<<dim3(2048, 3), 256>>>();                           // 2
    gemm_wino<<<dim3(16, 4, 48), 256, SMEM_BYTES>>>(0);              // 3  <- profiled
    wino_out_y<<<12288, 256>>>(bq, bk, bv);                          // 4
    remap_V<<<NELEM / 256, 256>>>();                                 // 5
    gemm_scores<<<dim3(4, 4, 32), 256, SMEM_BYTES>>>(attn_out);      // 6
    softmax_rows<<<32 * 512, 256>>>(attn_out);                       // 7
    gemm_nnout<<<dim3(2, 4, 32), 256, SMEM_BYTES>>>();               // 8
    remap_saf<<<NELEM / 256, 256>>>();                               // 9
    wino_in_o<<<2048, 256>>>();                                      // 10
    gemm_wino<<<dim3(16, 4, 16), 256, SMEM_BYTES>>>(48);             // 11
    wino_out_o<<<8192, 128>>>(bo, y_out);                            // 12
}

// round 12
// speedup vs baseline: 3.2175x; 1.3869x over previous
#include <cuda_runtime.h>
#include <cuda_bf16.h>
#include <cstdint>

#define NELEM 4194304          // 32*512*256 == 4*512*2048
#define PSZ   262144           // 512*512 (one U/V/M plane)

// ---------------------------------------------------------------------------
// device scratch
// ---------------------------------------------------------------------------
__device__ float g_xf[3*NELEM];          // qkv inputs fp32 pixel-major [z][n][pix][ci]
__device__ float g_saf[NELEM];           // conv_o input fp32 pixel-major [b][pix][ci]
__device__ __nv_bfloat16 g_Uh[144*PSZ];  // wino weights [conv*36+pos][co][ci]
__device__ __nv_bfloat16 g_Ul[144*PSZ];
__device__ __nv_bfloat16 g_Vh[108*PSZ];  // wino inputs  [plane][tile][ci]
__device__ __nv_bfloat16 g_Vl[108*PSZ];
__device__ float g_M[108*PSZ];           // GEMM out     [plane][co][tile]
__device__ float g_y2[NELEM];            // conv(v) output (32,512,256) fp32
__device__ __nv_bfloat16 g_Qh[NELEM], g_Ql[NELEM];   // [n][d][c], c=h*32+r
__device__ __nv_bfloat16 g_Kh[NELEM], g_Kl[NELEM];
__device__ __nv_bfloat16 g_Vth[NELEM], g_Vtl[NELEM]; // transposed: [n][c][dk]
__device__ __nv_bfloat16 g_ath[2*NELEM], g_atl[2*NELEM]; // attn hi/lo
__device__ float g_On[NELEM];            // attn @ V  [n][qd][c]

// ---------------------------------------------------------------------------
// helpers
// ---------------------------------------------------------------------------
__device__ __forceinline__ uint32_t smem_u32(const void* p) {
    uint32_t a;
    asm("{ .reg .u64 t; cvta.to.shared.u64 t, %1; cvt.u32.u64 %0, t; }" : "=r"(a) : "l"(p));
    return a;
}
#define SWZ(o) ((o) ^ (((o) >> 3) & 0x70))
#define CPA(dst, src, sz) \
    asm volatile("cp.async.cg.shared.global [%0], [%1], 16, %2;" \
        :: "r"(dst), "l"(src), "r"(sz) : "memory")
#define LDM4(r, addr) \
    asm volatile("ldmatrix.sync.aligned.m8n8.x4.shared.b16 {%0,%1,%2,%3}, [%4];" \
        : "=r"((r)[0]), "=r"((r)[1]), "=r"((r)[2]), "=r"((r)[3]) : "r"(addr))
#define MMA_BF16(d, a, b0, b1) \
    asm volatile("mma.sync.aligned.m16n8k16.row.col.f32.bf16.bf16.f32 " \
        "{%0,%1,%2,%3}, {%4,%5,%6,%7}, {%8,%9}, {%0,%1,%2,%3};" \
        : "+f"((d)[0]), "+f"((d)[1]), "+f"((d)[2]), "+f"((d)[3]) \
        : "r"((a)[0]), "r"((a)[1]), "r"((a)[2]), "r"((a)[3]), "r"(b0), "r"(b1))
#define WAITP(addr, ph) do { \
    asm volatile("{\n\t.reg .pred P;\n\tWL%=:\n\t" \
        "mbarrier.try_wait.parity.acquire.cta.shared::cta.b64 P, [%0], %1, 0x989680;\n\t" \
        "@P bra.uni WD%=;\n\tbra.uni WL%=;\n\tWD%=:\n\t}" \
        :: "r"(addr), "r"(ph) : "memory"); \
} while (0)

#define STAGE 32768u
#define MBAR_BASE 98304u
#define SMEM_BYTES 98368
#define PROW(r) ((uint32_t)((((r) >> 1) << 7) | (((r) & 1) << 6)))

__device__ __forceinline__ void split2(float v0, float v1, uint32_t& hp, uint32_t& lp) {
    __nv_bfloat16 h0 = __float2bfloat16(v0);
    __nv_bfloat16 h1 = __float2bfloat16(v1);
    __nv_bfloat16 l0 = __float2bfloat16(v0 - __bfloat162float(h0));
    __nv_bfloat16 l1 = __float2bfloat16(v1 - __bfloat162float(h1));
    hp = (uint32_t)*(uint16_t*)&h0 | ((uint32_t)*(uint16_t*)&h1 << 16);
    lp = (uint32_t)*(uint16_t*)&l0 | ((uint32_t)*(uint16_t*)&l1 << 16);
}

// ---------------------------------------------------------------------------
// compute one K32 chunk, warp tile 64x32: D += Ah*Bh + Ah*Bl + Al*Bh
// ---------------------------------------------------------------------------
__device__ __forceinline__ void mma_compute32(uint32_t bs, uint32_t a_rowb,
                                              uint32_t b_rowb, float (&acc)[16][4])
{
#pragma unroll
    for (int s = 0; s < 2; ++s) {
        uint32_t ah[4][4], bb[2][4], blf[2][4];
#pragma unroll
        for (int i = 0; i < 4; ++i)
            LDM4(ah[i], bs + SWZ(a_rowb + i * 1024 + s * 32));
#pragma unroll
        for (int j = 0; j < 2; ++j)
            LDM4(bb[j], bs + 16384u + SWZ(b_rowb + j * 1024 + s * 32));
#pragma unroll
        for (int i = 0; i < 4; ++i)
#pragma unroll
            for (int jj = 0; jj < 4; ++jj)
                MMA_BF16(acc[i * 4 + jj], ah[i],
                         bb[jj >> 1][(jj & 1) * 2], bb[jj >> 1][(jj & 1) * 2 + 1]);
#pragma unroll
        for (int j = 0; j < 2; ++j)
            LDM4(blf[j], bs + 24576u + SWZ(b_rowb + j * 1024 + s * 32));
#pragma unroll
        for (int i = 0; i < 4; ++i)
#pragma unroll
            for (int jj = 0; jj < 4; ++jj)
                MMA_BF16(acc[i * 4 + jj], ah[i],
                         blf[jj >> 1][(jj & 1) * 2], blf[jj >> 1][(jj & 1) * 2 + 1]);
#pragma unroll
        for (int i = 0; i < 4; ++i)
            LDM4(ah[i], bs + 8192u + SWZ(a_rowb + i * 1024 + s * 32));
#pragma unroll
        for (int i = 0; i < 4; ++i)
#pragma unroll
            for (int jj = 0; jj < 4; ++jj)
                MMA_BF16(acc[i * 4 + jj], ah[i],
                         bb[jj >> 1][(jj & 1) * 2], bb[jj >> 1][(jj & 1) * 2 + 1]);
    }
}

// ---------------------------------------------------------------------------
// mbarrier-pipelined GEMM: C(MxN) = A(MxK) * B(NxK)^T, bf16 hi/lo 3-term.
// ---------------------------------------------------------------------------
__device__ __forceinline__ void gemm_mb(
    const __nv_bfloat16* __restrict__ Ah, const __nv_bfloat16* __restrict__ Al,
    const __nv_bfloat16* __restrict__ Bh, const __nv_bfloat16* __restrict__ Bl,
    int Kdim, int nchunk, float* __restrict__ C, int ldc)
{
    extern __shared__ char smem[];
    uint32_t sb = smem_u32(smem);
    int tid = threadIdx.x, wid = tid >> 5, lane = tid & 31;
    int m0 = blockIdx.y * 128, n0 = blockIdx.x * 128;
    int wm = wid & 1, wn = wid >> 1;

    int lr = tid >> 1, lh = tid & 1;
    uint32_t stb = PROW(lr) + lh * 32u;
    const char* srcA_h = (const char*)(Ah + (size_t)(m0 + lr) * Kdim + lh * 16);
    const char* srcA_l = (const char*)(Al + (size_t)(m0 + lr) * Kdim + lh * 16);
    const char* srcB_h = (const char*)(Bh + (size_t)(n0 + lr) * Kdim + lh * 16);
    const char* srcB_l = (const char*)(Bl + (size_t)(n0 + lr) * Kdim + lh * 16);

    int arow = wm * 64 + (lane & 15);
    uint32_t a_rowb = PROW(arow) + ((lane & 16) ? 16u : 0u);
    int brow = wn * 32 + (lane & 7) + ((lane & 16) ? 8 : 0);
    uint32_t b_rowb = PROW(brow) + ((lane & 8) ? 16u : 0u);

    if (tid == 0) {
#pragma unroll
        for (int s = 0; s < 3; ++s) {
            asm volatile("mbarrier.init.shared.b64 [%0], %1;"
                         :: "r"(sb + MBAR_BASE + s * 16u), "r"(256) : "memory");
            asm volatile("mbarrier.init.shared.b64 [%0], %1;"
                         :: "r"(sb + MBAR_BASE + s * 16u + 8u), "r"(256) : "memory");
        }
    }
    __syncthreads();

    float acc[16][4];
#pragma unroll
    for (int i = 0; i < 16; ++i)
#pragma unroll
        for (int j = 0; j < 4; ++j) acc[i][j] = 0.f;

    int ps = 0, pph = 1;
    int cs = 0, cph = 0;

    auto produce = [&](int itn) {
        uint32_t fmb = sb + MBAR_BASE + (uint32_t)ps * 16u;
        WAITP(fmb + 8u, pph);
        int cb = itn * 64;
        uint32_t bs = sb + (uint32_t)ps * STAGE;
        uint32_t s0 = SWZ(stb), s1 = SWZ(stb + 16u);
        CPA(bs + s0,          srcA_h + cb,      16u);
        CPA(bs + s1,          srcA_h + cb + 16, 16u);
        CPA(bs + 8192u + s0,  srcA_l + cb,      16u);
        CPA(bs + 8192u + s1,  srcA_l + cb + 16, 16u);
        CPA(bs + 16384u + s0, srcB_h + cb,      16u);
        CPA(bs + 16384u + s1, srcB_h + cb + 16, 16u);
        CPA(bs + 24576u + s0, srcB_l + cb,      16u);
        CPA(bs + 24576u + s1, srcB_l + cb + 16, 16u);
        asm volatile("cp.async.mbarrier.arrive.noinc.shared::cta.b64 [%0];"
                     :: "r"(fmb) : "memory");
        if (++ps == 3) { ps = 0; pph ^= 1; }
    };

    produce(0);
    produce(1);
    for (int it = 0; it < nchunk; ++it) {
        if (it + 2 < nchunk) produce(it + 2);
        uint32_t fmb = sb + MBAR_BASE + (uint32_t)cs * 16u;
        WAITP(fmb, cph);
        mma_compute32(sb + (uint32_t)cs * STAGE, a_rowb, b_rowb, acc);
        asm volatile("mbarrier.arrive.shared::cta.b64 _, [%0];"
                     :: "r"(fmb + 8u) : "memory");
        if (++cs == 3) { cs = 0; cph ^= 1; }
    }

#pragma unroll
    for (int i = 0; i < 4; ++i) {
        int row = m0 + wm * 64 + i * 16 + (lane >> 2);
#pragma unroll
        for (int jj = 0; jj < 4; ++jj) {
            int col = n0 + wn * 32 + jj * 8 + (lane & 3) * 2;
            float* d = acc[i * 4 + jj];
            *(float2*)&C[(size_t)row * ldc + col]       = make_float2(d[0], d[1]);
            *(float2*)&C[(size_t)(row + 8) * ldc + col] = make_float2(d[2], d[3]);
        }
    }
}

// ---------------------------------------------------------------------------
// F(4,3) weight transform: u = G w G^T (6x6), ci-pair, bf16 hi/lo
// ---------------------------------------------------------------------------
__global__ void prep_wU43(const float* __restrict__ Wq, const float* __restrict__ Wk,
                          const float* __restrict__ Wv, const float* __restrict__ Wo)
{
    int g = blockIdx.x * 256 + threadIdx.x;     // 4conv * 512co * 256cip
    int conv = g >> 17;
    int r = g & 131071;
    int co = r >> 8, ci = (r & 255) * 2;
    const float* W = (conv == 0) ? Wq : (conv == 1) ? Wk : (conv == 2) ? Wv : Wo;
    const float* w = W + (size_t)co * 4608 + ci * 9;
    const float c6 = 1.f / 6.f, c12 = 1.f / 12.f, c24 = 1.f / 24.f;
    float TA[6][3], TB[6][3];
#pragma unroll
    for (int k = 0; k < 3; ++k) {
        float a = w[k], b = w[3 + k], c = w[6 + k];
        TA[0][k] = 0.25f * a;
        TA[1][k] = -c6 * (a + b + c);
        TA[2][k] = -c6 * (a - b + c);
        TA[3][k] = c24 * a + c12 * b + c6 * c;
        TA[4][k] = c24 * a - c12 * b + c6 * c;
        TA[5][k] = c;
        float a1 = w[9 + k], b1 = w[12 + k], c1 = w[15 + k];
        TB[0][k] = 0.25f * a1;
        TB[1][k] = -c6 * (a1 + b1 + c1);
        TB[2][k] = -c6 * (a1 - b1 + c1);
        TB[3][k] = c24 * a1 + c12 * b1 + c6 * c1;
        TB[4][k] = c24 * a1 - c12 * b1 + c6 * c1;
        TB[5][k] = c1;
    }
#pragma unroll
    for (int i = 0; i < 6; ++i) {
        float a = TA[i][0], b = TA[i][1], c = TA[i][2];
        float uA[6] = {0.25f * a, -c6 * (a + b + c), -c6 * (a - b + c),
                       c24 * a + c12 * b + c6 * c, c24 * a - c12 * b + c6 * c, c};
        float a1 = TB[i][0], b1 = TB[i][1], c1 = TB[i][2];
        float uB[6] = {0.25f * a1, -c6 * (a1 + b1 + c1), -c6 * (a1 - b1 + c1),
                       c24 * a1 + c12 * b1 + c6 * c1, c24 * a1 - c12 * b1 + c6 * c1, c1};
#pragma unroll
        for (int j = 0; j < 6; ++j) {
            size_t o = ((size_t)(conv * 36 + i * 6 + j) * 512 + co) * 512 + ci;
            uint32_t hp, lp;
            split2(uA[j], uB[j], hp, lp);
            *(uint32_t*)&g_Uh[o] = hp;
            *(uint32_t*)&g_Ul[o] = lp;
        }
    }
}

// ---------------------------------------------------------------------------
// transpose q/k/v to fp32 pixel-major [z][n][pix][ci]
// ---------------------------------------------------------------------------
__global__ void prep_xf(const float* __restrict__ q, const float* __restrict__ k,
                        const float* __restrict__ v)
{
    __shared__ float tile[32][33];
    int zz = blockIdx.z;
    int z = zz >> 5, n = zz & 31;
    const float* src = (z == 0) ? q : (z == 1) ? k : v;
    const float* xin = src + (size_t)n * 131072;
    float* out = g_xf + (size_t)z * NELEM + (size_t)n * 131072;
    int p0 = blockIdx.x * 32, c0 = blockIdx.y * 32;
    int tx = threadIdx.x, ty = threadIdx.y;
#pragma unroll
    for (int j = 0; j < 4; ++j)
        tile[ty + 8 * j][tx] = xin[(size_t)(c0 + ty + 8 * j) * 256 + p0 + tx];
    __syncthreads();
#pragma unroll
    for (int j = 0; j < 4; ++j)
        out[(size_t)(p0 + ty + 8 * j) * 512 + c0 + tx] = tile[tx][ty + 8 * j];
}

// ---------------------------------------------------------------------------
// F(4,3) input transform: d = B^T X B (6x6), ci-pair, store V planes
// ---------------------------------------------------------------------------
__device__ __forceinline__ void wino43_in(const float* __restrict__ src,
                                          int H, int W, int y0, int x0,
                                          int vbase, int m, int ci)
{
    float2 T[6][6];
#pragma unroll
    for (int c = 0; c < 6; ++c) {
        int x = x0 + c;
        float2 X[6];
#pragma unroll
        for (int r = 0; r < 6; ++r) {
            int y = y0 + r;
            bool ok = ((unsigned)y < (unsigned)H) && ((unsigned)x < (unsigned)W);
            X[r] = ok ? *(const float2*)&src[(size_t)(y * W + x) * 512]
                      : make_float2(0.f, 0.f);
        }
        T[0][c] = make_float2(4.f*X[0].x - 5.f*X[2].x + X[4].x,
                              4.f*X[0].y - 5.f*X[2].y + X[4].y);
        T[1][c] = make_float2(-4.f*X[1].x - 4.f*X[2].x + X[3].x + X[4].x,
                              -4.f*X[1].y - 4.f*X[2].y + X[3].y + X[4].y);
        T[2][c] = make_float2( 4.f*X[1].x - 4.f*X[2].x - X[3].x + X[4].x,
                               4.f*X[1].y - 4.f*X[2].y - X[3].y + X[4].y);
        T[3][c] = make_float2(-2.f*X[1].x - X[2].x + 2.f*X[3].x + X[4].x,
                              -2.f*X[1].y - X[2].y + 2.f*X[3].y + X[4].y);
        T[4][c] = make_float2( 2.f*X[1].x - X[2].x - 2.f*X[3].x + X[4].x,
                               2.f*X[1].y - X[2].y - 2.f*X[3].y + X[4].y);
        T[5][c] = make_float2( 4.f*X[1].x - 5.f*X[3].x + X[5].x,
                               4.f*X[1].y - 5.f*X[3].y + X[5].y);
    }
#pragma unroll
    for (int i = 0; i < 6; ++i) {
        float2 t0 = T[i][0], t1 = T[i][1], t2 = T[i][2];
        float2 t3 = T[i][3], t4 = T[i][4], t5 = T[i][5];
        float2 d[6];
        d[0] = make_float2(4.f*t0.x - 5.f*t2.x + t4.x, 4.f*t0.y - 5.f*t2.y + t4.y);
        d[1] = make_float2(-4.f*t1.x - 4.f*t2.x + t3.x + t4.x,
                           -4.f*t1.y - 4.f*t2.y + t3.y + t4.y);
        d[2] = make_float2( 4.f*t1.x - 4.f*t2.x - t3.x + t4.x,
                            4.f*t1.y - 4.f*t2.y - t3.y + t4.y);
        d[3] = make_float2(-2.f*t1.x - t2.x + 2.f*t3.x + t4.x,
                           -2.f*t1.y - t2.y + 2.f*t3.y + t4.y);
        d[4] = make_float2( 2.f*t1.x - t2.x - 2.f*t3.x + t4.x,
                            2.f*t1.y - t2.y - 2.f*t3.y + t4.y);
        d[5] = make_float2( 4.f*t1.x - 5.f*t3.x + t5.x,
                            4.f*t1.y - 5.f*t3.y + t5.y);
#pragma unroll
        for (int j = 0; j < 6; ++j) {
            size_t o = ((size_t)(vbase + i * 6 + j) * 512 + m) * 512 + ci;
            uint32_t hp, lp;
            split2(d[j].x, d[j].y, hp, lp);
            *(uint32_t*)&g_Vh[o] = hp;
            *(uint32_t*)&g_Vl[o] = lp;
        }
    }
}

// qkv: H=32, W=8; tiles 8x2 per image, 32 images -> 512 tiles per conv
__global__ void wino_in_qkv43()
{
    int e = blockIdx.x * 256 + threadIdx.x;     // 3 * 512 * 256
    int z = e >> 17;
    int r = e & 131071;
    int m = r >> 8, ci = (r & 255) * 2;
    int img = m >> 4, mr = m & 15;
    int ty = mr >> 1, tx = mr & 1;
    const float* src = g_xf + (size_t)z * NELEM + (size_t)img * 131072 + ci;
    wino43_in(src, 32, 8, 4 * ty - 1, 4 * tx - 1, z * 36, m, ci);
}

// conv_o: H=8, W=256; tiles 2x64 per image, 4 images -> 512 tiles
__global__ void wino_in_o43()
{
    int e = blockIdx.x * 256 + threadIdx.x;     // 512 * 256
    int m = e >> 8, ci = (e & 255) * 2;
    int img = m >> 7, mr = m & 127;
    int ty = mr >> 6, tx = mr & 63;
    const float* src = g_saf + (size_t)img * 1048576 + ci;
    wino43_in(src, 8, 256, 4 * ty - 1, 4 * tx - 1, 0, m, ci);
}

// ---------------------------------------------------------------------------
// Winograd GEMM: per plane, C[co][tile] = U[co][ci] . V[tile][ci]^T
// ---------------------------------------------------------------------------
__global__ __launch_bounds__(256, 2) void gemm_wino(int ubase)
{
    int zp = blockIdx.z;
    gemm_mb(g_Uh + (size_t)(ubase + zp) * PSZ, g_Ul + (size_t)(ubase + zp) * PSZ,
            g_Vh + (size_t)zp * PSZ, g_Vl + (size_t)zp * PSZ,
            512, 16, g_M + (size_t)zp * PSZ, 512);
}

// ---------------------------------------------------------------------------
// F(4,3) inverse: Y = A^T M A (4x4 from 6x6)
// ---------------------------------------------------------------------------
__device__ __forceinline__ void wino43_inv(const float (&M)[36], float (&Y)[4][4])
{
    float S[4][6];
#pragma unroll
    for (int c = 0; c < 6; ++c) {
        float m0 = M[c], m1 = M[6 + c], m2 = M[12 + c];
        float m3 = M[18 + c], m4 = M[24 + c], m5 = M[30 + c];
        S[0][c] = m0 + m1 + m2 + m3 + m4;
        S[1][c] = m1 - m2 + 2.f * m3 - 2.f * m4;
        S[2][c] = m1 + m2 + 4.f * m3 + 4.f * m4;
        S[3][c] = m1 - m2 + 8.f * m3 - 8.f * m4 + m5;
    }
#pragma unroll
    for (int i = 0; i < 4; ++i) {
        float s0 = S[i][0], s1 = S[i][1], s2 = S[i][2];
        float s3 = S[i][3], s4 = S[i][4], s5 = S[i][5];
        Y[i][0] = s0 + s1 + s2 + s3 + s4;
        Y[i][1] = s1 - s2 + 2.f * s3 - 2.f * s4;
        Y[i][2] = s1 + s2 + 4.f * s3 + 4.f * s4;
        Y[i][3] = s1 - s2 + 8.f * s3 - 8.f * s4 + s5;
    }
}

// qkv inverse; z<2: fused remap -> Q/K bf16 hi/lo; z=2: fp32 y2
__global__ void wino_out_y43(const float* __restrict__ bq, const float* __restrict__ bk,
                             const float* __restrict__ bv)
{
    int blk = blockIdx.x;          // 3072 = 3z * 512co * 2
    int z = blk >> 10;
    int r = blk & 1023;
    int co = r >> 1;
    int m = (r & 1) * 256 + threadIdx.x;
    const float* bias = (z == 0) ? bq : (z == 1) ? bk : bv;
    float M[36];
#pragma unroll
    for (int p = 0; p < 36; ++p)
        M[p] = g_M[(size_t)(z * 36 + p) * PSZ + co * 512 + m];
    float Y[4][4];
    wino43_inv(M, Y);
    float b = bias[co];
    int img = m >> 4, mr = m & 15;
    int ty = mr >> 1, tx = mr & 1;
    if (z == 2) {
        float* dst = g_y2 + ((size_t)img * 512 + co) * 256 + 32 * ty + 4 * tx;
#pragma unroll
        for (int i = 0; i < 4; ++i)
            *(float4*)&dst[8 * i] = make_float4(Y[i][0] + b, Y[i][1] + b,
                                                Y[i][2] + b, Y[i][3] + b);
    } else {
        __nv_bfloat16* oh = z ? g_Kh : g_Qh;
        __nv_bfloat16* ol = z ? g_Kl : g_Ql;
        int hh = img >> 2;
        int nn = (img & 3) * 8 + (co >> 6);
        int d  = (co & 63) * 8 + ty;
        size_t rowo = ((size_t)nn * 512 + d) * 256;
#pragma unroll
        for (int i = 0; i < 4; ++i) {
            int cbase = hh * 32 + 8 * i + 4 * tx;
            uint32_t h0, l0, h1, l1;
            split2(Y[i][0] + b, Y[i][1] + b, h0, l0);
            split2(Y[i][2] + b, Y[i][3] + b, h1, l1);
            *(uint2*)&oh[rowo + cbase] = make_uint2(h0, h1);
            *(uint2*)&ol[rowo + cbase] = make_uint2(l0, l1);
        }
    }
}

__global__ void wino_out_o43(const float* __restrict__ bo, float* __restrict__ out)
{
    int blk = blockIdx.x;          // 1024 = 512co * 2
    int co = blk >> 1;
    int m = (blk & 1) * 256 + threadIdx.x;
    float M[36];
#pragma unroll
    for (int p = 0; p < 36; ++p)
        M[p] = g_M[(size_t)p * PSZ + co * 512 + m];
    float Y[4][4];
    wino43_inv(M, Y);
    float b = bo[co];
    int img = m >> 7, mr = m & 127;
    int ty = mr >> 6, tx = mr & 63;
    float* dst = out + ((size_t)img * 512 + co) * 2048 + (4 * ty) * 256 + 4 * tx;
#pragma unroll
    for (int i = 0; i < 4; ++i)
        *(float4*)&dst[256 * i] = make_float4(Y[i][0] + b, Y[i][1] + b,
                                              Y[i][2] + b, Y[i][3] + b);
}

// ---------------------------------------------------------------------------
// V transpose remap: g_y2 -> Vt bf16 hi/lo [n][c][dk]
// ---------------------------------------------------------------------------
__global__ void remap_V()
{
    int e = blockIdx.x * 256 + threadIdx.x;
    int n = e >> 17, c = (e >> 9) & 255, dk = e & 511;
    int h = c >> 5, r = c & 31;
    float v = g_y2[(h * 4 + (n >> 3)) * 131072 + ((n & 7) * 64 + (dk >> 3)) * 256
                   + (dk & 7) * 32 + r];
    __nv_bfloat16 hh = __float2bfloat16(v);
    g_Vth[e] = hh;
    g_Vtl[e] = __float2bfloat16(v - __bfloat162float(hh));
}

// ---------------------------------------------------------------------------
// attention GEMMs (mbarrier pipeline)
// ---------------------------------------------------------------------------
__global__ __launch_bounds__(256, 2) void gemm_scores(float* __restrict__ attn)
{
    int nb = blockIdx.z;
    gemm_mb(g_Qh + (size_t)nb * 131072, g_Ql + (size_t)nb * 131072,
            g_Kh + (size_t)nb * 131072, g_Kl + (size_t)nb * 131072,
            256, 8, attn + (size_t)nb * 262144, 512);
}

__global__ __launch_bounds__(256, 2) void gemm_nnout()
{
    int nb = blockIdx.z;
    gemm_mb(g_ath + (size_t)nb * 262144, g_atl + (size_t)nb * 262144,
            g_Vth + (size_t)nb * 131072, g_Vtl + (size_t)nb * 131072,
            512, 16, g_On + (size_t)nb * 131072, 256);
}

// ---------------------------------------------------------------------------
// softmax over 512-wide rows, in place; also emit bf16 hi/lo
// ---------------------------------------------------------------------------
__global__ void softmax_rows(float* __restrict__ attn)
{
    size_t base = (size_t)blockIdx.x * 512;
    float* p = attn + base;
    int tid = threadIdx.x;
    float v0 = p[tid], v1 = p[tid + 256];
    float m = fmaxf(v0, v1);
#pragma unroll
    for (int o = 16; o; o >>= 1) m = fmaxf(m, __shfl_xor_sync(~0u, m, o));
    __shared__ float sm[8], ss[8];
    if ((tid & 31) == 0) sm[tid >> 5] = m;
    __syncthreads();
    if (tid < 8) {
        float mm = sm[tid];
#pragma unroll
        for (int o = 4; o; o >>= 1) mm = fmaxf(mm, __shfl_xor_sync(0xffu, mm, o));
        if (tid == 0) sm[0] = mm;
    }
    __syncthreads();
    float M = sm[0];
    float e0 = expf(v0 - M), e1 = expf(v1 - M);
    float s = e0 + e1;
#pragma unroll
    for (int o = 16; o; o >>= 1) s += __shfl_xor_sync(~0u, s, o);
    if ((tid & 31) == 0) ss[tid >> 5] = s;
    __syncthreads();
    if (tid < 8) {
        float t2 = ss[tid];
#pragma unroll
        for (int o = 4; o; o >>= 1) t2 += __shfl_xor_sync(0xffu, t2, o);
        if (tid == 0) ss[0] = t2;
    }
    __syncthreads();
    float inv = 1.f / ss[0];
    float a0 = e0 * inv, a1 = e1 * inv;
    p[tid] = a0;
    p[tid + 256] = a1;
    __nv_bfloat16 h0 = __float2bfloat16(a0), h1 = __float2bfloat16(a1);
    g_ath[base + tid]       = h0;
    g_atl[base + tid]       = __float2bfloat16(a0 - __bfloat162float(h0));
    g_ath[base + tid + 256] = h1;
    g_atl[base + tid + 256] = __float2bfloat16(a1 - __bfloat162float(h1));
}

// ---------------------------------------------------------------------------
// scatter O into conv_o input, fp32 pixel-major [b][pix][ci]
// ---------------------------------------------------------------------------
__global__ void remap_saf()
{
    int e = blockIdx.x * 256 + threadIdx.x;
    int b  = e >> 20;
    int p  = (e >> 9) & 2047;
    int d2 = e & 511;
    int s  = p >> 8;
    int rh = p & 255;
    int r2 = rh >> 3, h2 = rh & 7;
    int n  = b * 8 + s;
    int qd = r2 * 16 + h2 * 2 + (d2 >> 8);
    int rr = (d2 & 255) >> 3;
    int hh = d2 & 7;
    g_saf[e] = g_On[n * 131072 + qd * 256 + hh * 32 + rr];
}

// ---------------------------------------------------------------------------
extern "C" void kernel_launch(void* const* d_in, const int* in_sizes, int n_in,
                              void* d_out, int out_size)
{
    const float* q  = (const float*)d_in[0];
    const float* k  = (const float*)d_in[1];
    const float* v  = (const float*)d_in[2];
    const float* Wq = (const float*)d_in[3];
    const float* bq = (const float*)d_in[4];
    const float* Wk = (const float*)d_in[5];
    const float* bk = (const float*)d_in[6];
    const float* Wv = (const float*)d_in[7];
    const float* bv = (const float*)d_in[8];
    const float* Wo = (const float*)d_in[9];
    const float* bo = (const float*)d_in[10];

    float* y_out    = (float*)d_out;            // (4,512,8,32,8) = 4194304
    float* attn_out = y_out + NELEM;            // (1,32,512,512) = 8388608

    cudaFuncSetAttribute(gemm_wino,   cudaFuncAttributeMaxDynamicSharedMemorySize, SMEM_BYTES);
    cudaFuncSetAttribute(gemm_scores, cudaFuncAttributeMaxDynamicSharedMemorySize, SMEM_BYTES);
    cudaFuncSetAttribute(gemm_nnout,  cudaFuncAttributeMaxDynamicSharedMemorySize, SMEM_BYTES);

    // launch order: index 3 = gemm_wino (qkv), dominant kernel (profiled)
    prep_wU43<<<2048, 256>>>(Wq, Wk, Wv, Wo);                        // 0
    prep_xf<<<dim3(8, 16, 96), dim3(32, 8)>>>(q, k, v);              // 1
    wino_in_qkv43<<<1536, 256>>>();                                  // 2
    gemm_wino<<<dim3(4, 4, 108), 256, SMEM_BYTES>>>(0);              // 3  <- profiled
    wino_out_y43<<<3072, 256>>>(bq, bk, bv);                         // 4
    remap_V<<<NELEM / 256, 256>>>();                                 // 5
    gemm_scores<<<dim3(4, 4, 32), 256, SMEM_BYTES>>>(attn_out);      // 6
    softmax_rows<<<32 * 512, 256>>>(attn_out);                       // 7
    gemm_nnout<<<dim3(2, 4, 32), 256, SMEM_BYTES>>>();               // 8
    remap_saf<<<NELEM / 256, 256>>>();                               // 9
    wino_in_o43<<<512, 256>>>();                                     // 10
    gemm_wino<<<dim3(4, 4, 36), 256, SMEM_BYTES>>>(108);             // 11
    wino_out_o43<<<1024, 256>>>(bo, y_out);                          // 12
}

// round 13
// speedup vs baseline: 3.2432x; 1.0080x over previous
#include <cuda_runtime.h>
#include <cuda_bf16.h>
#include <cstdint>

#define NELEM 4194304          // 32*512*256 == 4*512*2048
#define PSZ   262144           // 512*512 (one U/V/M plane)

// ---------------------------------------------------------------------------
// device scratch
// ---------------------------------------------------------------------------
__device__ float g_saf[NELEM];           // conv_o input fp32 pixel-major [b][pix][ci]
__device__ __nv_bfloat16 g_Uh[144*PSZ];  // wino weights [conv*36+pos][co][ci]
__device__ __nv_bfloat16 g_Ul[144*PSZ];
__device__ __nv_bfloat16 g_Vh[108*PSZ];  // wino inputs  [plane][tile][ci]
__device__ __nv_bfloat16 g_Vl[108*PSZ];
__device__ float g_M[108*PSZ];           // GEMM out     [plane][co][tile]
__device__ float g_y2[NELEM];            // conv(v) output (32,512,256) fp32
__device__ __nv_bfloat16 g_Qh[NELEM], g_Ql[NELEM];   // [n][d][c], c=h*32+r
__device__ __nv_bfloat16 g_Kh[NELEM], g_Kl[NELEM];
__device__ __nv_bfloat16 g_Vth[NELEM], g_Vtl[NELEM]; // transposed: [n][c][dk]
__device__ __nv_bfloat16 g_ath[2*NELEM], g_atl[2*NELEM]; // attn hi/lo
__device__ float g_On[NELEM];            // attn @ V  [n][qd][c]

// ---------------------------------------------------------------------------
// helpers
// ---------------------------------------------------------------------------
__device__ __forceinline__ uint32_t smem_u32(const void* p) {
    uint32_t a;
    asm("{ .reg .u64 t; cvta.to.shared.u64 t, %1; cvt.u32.u64 %0, t; }" : "=r"(a) : "l"(p));
    return a;
}
#define SWZ(o) ((o) ^ (((o) >> 3) & 0x70))
#define CPA(dst, src, sz) \
    asm volatile("cp.async.cg.shared.global [%0], [%1], 16, %2;" \
        :: "r"(dst), "l"(src), "r"(sz) : "memory")
#define LDM4(r, addr) \
    asm volatile("ldmatrix.sync.aligned.m8n8.x4.shared.b16 {%0,%1,%2,%3}, [%4];" \
        : "=r"((r)[0]), "=r"((r)[1]), "=r"((r)[2]), "=r"((r)[3]) : "r"(addr))
#define MMA_BF16(d, a, b0, b1) \
    asm volatile("mma.sync.aligned.m16n8k16.row.col.f32.bf16.bf16.f32 " \
        "{%0,%1,%2,%3}, {%4,%5,%6,%7}, {%8,%9}, {%0,%1,%2,%3};" \
        : "+f"((d)[0]), "+f"((d)[1]), "+f"((d)[2]), "+f"((d)[3]) \
        : "r"((a)[0]), "r"((a)[1]), "r"((a)[2]), "r"((a)[3]), "r"(b0), "r"(b1))
#define WAITP(addr, ph) do { \
    asm volatile("{\n\t.reg .pred P;\n\tWL%=:\n\t" \
        "mbarrier.try_wait.parity.acquire.cta.shared::cta.b64 P, [%0], %1, 0x989680;\n\t" \
        "@P bra.uni WD%=;\n\tbra.uni WL%=;\n\tWD%=:\n\t}" \
        :: "r"(addr), "r"(ph) : "memory"); \
} while (0)

#define STAGE 32768u
#define MBAR_BASE 98304u
#define SMEM_BYTES 98368
#define PROW(r) ((uint32_t)((((r) >> 1) << 7) | (((r) & 1) << 6)))

__device__ __forceinline__ void split2(float v0, float v1, uint32_t& hp, uint32_t& lp) {
    __nv_bfloat16 h0 = __float2bfloat16(v0);
    __nv_bfloat16 h1 = __float2bfloat16(v1);
    __nv_bfloat16 l0 = __float2bfloat16(v0 - __bfloat162float(h0));
    __nv_bfloat16 l1 = __float2bfloat16(v1 - __bfloat162float(h1));
    hp = (uint32_t)*(uint16_t*)&h0 | ((uint32_t)*(uint16_t*)&h1 << 16);
    lp = (uint32_t)*(uint16_t*)&l0 | ((uint32_t)*(uint16_t*)&l1 << 16);
}

// ---------------------------------------------------------------------------
// compute one K32 chunk, warp tile 64x32: D += Ah*Bh + Ah*Bl + Al*Bh
// ---------------------------------------------------------------------------
__device__ __forceinline__ void mma_compute32(uint32_t bs, uint32_t a_rowb,
                                              uint32_t b_rowb, float (&acc)[16][4])
{
#pragma unroll
    for (int s = 0; s < 2; ++s) {
        uint32_t ah[4][4], bb[2][4], blf[2][4];
#pragma unroll
        for (int i = 0; i < 4; ++i)
            LDM4(ah[i], bs + SWZ(a_rowb + i * 1024 + s * 32));
#pragma unroll
        for (int j = 0; j < 2; ++j)
            LDM4(bb[j], bs + 16384u + SWZ(b_rowb + j * 1024 + s * 32));
#pragma unroll
        for (int i = 0; i < 4; ++i)
#pragma unroll
            for (int jj = 0; jj < 4; ++jj)
                MMA_BF16(acc[i * 4 + jj], ah[i],
                         bb[jj >> 1][(jj & 1) * 2], bb[jj >> 1][(jj & 1) * 2 + 1]);
#pragma unroll
        for (int j = 0; j < 2; ++j)
            LDM4(blf[j], bs + 24576u + SWZ(b_rowb + j * 1024 + s * 32));
#pragma unroll
        for (int i = 0; i < 4; ++i)
#pragma unroll
            for (int jj = 0; jj < 4; ++jj)
                MMA_BF16(acc[i * 4 + jj], ah[i],
                         blf[jj >> 1][(jj & 1) * 2], blf[jj >> 1][(jj & 1) * 2 + 1]);
#pragma unroll
        for (int i = 0; i < 4; ++i)
            LDM4(ah[i], bs + 8192u + SWZ(a_rowb + i * 1024 + s * 32));
#pragma unroll
        for (int i = 0; i < 4; ++i)
#pragma unroll
            for (int jj = 0; jj < 4; ++jj)
                MMA_BF16(acc[i * 4 + jj], ah[i],
                         bb[jj >> 1][(jj & 1) * 2], bb[jj >> 1][(jj & 1) * 2 + 1]);
    }
}

// ---------------------------------------------------------------------------
// tile decode for persistent GEMM
// mode 0: winograd planes (ubase = U plane offset), 4x4 tiles/plane
// mode 1: attention scores (Q.K^T), 4x4 tiles/batch
// mode 2: attention output (attn.Vt^T), 4x2 tiles/batch
// ---------------------------------------------------------------------------
__device__ __forceinline__ void decode_tile(
    int mode, int ubase, int tile, float* attn,
    const __nv_bfloat16*& ah, const __nv_bfloat16*& al,
    const __nv_bfloat16*& bh, const __nv_bfloat16*& bl,
    float*& c, int& ldc)
{
    if (mode == 0) {
        int plane = tile >> 4, sub = tile & 15;
        int m0 = (sub >> 2) << 7, n0 = (sub & 3) << 7;
        size_t up = (size_t)(ubase + plane) * PSZ + (size_t)m0 * 512;
        size_t vp = (size_t)plane * PSZ + (size_t)n0 * 512;
        ah = g_Uh + up;  al = g_Ul + up;
        bh = g_Vh + vp;  bl = g_Vl + vp;
        c = g_M + (size_t)plane * PSZ + (size_t)m0 * 512 + n0;
        ldc = 512;
    } else if (mode == 1) {
        int nb = tile >> 4, sub = tile & 15;
        int m0 = (sub >> 2) << 7, n0 = (sub & 3) << 7;
        size_t ap = (size_t)nb * 131072 + (size_t)m0 * 256;
        size_t bp = (size_t)nb * 131072 + (size_t)n0 * 256;
        ah = g_Qh + ap;  al = g_Ql + ap;
        bh = g_Kh + bp;  bl = g_Kl + bp;
        c = attn + (size_t)nb * 262144 + (size_t)m0 * 512 + n0;
        ldc = 512;
    } else {
        int nb = tile >> 3, sub = tile & 7;
        int m0 = (sub >> 1) << 7, n0 = (sub & 1) << 7;
        size_t ap = (size_t)nb * 262144 + (size_t)m0 * 512;
        size_t bp = (size_t)nb * 131072 + (size_t)n0 * 512;
        ah = g_ath + ap;  al = g_atl + ap;
        bh = g_Vth + bp;  bl = g_Vtl + bp;
        c = g_On + (size_t)nb * 131072 + (size_t)m0 * 256 + n0;
        ldc = 256;
    }
}

// ---------------------------------------------------------------------------
// persistent mbarrier-pipelined GEMM: each CTA streams chunks across its
// tiles continuously; epilogue of tile i overlaps prefetch of tile i+1.
// ---------------------------------------------------------------------------
__global__ __launch_bounds__(256, 2) void gemm_persist(
    int mode, int ubase, int ntiles, int kdim, int lognch, float* attn)
{
    extern __shared__ char smem[];
    uint32_t sb = smem_u32(smem);
    int tid = threadIdx.x, wid = tid >> 5, lane = tid & 31;
    int wm = wid & 1, wn = wid >> 1;
    int nchunk = 1 << lognch;

    int lr = tid >> 1, lh = tid & 1;
    uint32_t stb = PROW(lr) + lh * 32u;
    int arowoff = (lr * kdim + lh * 16) * 2;          // bytes into A/B rows

    int arow = wm * 64 + (lane & 15);
    uint32_t a_rowb = PROW(arow) + ((lane & 16) ? 16u : 0u);
    int brow = wn * 32 + (lane & 7) + ((lane & 16) ? 8 : 0);
    uint32_t b_rowb = PROW(brow) + ((lane & 8) ? 16u : 0u);

    if (tid == 0) {
#pragma unroll
        for (int s = 0; s < 3; ++s) {
            asm volatile("mbarrier.init.shared.b64 [%0], %1;"
                         :: "r"(sb + MBAR_BASE + s * 16u), "r"(256) : "memory");
            asm volatile("mbarrier.init.shared.b64 [%0], %1;"
                         :: "r"(sb + MBAR_BASE + s * 16u + 8u), "r"(256) : "memory");
        }
    }
    __syncthreads();

    int bid = blockIdx.x, grid = gridDim.x;
    int my_ntiles = (ntiles - bid + grid - 1) / grid;
    int total = my_ntiles << lognch;

    int ps = 0, pph = 1;
    int cs = 0, cph = 0;

    auto produce = [&](int gi) {
        uint32_t fmb = sb + MBAR_BASE + (uint32_t)ps * 16u;
        WAITP(fmb + 8u, pph);
        int mt = gi >> lognch, ch = gi & (nchunk - 1);
        int tile = bid + mt * grid;
        const __nv_bfloat16 *ah, *al, *bh, *bl;
        float* c; int ldc;
        decode_tile(mode, ubase, tile, attn, ah, al, bh, bl, c, ldc);
        int off = arowoff + ch * 64;
        const char* pAh = (const char*)ah + off;
        const char* pAl = (const char*)al + off;
        const char* pBh = (const char*)bh + off;
        const char* pBl = (const char*)bl + off;
        uint32_t bs = sb + (uint32_t)ps * STAGE;
        uint32_t s0 = SWZ(stb), s1 = SWZ(stb + 16u);
        CPA(bs + s0,          pAh,      16u);
        CPA(bs + s1,          pAh + 16, 16u);
        CPA(bs + 8192u + s0,  pAl,      16u);
        CPA(bs + 8192u + s1,  pAl + 16, 16u);
        CPA(bs + 16384u + s0, pBh,      16u);
        CPA(bs + 16384u + s1, pBh + 16, 16u);
        CPA(bs + 24576u + s0, pBl,      16u);
        CPA(bs + 24576u + s1, pBl + 16, 16u);
        asm volatile("cp.async.mbarrier.arrive.noinc.shared::cta.b64 [%0];"
                     :: "r"(fmb) : "memory");
        if (++ps == 3) { ps = 0; pph ^= 1; }
    };

    produce(0);
    if (total > 1) produce(1);

    int gi = 0;
    for (int mt = 0; mt < my_ntiles; ++mt) {
        int tile = bid + mt * grid;
        float acc[16][4];
#pragma unroll
        for (int i = 0; i < 16; ++i)
#pragma unroll
            for (int j = 0; j < 4; ++j) acc[i][j] = 0.f;

        for (int ch = 0; ch < nchunk; ++ch, ++gi) {
            if (gi + 2 < total) produce(gi + 2);
            uint32_t fmb = sb + MBAR_BASE + (uint32_t)cs * 16u;
            WAITP(fmb, cph);
            mma_compute32(sb + (uint32_t)cs * STAGE, a_rowb, b_rowb, acc);
            asm volatile("mbarrier.arrive.shared::cta.b64 _, [%0];"
                         :: "r"(fmb + 8u) : "memory");
            if (++cs == 3) { cs = 0; cph ^= 1; }
        }
        // epilogue (overlaps next tile's in-flight prefetches)
        const __nv_bfloat16 *ah, *al, *bh, *bl;
        float* c; int ldc;
        decode_tile(mode, ubase, tile, attn, ah, al, bh, bl, c, ldc);
#pragma unroll
        for (int i = 0; i < 4; ++i) {
            int row = wm * 64 + i * 16 + (lane >> 2);
#pragma unroll
            for (int jj = 0; jj < 4; ++jj) {
                int col = wn * 32 + jj * 8 + (lane & 3) * 2;
                float* d = acc[i * 4 + jj];
                *(float2*)&c[(size_t)row * ldc + col]       = make_float2(d[0], d[1]);
                *(float2*)&c[(size_t)(row + 8) * ldc + col] = make_float2(d[2], d[3]);
            }
        }
    }
}

// ---------------------------------------------------------------------------
// F(4,3) weight transform: u = G w G^T (6x6), ci-pair, bf16 hi/lo
// ---------------------------------------------------------------------------
__global__ void prep_wU43(const float* __restrict__ Wa, const float* __restrict__ Wb,
                          int cbase)
{
    int g = blockIdx.x * 256 + threadIdx.x;     // 2conv * 512co * 256cip
    int conv = g >> 17;
    int r = g & 131071;
    int co = r >> 8, ci = (r & 255) * 2;
    const float* W = conv ? Wb : Wa;
    const float* w = W + (size_t)co * 4608 + ci * 9;
    const float c6 = 1.f / 6.f, c12 = 1.f / 12.f, c24 = 1.f / 24.f;
    float TA[6][3], TB[6][3];
#pragma unroll
    for (int k = 0; k < 3; ++k) {
        float a = w[k], b = w[3 + k], c = w[6 + k];
        TA[0][k] = 0.25f * a;
        TA[1][k] = -c6 * (a + b + c);
        TA[2][k] = -c6 * (a - b + c);
        TA[3][k] = c24 * a + c12 * b + c6 * c;
        TA[4][k] = c24 * a - c12 * b + c6 * c;
        TA[5][k] = c;
        float a1 = w[9 + k], b1 = w[12 + k], c1 = w[15 + k];
        TB[0][k] = 0.25f * a1;
        TB[1][k] = -c6 * (a1 + b1 + c1);
        TB[2][k] = -c6 * (a1 - b1 + c1);
        TB[3][k] = c24 * a1 + c12 * b1 + c6 * c1;
        TB[4][k] = c24 * a1 - c12 * b1 + c6 * c1;
        TB[5][k] = c1;
    }
#pragma unroll
    for (int i = 0; i < 6; ++i) {
        float a = TA[i][0], b = TA[i][1], c = TA[i][2];
        float uA[6] = {0.25f * a, -c6 * (a + b + c), -c6 * (a - b + c),
                       c24 * a + c12 * b + c6 * c, c24 * a - c12 * b + c6 * c, c};
        float a1 = TB[i][0], b1 = TB[i][1], c1 = TB[i][2];
        float uB[6] = {0.25f * a1, -c6 * (a1 + b1 + c1), -c6 * (a1 - b1 + c1),
                       c24 * a1 + c12 * b1 + c6 * c1, c24 * a1 - c12 * b1 + c6 * c1, c1};
#pragma unroll
        for (int j = 0; j < 6; ++j) {
            size_t o = ((size_t)((cbase + conv) * 36 + i * 6 + j) * 512 + co) * 512 + ci;
            uint32_t hp, lp;
            split2(uA[j], uB[j], hp, lp);
            *(uint32_t*)&g_Uh[o] = hp;
            *(uint32_t*)&g_Ul[o] = lp;
        }
    }
}

// ---------------------------------------------------------------------------
// fused transpose + F(4,3) input transform for q/k/v.
// CTA: (cig, img, z). Loads 64ci x 256pix slab coalesced into smem (stride 65),
// transforms, writes V planes bf16 hi/lo.
// ---------------------------------------------------------------------------
#define XF_SMEM (256 * 65 * 4)
__global__ void wino_in_qkv_f(const float* __restrict__ q, const float* __restrict__ k,
                              const float* __restrict__ v)
{
    extern __shared__ float sx[];     // [pix][ci] stride 65
    int cig = blockIdx.x;             // 0..7  (ci group of 64)
    int img = blockIdx.y;             // 0..31
    int z   = blockIdx.z;             // 0..2
    int tid = threadIdx.x;
    const float* base = (z == 0) ? q : (z == 1) ? k : v;
    const float* src = base + (size_t)img * 131072 + (size_t)cig * 64 * 256;
    // load: 64 ci rows x 256 pix, coalesced reads, conflict-free smem writes
    for (int r = 0; r < 64; ++r)
        sx[tid * 65 + r] = src[(size_t)r * 256 + tid];
    __syncthreads();

#pragma unroll
    for (int item2 = 0; item2 < 2; ++item2) {
        int item = item2 * 256 + tid;           // 512 items: 16 tiles x 32 cipairs
        int mloc = item >> 5, cip = item & 31;
        int ty = mloc >> 1, tx = mloc & 1;
        int y0 = 4 * ty - 1, x0 = 4 * tx - 1;
        int cb = 2 * cip;
        int m = img * 16 + mloc;
        int ci = cig * 64 + cb;

        float2 T[6][6];
#pragma unroll
        for (int c = 0; c < 6; ++c) {
            int x = x0 + c;
            float2 X[6];
#pragma unroll
            for (int r = 0; r < 6; ++r) {
                int y = y0 + r;
                bool ok = ((unsigned)y < 32u) && ((unsigned)x < 8u);
                if (ok) {
                    int pix = y * 8 + x;
                    X[r] = make_float2(sx[pix * 65 + cb], sx[pix * 65 + cb + 1]);
                } else X[r] = make_float2(0.f, 0.f);
            }
            T[0][c] = make_float2(4.f*X[0].x - 5.f*X[2].x + X[4].x,
                                  4.f*X[0].y - 5.f*X[2].y + X[4].y);
            T[1][c] = make_float2(-4.f*X[1].x - 4.f*X[2].x + X[3].x + X[4].x,
                                  -4.f*X[1].y - 4.f*X[2].y + X[3].y + X[4].y);
            T[2][c] = make_float2( 4.f*X[1].x - 4.f*X[2].x - X[3].x + X[4].x,
                                   4.f*X[1].y - 4.f*X[2].y - X[3].y + X[4].y);
            T[3][c] = make_float2(-2.f*X[1].x - X[2].x + 2.f*X[3].x + X[4].x,
                                  -2.f*X[1].y - X[2].y + 2.f*X[3].y + X[4].y);
            T[4][c] = make_float2( 2.f*X[1].x - X[2].x - 2.f*X[3].x + X[4].x,
                                   2.f*X[1].y - X[2].y - 2.f*X[3].y + X[4].y);
            T[5][c] = make_float2( 4.f*X[1].x - 5.f*X[3].x + X[5].x,
                                   4.f*X[1].y - 5.f*X[3].y + X[5].y);
        }
#pragma unroll
        for (int i = 0; i < 6; ++i) {
            float2 t0 = T[i][0], t1 = T[i][1], t2 = T[i][2];
            float2 t3 = T[i][3], t4 = T[i][4], t5 = T[i][5];
            float2 d[6];
            d[0] = make_float2(4.f*t0.x - 5.f*t2.x + t4.x, 4.f*t0.y - 5.f*t2.y + t4.y);
            d[1] = make_float2(-4.f*t1.x - 4.f*t2.x + t3.x + t4.x,
                               -4.f*t1.y - 4.f*t2.y + t3.y + t4.y);
            d[2] = make_float2( 4.f*t1.x - 4.f*t2.x - t3.x + t4.x,
                                4.f*t1.y - 4.f*t2.y - t3.y + t4.y);
            d[3] = make_float2(-2.f*t1.x - t2.x + 2.f*t3.x + t4.x,
                               -2.f*t1.y - t2.y + 2.f*t3.y + t4.y);
            d[4] = make_float2( 2.f*t1.x - t2.x - 2.f*t3.x + t4.x,
                                2.f*t1.y - t2.y - 2.f*t3.y + t4.y);
            d[5] = make_float2( 4.f*t1.x - 5.f*t3.x + t5.x,
                                4.f*t1.y - 5.f*t3.y + t5.y);
#pragma unroll
            for (int j = 0; j < 6; ++j) {
                size_t o = ((size_t)(z * 36 + i * 6 + j) * 512 + m) * 512 + ci;
                uint32_t hp, lp;
                split2(d[j].x, d[j].y, hp, lp);
                *(uint32_t*)&g_Vh[o] = hp;
                *(uint32_t*)&g_Vl[o] = lp;
            }
        }
    }
}

// ---------------------------------------------------------------------------
// F(4,3) input transform from g_saf (conv_o path), gmem reads (already coalesced)
// ---------------------------------------------------------------------------
__global__ void wino_in_o43()
{
    int e = blockIdx.x * 256 + threadIdx.x;     // 512 * 256
    int m = e >> 8, ci = (e & 255) * 2;
    int img = m >> 7, mr = m & 127;
    int ty = mr >> 6, tx = mr & 63;
    const float* src = g_saf + (size_t)img * 1048576 + ci;
    int y0 = 4 * ty - 1, x0 = 4 * tx - 1;
    float2 T[6][6];
#pragma unroll
    for (int c = 0; c < 6; ++c) {
        int x = x0 + c;
        float2 X[6];
#pragma unroll
        for (int r = 0; r < 6; ++r) {
            int y = y0 + r;
            bool ok = ((unsigned)y < 8u) && ((unsigned)x < 256u);
            X[r] = ok ? *(const float2*)&src[(size_t)(y * 256 + x) * 512]
                      : make_float2(0.f, 0.f);
        }
        T[0][c] = make_float2(4.f*X[0].x - 5.f*X[2].x + X[4].x,
                              4.f*X[0].y - 5.f*X[2].y + X[4].y);
        T[1][c] = make_float2(-4.f*X[1].x - 4.f*X[2].x + X[3].x + X[4].x,
                              -4.f*X[1].y - 4.f*X[2].y + X[3].y + X[4].y);
        T[2][c] = make_float2( 4.f*X[1].x - 4.f*X[2].x - X[3].x + X[4].x,
                               4.f*X[1].y - 4.f*X[2].y - X[3].y + X[4].y);
        T[3][c] = make_float2(-2.f*X[1].x - X[2].x + 2.f*X[3].x + X[4].x,
                              -2.f*X[1].y - X[2].y + 2.f*X[3].y + X[4].y);
        T[4][c] = make_float2( 2.f*X[1].x - X[2].x - 2.f*X[3].x + X[4].x,
                               2.f*X[1].y - X[2].y - 2.f*X[3].y + X[4].y);
        T[5][c] = make_float2( 4.f*X[1].x - 5.f*X[3].x + X[5].x,
                               4.f*X[1].y - 5.f*X[3].y + X[5].y);
    }
#pragma unroll
    for (int i = 0; i < 6; ++i) {
        float2 t0 = T[i][0], t1 = T[i][1], t2 = T[i][2];
        float2 t3 = T[i][3], t4 = T[i][4], t5 = T[i][5];
        float2 d[6];
        d[0] = make_float2(4.f*t0.x - 5.f*t2.x + t4.x, 4.f*t0.y - 5.f*t2.y + t4.y);
        d[1] = make_float2(-4.f*t1.x - 4.f*t2.x + t3.x + t4.x,
                           -4.f*t1.y - 4.f*t2.y + t3.y + t4.y);
        d[2] = make_float2( 4.f*t1.x - 4.f*t2.x - t3.x + t4.x,
                            4.f*t1.y - 4.f*t2.y - t3.y + t4.y);
        d[3] = make_float2(-2.f*t1.x - t2.x + 2.f*t3.x + t4.x,
                           -2.f*t1.y - t2.y + 2.f*t3.y + t4.y);
        d[4] = make_float2( 2.f*t1.x - t2.x - 2.f*t3.x + t4.x,
                            2.f*t1.y - t2.y - 2.f*t3.y + t4.y);
        d[5] = make_float2( 4.f*t1.x - 5.f*t3.x + t5.x,
                            4.f*t1.y - 5.f*t3.y + t5.y);
#pragma unroll
        for (int j = 0; j < 6; ++j) {
            size_t o = ((size_t)(i * 6 + j) * 512 + m) * 512 + ci;
            uint32_t hp, lp;
            split2(d[j].x, d[j].y, hp, lp);
            *(uint32_t*)&g_Vh[o] = hp;
            *(uint32_t*)&g_Vl[o] = lp;
        }
    }
}

// ---------------------------------------------------------------------------
// F(4,3) inverse: Y = A^T M A (4x4 from 6x6)
// ---------------------------------------------------------------------------
__device__ __forceinline__ void wino43_inv(const float (&M)[36], float (&Y)[4][4])
{
    float S[4][6];
#pragma unroll
    for (int c = 0; c < 6; ++c) {
        float m0 = M[c], m1 = M[6 + c], m2 = M[12 + c];
        float m3 = M[18 + c], m4 = M[24 + c], m5 = M[30 + c];
        S[0][c] = m0 + m1 + m2 + m3 + m4;
        S[1][c] = m1 - m2 + 2.f * m3 - 2.f * m4;
        S[2][c] = m1 + m2 + 4.f * m3 + 4.f * m4;
        S[3][c] = m1 - m2 + 8.f * m3 - 8.f * m4 + m5;
    }
#pragma unroll
    for (int i = 0; i < 4; ++i) {
        float s0 = S[i][0], s1 = S[i][1], s2 = S[i][2];
        float s3 = S[i][3], s4 = S[i][4], s5 = S[i][5];
        Y[i][0] = s0 + s1 + s2 + s3 + s4;
        Y[i][1] = s1 - s2 + 2.f * s3 - 2.f * s4;
        Y[i][2] = s1 + s2 + 4.f * s3 + 4.f * s4;
        Y[i][3] = s1 - s2 + 8.f * s3 - 8.f * s4 + s5;
    }
}

// qkv inverse; z<2: fused remap -> Q/K bf16 hi/lo; z=2: fp32 y2
__global__ void wino_out_y43(const float* __restrict__ bq, const float* __restrict__ bk,
                             const float* __restrict__ bv)
{
    int blk = blockIdx.x;          // 3072 = 3z * 512co * 2
    int z = blk >> 10;
    int r = blk & 1023;
    int co = r >> 1;
    int m = (r & 1) * 256 + threadIdx.x;
    const float* bias = (z == 0) ? bq : (z == 1) ? bk : bv;
    float M[36];
#pragma unroll
    for (int p = 0; p < 36; ++p)
        M[p] = g_M[(size_t)(z * 36 + p) * PSZ + co * 512 + m];
    float Y[4][4];
    wino43_inv(M, Y);
    float b = bias[co];
    int img = m >> 4, mr = m & 15;
    int ty = mr >> 1, tx = mr & 1;
    if (z == 2) {
        float* dst = g_y2 + ((size_t)img * 512 + co) * 256 + 32 * ty + 4 * tx;
#pragma unroll
        for (int i = 0; i < 4; ++i)
            *(float4*)&dst[8 * i] = make_float4(Y[i][0] + b, Y[i][1] + b,
                                                Y[i][2] + b, Y[i][3] + b);
    } else {
        __nv_bfloat16* oh = z ? g_Kh : g_Qh;
        __nv_bfloat16* ol = z ? g_Kl : g_Ql;
        int hh = img >> 2;
        int nn = (img & 3) * 8 + (co >> 6);
        int d  = (co & 63) * 8 + ty;
        size_t rowo = ((size_t)nn * 512 + d) * 256;
#pragma unroll
        for (int i = 0; i < 4; ++i) {
            int cbase = hh * 32 + 8 * i + 4 * tx;
            uint32_t h0, l0, h1, l1;
            split2(Y[i][0] + b, Y[i][1] + b, h0, l0);
            split2(Y[i][2] + b, Y[i][3] + b, h1, l1);
            *(uint2*)&oh[rowo + cbase] = make_uint2(h0, h1);
            *(uint2*)&ol[rowo + cbase] = make_uint2(l0, l1);
        }
    }
}

__global__ void wino_out_o43(const float* __restrict__ bo, float* __restrict__ out)
{
    int blk = blockIdx.x;          // 1024 = 512co * 2
    int co = blk >> 1;
    int m = (blk & 1) * 256 + threadIdx.x;
    float M[36];
#pragma unroll
    for (int p = 0; p < 36; ++p)
        M[p] = g_M[(size_t)p * PSZ + co * 512 + m];
    float Y[4][4];
    wino43_inv(M, Y);
    float b = bo[co];
    int img = m >> 7, mr = m & 127;
    int ty = mr >> 6, tx = mr & 63;
    float* dst = out + ((size_t)img * 512 + co) * 2048 + (4 * ty) * 256 + 4 * tx;
#pragma unroll
    for (int i = 0; i < 4; ++i)
        *(float4*)&dst[256 * i] = make_float4(Y[i][0] + b, Y[i][1] + b,
                                              Y[i][2] + b, Y[i][3] + b);
}

// ---------------------------------------------------------------------------
// V transpose remap: g_y2 -> Vt bf16 hi/lo [n][c][dk]
// ---------------------------------------------------------------------------
__global__ void remap_V()
{
    int e = blockIdx.x * 256 + threadIdx.x;
    int n = e >> 17, c = (e >> 9) & 255, dk = e & 511;
    int h = c >> 5, r = c & 31;
    float v = g_y2[(h * 4 + (n >> 3)) * 131072 + ((n & 7) * 64 + (dk >> 3)) * 256
                   + (dk & 7) * 32 + r];
    __nv_bfloat16 hh = __float2bfloat16(v);
    g_Vth[e] = hh;
    g_Vtl[e] = __float2bfloat16(v - __bfloat162float(hh));
}

// ---------------------------------------------------------------------------
// softmax over 512-wide rows, in place; also emit bf16 hi/lo
// ---------------------------------------------------------------------------
__global__ void softmax_rows(float* __restrict__ attn)
{
    size_t base = (size_t)blockIdx.x * 512;
    float* p = attn + base;
    int tid = threadIdx.x;
    float v0 = p[tid], v1 = p[tid + 256];
    float m = fmaxf(v0, v1);
#pragma unroll
    for (int o = 16; o; o >>= 1) m = fmaxf(m, __shfl_xor_sync(~0u, m, o));
    __shared__ float sm[8], ss[8];
    if ((tid & 31) == 0) sm[tid >> 5] = m;
    __syncthreads();
    if (tid < 8) {
        float mm = sm[tid];
#pragma unroll
        for (int o = 4; o; o >>= 1) mm = fmaxf(mm, __shfl_xor_sync(0xffu, mm, o));
        if (tid == 0) sm[0] = mm;
    }
    __syncthreads();
    float M = sm[0];
    float e0 = expf(v0 - M), e1 = expf(v1 - M);
    float s = e0 + e1;
#pragma unroll
    for (int o = 16; o; o >>= 1) s += __shfl_xor_sync(~0u, s, o);
    if ((tid & 31) == 0) ss[tid >> 5] = s;
    __syncthreads();
    if (tid < 8) {
        float t2 = ss[tid];
#pragma unroll
        for (int o = 4; o; o >>= 1) t2 += __shfl_xor_sync(0xffu, t2, o);
        if (tid == 0) ss[0] = t2;
    }
    __syncthreads();
    float inv = 1.f / ss[0];
    float a0 = e0 * inv, a1 = e1 * inv;
    p[tid] = a0;
    p[tid + 256] = a1;
    __nv_bfloat16 h0 = __float2bfloat16(a0), h1 = __float2bfloat16(a1);
    g_ath[base + tid]       = h0;
    g_atl[base + tid]       = __float2bfloat16(a0 - __bfloat162float(h0));
    g_ath[base + tid + 256] = h1;
    g_atl[base + tid + 256] = __float2bfloat16(a1 - __bfloat162float(h1));
}

// ---------------------------------------------------------------------------
// scatter O into conv_o input, fp32 pixel-major [b][pix][ci]
// ---------------------------------------------------------------------------
__global__ void remap_saf()
{
    int e = blockIdx.x * 256 + threadIdx.x;
    int b  = e >> 20;
    int p  = (e >> 9) & 2047;
    int d2 = e & 511;
    int s  = p >> 8;
    int rh = p & 255;
    int r2 = rh >> 3, h2 = rh & 7;
    int n  = b * 8 + s;
    int qd = r2 * 16 + h2 * 2 + (d2 >> 8);
    int rr = (d2 & 255) >> 3;
    int hh = d2 & 7;
    g_saf[e] = g_On[n * 131072 + qd * 256 + hh * 32 + rr];
}

// ---------------------------------------------------------------------------
extern "C" void kernel_launch(void* const* d_in, const int* in_sizes, int n_in,
                              void* d_out, int out_size)
{
    const float* q  = (const float*)d_in[0];
    const float* k  = (const float*)d_in[1];
    const float* v  = (const float*)d_in[2];
    const float* Wq = (const float*)d_in[3];
    const float* bq = (const float*)d_in[4];
    const float* Wk = (const float*)d_in[5];
    const float* bk = (const float*)d_in[6];
    const float* Wv = (const float*)d_in[7];
    const float* bv = (const float*)d_in[8];
    const float* Wo = (const float*)d_in[9];
    const float* bo = (const float*)d_in[10];

    float* y_out    = (float*)d_out;            // (4,512,8,32,8) = 4194304
    float* attn_out = y_out + NELEM;            // (1,32,512,512) = 8388608

    cudaFuncSetAttribute(gemm_persist,  cudaFuncAttributeMaxDynamicSharedMemorySize, SMEM_BYTES);
    cudaFuncSetAttribute(wino_in_qkv_f, cudaFuncAttributeMaxDynamicSharedMemorySize, XF_SMEM);

    // launch order: index 3 = gemm_persist (wino qkv), dominant kernel (profiled)
    prep_wU43<<<1024, 256>>>(Wq, Wk, 0);                                   // 0
    prep_wU43<<<1024, 256>>>(Wv, Wo, 2);                                   // 1
    wino_in_qkv_f<<<dim3(8, 32, 3), 256, XF_SMEM>>>(q, k, v);              // 2
    gemm_persist<<<296, 256, SMEM_BYTES>>>(0, 0, 1728, 512, 4, nullptr);   // 3 <- profiled
    wino_out_y43<<<3072, 256>>>(bq, bk, bv);                               // 4
    remap_V<<<NELEM / 256, 256>>>();                                       // 5
    gemm_persist<<<296, 256, SMEM_BYTES>>>(1, 0, 512, 256, 3, attn_out);   // 6
    softmax_rows<<<32 * 512, 256>>>(attn_out);                             // 7
    gemm_persist<<<256, 256, SMEM_BYTES>>>(2, 0, 256, 512, 4, nullptr);    // 8
    remap_saf<<<NELEM / 256, 256>>>();                                     // 9
    wino_in_o43<<<512, 256>>>();                                           // 10
    gemm_persist<<<296, 256, SMEM_BYTES>>>(0, 108, 576, 512, 4, nullptr);  // 11
    wino_out_o43<<<1024, 256>>>(bo, y_out);                                // 12
}

// round 14
// speedup vs baseline: 3.3279x; 1.0261x over previous
#include <cuda_runtime.h>
#include <cuda_bf16.h>
#include <cstdint>

#define NELEM 4194304          // 32*512*256 == 4*512*2048
#define PSZ   262144           // 512*512 (one U/V/M plane)

// ---------------------------------------------------------------------------
// device scratch
// ---------------------------------------------------------------------------
__device__ float g_saf[NELEM];           // conv_o input fp32 pixel-major [b][pix][ci]
__device__ __nv_bfloat16 g_Uh[144*PSZ];  // wino weights [conv*36+pos][co][ci]
__device__ __nv_bfloat16 g_Ul[144*PSZ];
__device__ __nv_bfloat16 g_Vh[108*PSZ];  // wino inputs  [plane][tile][ci]
__device__ __nv_bfloat16 g_Vl[108*PSZ];
__device__ float g_M[108*PSZ];           // GEMM out     [plane][co][tile]
__device__ float g_y2[NELEM];            // conv(v) output (32,512,256) fp32
__device__ __nv_bfloat16 g_Qh[NELEM], g_Ql[NELEM];   // [n][d][c], c=h*32+r
__device__ __nv_bfloat16 g_Kh[NELEM], g_Kl[NELEM];
__device__ __nv_bfloat16 g_Vth[NELEM], g_Vtl[NELEM]; // transposed: [n][c][dk]
__device__ __nv_bfloat16 g_ath[2*NELEM], g_atl[2*NELEM]; // attn hi/lo
__device__ float g_On[NELEM];            // attn @ V  [n][qd][c]

// ---------------------------------------------------------------------------
// helpers
// ---------------------------------------------------------------------------
__device__ __forceinline__ uint32_t smem_u32(const void* p) {
    uint32_t a;
    asm("{ .reg .u64 t; cvta.to.shared.u64 t, %1; cvt.u32.u64 %0, t; }" : "=r"(a) : "l"(p));
    return a;
}
#define SWZ(o) ((o) ^ (((o) >> 3) & 0x70))
#define CPA(dst, src, sz) \
    asm volatile("cp.async.cg.shared.global [%0], [%1], 16, %2;" \
        :: "r"(dst), "l"(src), "r"(sz) : "memory")
#define LDM4(r, addr) \
    asm volatile("ldmatrix.sync.aligned.m8n8.x4.shared.b16 {%0,%1,%2,%3}, [%4];" \
        : "=r"((r)[0]), "=r"((r)[1]), "=r"((r)[2]), "=r"((r)[3]) : "r"(addr))
#define MMA_BF16(d, a, b0, b1) \
    asm volatile("mma.sync.aligned.m16n8k16.row.col.f32.bf16.bf16.f32 " \
        "{%0,%1,%2,%3}, {%4,%5,%6,%7}, {%8,%9}, {%0,%1,%2,%3};" \
        : "+f"((d)[0]), "+f"((d)[1]), "+f"((d)[2]), "+f"((d)[3]) \
        : "r"((a)[0]), "r"((a)[1]), "r"((a)[2]), "r"((a)[3]), "r"(b0), "r"(b1))
#define WAITP(addr, ph) do { \
    asm volatile("{\n\t.reg .pred P;\n\tWL%=:\n\t" \
        "mbarrier.try_wait.parity.acquire.cta.shared::cta.b64 P, [%0], %1, 0x989680;\n\t" \
        "@P bra.uni WD%=;\n\tbra.uni WL%=;\n\tWD%=:\n\t}" \
        :: "r"(addr), "r"(ph) : "memory"); \
} while (0)

#define STAGE 32768u
#define MBAR_BASE 98304u
#define SMEM_BYTES 98368
#define PROW(r) ((uint32_t)((((r) >> 1) << 7) | (((r) & 1) << 6)))

__device__ __forceinline__ void split2(float v0, float v1, uint32_t& hp, uint32_t& lp) {
    __nv_bfloat16 h0 = __float2bfloat16(v0);
    __nv_bfloat16 h1 = __float2bfloat16(v1);
    __nv_bfloat16 l0 = __float2bfloat16(v0 - __bfloat162float(h0));
    __nv_bfloat16 l1 = __float2bfloat16(v1 - __bfloat162float(h1));
    hp = (uint32_t)*(uint16_t*)&h0 | ((uint32_t)*(uint16_t*)&h1 << 16);
    lp = (uint32_t)*(uint16_t*)&l0 | ((uint32_t)*(uint16_t*)&l1 << 16);
}

// ---------------------------------------------------------------------------
// compute one K32 chunk, warp tile 64x32: D += Ah*Bh + Ah*Bl + Al*Bh
// ---------------------------------------------------------------------------
__device__ __forceinline__ void mma_compute32(uint32_t bs, uint32_t a_rowb,
                                              uint32_t b_rowb, float (&acc)[16][4])
{
#pragma unroll
    for (int s = 0; s < 2; ++s) {
        uint32_t ah[4][4], bb[2][4], blf[2][4];
#pragma unroll
        for (int i = 0; i < 4; ++i)
            LDM4(ah[i], bs + SWZ(a_rowb + i * 1024 + s * 32));
#pragma unroll
        for (int j = 0; j < 2; ++j)
            LDM4(bb[j], bs + 16384u + SWZ(b_rowb + j * 1024 + s * 32));
#pragma unroll
        for (int i = 0; i < 4; ++i)
#pragma unroll
            for (int jj = 0; jj < 4; ++jj)
                MMA_BF16(acc[i * 4 + jj], ah[i],
                         bb[jj >> 1][(jj & 1) * 2], bb[jj >> 1][(jj & 1) * 2 + 1]);
#pragma unroll
        for (int j = 0; j < 2; ++j)
            LDM4(blf[j], bs + 24576u + SWZ(b_rowb + j * 1024 + s * 32));
#pragma unroll
        for (int i = 0; i < 4; ++i)
#pragma unroll
            for (int jj = 0; jj < 4; ++jj)
                MMA_BF16(acc[i * 4 + jj], ah[i],
                         blf[jj >> 1][(jj & 1) * 2], blf[jj >> 1][(jj & 1) * 2 + 1]);
#pragma unroll
        for (int i = 0; i < 4; ++i)
            LDM4(ah[i], bs + 8192u + SWZ(a_rowb + i * 1024 + s * 32));
#pragma unroll
        for (int i = 0; i < 4; ++i)
#pragma unroll
            for (int jj = 0; jj < 4; ++jj)
                MMA_BF16(acc[i * 4 + jj], ah[i],
                         bb[jj >> 1][(jj & 1) * 2], bb[jj >> 1][(jj & 1) * 2 + 1]);
    }
}

// ---------------------------------------------------------------------------
// mbarrier-pipelined GEMM: C(MxN) = A(MxK) * B(NxK)^T, bf16 hi/lo 3-term.
// CTA tile 128x128, warp tile 64x32, K32 chunks, 3 stages, 2 CTAs/SM.
// ---------------------------------------------------------------------------
__device__ __forceinline__ void gemm_mb(
    const __nv_bfloat16* __restrict__ Ah, const __nv_bfloat16* __restrict__ Al,
    const __nv_bfloat16* __restrict__ Bh, const __nv_bfloat16* __restrict__ Bl,
    int Kdim, int nchunk, float* __restrict__ C, int ldc)
{
    extern __shared__ char smem[];
    uint32_t sb = smem_u32(smem);
    int tid = threadIdx.x, wid = tid >> 5, lane = tid & 31;
    int m0 = blockIdx.y * 128, n0 = blockIdx.x * 128;
    int wm = wid & 1, wn = wid >> 1;

    int lr = tid >> 1, lh = tid & 1;
    uint32_t stb = PROW(lr) + lh * 32u;
    const char* srcA_h = (const char*)(Ah + (size_t)(m0 + lr) * Kdim + lh * 16);
    const char* srcA_l = (const char*)(Al + (size_t)(m0 + lr) * Kdim + lh * 16);
    const char* srcB_h = (const char*)(Bh + (size_t)(n0 + lr) * Kdim + lh * 16);
    const char* srcB_l = (const char*)(Bl + (size_t)(n0 + lr) * Kdim + lh * 16);

    int arow = wm * 64 + (lane & 15);
    uint32_t a_rowb = PROW(arow) + ((lane & 16) ? 16u : 0u);
    int brow = wn * 32 + (lane & 7) + ((lane & 16) ? 8 : 0);
    uint32_t b_rowb = PROW(brow) + ((lane & 8) ? 16u : 0u);

    if (tid == 0) {
#pragma unroll
        for (int s = 0; s < 3; ++s) {
            asm volatile("mbarrier.init.shared.b64 [%0], %1;"
                         :: "r"(sb + MBAR_BASE + s * 16u), "r"(256) : "memory");
            asm volatile("mbarrier.init.shared.b64 [%0], %1;"
                         :: "r"(sb + MBAR_BASE + s * 16u + 8u), "r"(256) : "memory");
        }
    }
    __syncthreads();

    float acc[16][4];
#pragma unroll
    for (int i = 0; i < 16; ++i)
#pragma unroll
        for (int j = 0; j < 4; ++j) acc[i][j] = 0.f;

    int ps = 0, pph = 1;
    int cs = 0, cph = 0;

    auto produce = [&](int itn) {
        uint32_t fmb = sb + MBAR_BASE + (uint32_t)ps * 16u;
        WAITP(fmb + 8u, pph);
        int cb = itn * 64;
        uint32_t bs = sb + (uint32_t)ps * STAGE;
        uint32_t s0 = SWZ(stb), s1 = SWZ(stb + 16u);
        CPA(bs + s0,          srcA_h + cb,      16u);
        CPA(bs + s1,          srcA_h + cb + 16, 16u);
        CPA(bs + 8192u + s0,  srcA_l + cb,      16u);
        CPA(bs + 8192u + s1,  srcA_l + cb + 16, 16u);
        CPA(bs + 16384u + s0, srcB_h + cb,      16u);
        CPA(bs + 16384u + s1, srcB_h + cb + 16, 16u);
        CPA(bs + 24576u + s0, srcB_l + cb,      16u);
        CPA(bs + 24576u + s1, srcB_l + cb + 16, 16u);
        asm volatile("cp.async.mbarrier.arrive.noinc.shared::cta.b64 [%0];"
                     :: "r"(fmb) : "memory");
        if (++ps == 3) { ps = 0; pph ^= 1; }
    };

    produce(0);
    produce(1);
    for (int it = 0; it < nchunk; ++it) {
        if (it + 2 < nchunk) produce(it + 2);
        uint32_t fmb = sb + MBAR_BASE + (uint32_t)cs * 16u;
        WAITP(fmb, cph);
        mma_compute32(sb + (uint32_t)cs * STAGE, a_rowb, b_rowb, acc);
        asm volatile("mbarrier.arrive.shared::cta.b64 _, [%0];"
                     :: "r"(fmb + 8u) : "memory");
        if (++cs == 3) { cs = 0; cph ^= 1; }
    }

#pragma unroll
    for (int i = 0; i < 4; ++i) {
        int row = m0 + wm * 64 + i * 16 + (lane >> 2);
#pragma unroll
        for (int jj = 0; jj < 4; ++jj) {
            int col = n0 + wn * 32 + jj * 8 + (lane & 3) * 2;
            float* d = acc[i * 4 + jj];
            *(float2*)&C[(size_t)row * ldc + col]       = make_float2(d[0], d[1]);
            *(float2*)&C[(size_t)(row + 8) * ldc + col] = make_float2(d[2], d[3]);
        }
    }
}

// ---------------------------------------------------------------------------
// F(4,3) weight transform: u = G w G^T (6x6), ci-pair, bf16 hi/lo
// ---------------------------------------------------------------------------
__global__ void prep_wU43(const float* __restrict__ Wa, const float* __restrict__ Wb,
                          int cbase)
{
    int g = blockIdx.x * 256 + threadIdx.x;     // 2conv * 512co * 256cip
    int conv = g >> 17;
    int r = g & 131071;
    int co = r >> 8, ci = (r & 255) * 2;
    const float* W = conv ? Wb : Wa;
    const float* w = W + (size_t)co * 4608 + ci * 9;
    const float c6 = 1.f / 6.f, c12 = 1.f / 12.f, c24 = 1.f / 24.f;
    float TA[6][3], TB[6][3];
#pragma unroll
    for (int k = 0; k < 3; ++k) {
        float a = w[k], b = w[3 + k], c = w[6 + k];
        TA[0][k] = 0.25f * a;
        TA[1][k] = -c6 * (a + b + c);
        TA[2][k] = -c6 * (a - b + c);
        TA[3][k] = c24 * a + c12 * b + c6 * c;
        TA[4][k] = c24 * a - c12 * b + c6 * c;
        TA[5][k] = c;
        float a1 = w[9 + k], b1 = w[12 + k], c1 = w[15 + k];
        TB[0][k] = 0.25f * a1;
        TB[1][k] = -c6 * (a1 + b1 + c1);
        TB[2][k] = -c6 * (a1 - b1 + c1);
        TB[3][k] = c24 * a1 + c12 * b1 + c6 * c1;
        TB[4][k] = c24 * a1 - c12 * b1 + c6 * c1;
        TB[5][k] = c1;
    }
#pragma unroll
    for (int i = 0; i < 6; ++i) {
        float a = TA[i][0], b = TA[i][1], c = TA[i][2];
        float uA[6] = {0.25f * a, -c6 * (a + b + c), -c6 * (a - b + c),
                       c24 * a + c12 * b + c6 * c, c24 * a - c12 * b + c6 * c, c};
        float a1 = TB[i][0], b1 = TB[i][1], c1 = TB[i][2];
        float uB[6] = {0.25f * a1, -c6 * (a1 + b1 + c1), -c6 * (a1 - b1 + c1),
                       c24 * a1 + c12 * b1 + c6 * c1, c24 * a1 - c12 * b1 + c6 * c1, c1};
#pragma unroll
        for (int j = 0; j < 6; ++j) {
            size_t o = ((size_t)((cbase + conv) * 36 + i * 6 + j) * 512 + co) * 512 + ci;
            uint32_t hp, lp;
            split2(uA[j], uB[j], hp, lp);
            *(uint32_t*)&g_Uh[o] = hp;
            *(uint32_t*)&g_Ul[o] = lp;
        }
    }
}

// ---------------------------------------------------------------------------
// fused transpose + F(4,3) input transform for q/k/v.
// CTA: (cig, img, z). Loads 64ci x 256pix slab coalesced into smem (stride 65),
// transforms, writes V planes bf16 hi/lo.
// ---------------------------------------------------------------------------
#define XF_SMEM (256 * 65 * 4)
__global__ void wino_in_qkv_f(const float* __restrict__ q, const float* __restrict__ k,
                              const float* __restrict__ v)
{
    extern __shared__ float sx[];     // [pix][ci] stride 65
    int cig = blockIdx.x;             // 0..7  (ci group of 64)
    int img = blockIdx.y;             // 0..31
    int z   = blockIdx.z;             // 0..2
    int tid = threadIdx.x;
    const float* base = (z == 0) ? q : (z == 1) ? k : v;
    const float* src = base + (size_t)img * 131072 + (size_t)cig * 64 * 256;
    for (int r = 0; r < 64; ++r)
        sx[tid * 65 + r] = src[(size_t)r * 256 + tid];
    __syncthreads();

#pragma unroll
    for (int item2 = 0; item2 < 2; ++item2) {
        int item = item2 * 256 + tid;           // 512 items: 16 tiles x 32 cipairs
        int mloc = item >> 5, cip = item & 31;
        int ty = mloc >> 1, tx = mloc & 1;
        int y0 = 4 * ty - 1, x0 = 4 * tx - 1;
        int cb = 2 * cip;
        int m = img * 16 + mloc;
        int ci = cig * 64 + cb;

        float2 T[6][6];
#pragma unroll
        for (int c = 0; c < 6; ++c) {
            int x = x0 + c;
            float2 X[6];
#pragma unroll
            for (int r = 0; r < 6; ++r) {
                int y = y0 + r;
                bool ok = ((unsigned)y < 32u) && ((unsigned)x < 8u);
                if (ok) {
                    int pix = y * 8 + x;
                    X[r] = make_float2(sx[pix * 65 + cb], sx[pix * 65 + cb + 1]);
                } else X[r] = make_float2(0.f, 0.f);
            }
            T[0][c] = make_float2(4.f*X[0].x - 5.f*X[2].x + X[4].x,
                                  4.f*X[0].y - 5.f*X[2].y + X[4].y);
            T[1][c] = make_float2(-4.f*X[1].x - 4.f*X[2].x + X[3].x + X[4].x,
                                  -4.f*X[1].y - 4.f*X[2].y + X[3].y + X[4].y);
            T[2][c] = make_float2( 4.f*X[1].x - 4.f*X[2].x - X[3].x + X[4].x,
                                   4.f*X[1].y - 4.f*X[2].y - X[3].y + X[4].y);
            T[3][c] = make_float2(-2.f*X[1].x - X[2].x + 2.f*X[3].x + X[4].x,
                                  -2.f*X[1].y - X[2].y + 2.f*X[3].y + X[4].y);
            T[4][c] = make_float2( 2.f*X[1].x - X[2].x - 2.f*X[3].x + X[4].x,
                                   2.f*X[1].y - X[2].y - 2.f*X[3].y + X[4].y);
            T[5][c] = make_float2( 4.f*X[1].x - 5.f*X[3].x + X[5].x,
                                   4.f*X[1].y - 5.f*X[3].y + X[5].y);
        }
#pragma unroll
        for (int i = 0; i < 6; ++i) {
            float2 t0 = T[i][0], t1 = T[i][1], t2 = T[i][2];
            float2 t3 = T[i][3], t4 = T[i][4], t5 = T[i][5];
            float2 d[6];
            d[0] = make_float2(4.f*t0.x - 5.f*t2.x + t4.x, 4.f*t0.y - 5.f*t2.y + t4.y);
            d[1] = make_float2(-4.f*t1.x - 4.f*t2.x + t3.x + t4.x,
                               -4.f*t1.y - 4.f*t2.y + t3.y + t4.y);
            d[2] = make_float2( 4.f*t1.x - 4.f*t2.x - t3.x + t4.x,
                                4.f*t1.y - 4.f*t2.y - t3.y + t4.y);
            d[3] = make_float2(-2.f*t1.x - t2.x + 2.f*t3.x + t4.x,
                               -2.f*t1.y - t2.y + 2.f*t3.y + t4.y);
            d[4] = make_float2( 2.f*t1.x - t2.x - 2.f*t3.x + t4.x,
                                2.f*t1.y - t2.y - 2.f*t3.y + t4.y);
            d[5] = make_float2( 4.f*t1.x - 5.f*t3.x + t5.x,
                                4.f*t1.y - 5.f*t3.y + t5.y);
#pragma unroll
            for (int j = 0; j < 6; ++j) {
                size_t o = ((size_t)(z * 36 + i * 6 + j) * 512 + m) * 512 + ci;
                uint32_t hp, lp;
                split2(d[j].x, d[j].y, hp, lp);
                *(uint32_t*)&g_Vh[o] = hp;
                *(uint32_t*)&g_Vl[o] = lp;
            }
        }
    }
}

// ---------------------------------------------------------------------------
// F(4,3) input transform from g_saf (conv_o path)
// ---------------------------------------------------------------------------
__global__ void wino_in_o43()
{
    int e = blockIdx.x * 256 + threadIdx.x;     // 512 * 256
    int m = e >> 8, ci = (e & 255) * 2;
    int img = m >> 7, mr = m & 127;
    int ty = mr >> 6, tx = mr & 63;
    const float* src = g_saf + (size_t)img * 1048576 + ci;
    int y0 = 4 * ty - 1, x0 = 4 * tx - 1;
    float2 T[6][6];
#pragma unroll
    for (int c = 0; c < 6; ++c) {
        int x = x0 + c;
        float2 X[6];
#pragma unroll
        for (int r = 0; r < 6; ++r) {
            int y = y0 + r;
            bool ok = ((unsigned)y < 8u) && ((unsigned)x < 256u);
            X[r] = ok ? *(const float2*)&src[(size_t)(y * 256 + x) * 512]
                      : make_float2(0.f, 0.f);
        }
        T[0][c] = make_float2(4.f*X[0].x - 5.f*X[2].x + X[4].x,
                              4.f*X[0].y - 5.f*X[2].y + X[4].y);
        T[1][c] = make_float2(-4.f*X[1].x - 4.f*X[2].x + X[3].x + X[4].x,
                              -4.f*X[1].y - 4.f*X[2].y + X[3].y + X[4].y);
        T[2][c] = make_float2( 4.f*X[1].x - 4.f*X[2].x - X[3].x + X[4].x,
                               4.f*X[1].y - 4.f*X[2].y - X[3].y + X[4].y);
        T[3][c] = make_float2(-2.f*X[1].x - X[2].x + 2.f*X[3].x + X[4].x,
                              -2.f*X[1].y - X[2].y + 2.f*X[3].y + X[4].y);
        T[4][c] = make_float2( 2.f*X[1].x - X[2].x - 2.f*X[3].x + X[4].x,
                               2.f*X[1].y - X[2].y - 2.f*X[3].y + X[4].y);
        T[5][c] = make_float2( 4.f*X[1].x - 5.f*X[3].x + X[5].x,
                               4.f*X[1].y - 5.f*X[3].y + X[5].y);
    }
#pragma unroll
    for (int i = 0; i < 6; ++i) {
        float2 t0 = T[i][0], t1 = T[i][1], t2 = T[i][2];
        float2 t3 = T[i][3], t4 = T[i][4], t5 = T[i][5];
        float2 d[6];
        d[0] = make_float2(4.f*t0.x - 5.f*t2.x + t4.x, 4.f*t0.y - 5.f*t2.y + t4.y);
        d[1] = make_float2(-4.f*t1.x - 4.f*t2.x + t3.x + t4.x,
                           -4.f*t1.y - 4.f*t2.y + t3.y + t4.y);
        d[2] = make_float2( 4.f*t1.x - 4.f*t2.x - t3.x + t4.x,
                            4.f*t1.y - 4.f*t2.y - t3.y + t4.y);
        d[3] = make_float2(-2.f*t1.x - t2.x + 2.f*t3.x + t4.x,
                           -2.f*t1.y - t2.y + 2.f*t3.y + t4.y);
        d[4] = make_float2( 2.f*t1.x - t2.x - 2.f*t3.x + t4.x,
                            2.f*t1.y - t2.y - 2.f*t3.y + t4.y);
        d[5] = make_float2( 4.f*t1.x - 5.f*t3.x + t5.x,
                            4.f*t1.y - 5.f*t3.y + t5.y);
#pragma unroll
        for (int j = 0; j < 6; ++j) {
            size_t o = ((size_t)(i * 6 + j) * 512 + m) * 512 + ci;
            uint32_t hp, lp;
            split2(d[j].x, d[j].y, hp, lp);
            *(uint32_t*)&g_Vh[o] = hp;
            *(uint32_t*)&g_Vl[o] = lp;
        }
    }
}

// ---------------------------------------------------------------------------
// Winograd GEMM: per plane, C[co][tile] = U[co][ci] . V[tile][ci]^T
// ---------------------------------------------------------------------------
__global__ __launch_bounds__(256, 2) void gemm_wino(int ubase)
{
    int zp = blockIdx.z;
    gemm_mb(g_Uh + (size_t)(ubase + zp) * PSZ, g_Ul + (size_t)(ubase + zp) * PSZ,
            g_Vh + (size_t)zp * PSZ, g_Vl + (size_t)zp * PSZ,
            512, 16, g_M + (size_t)zp * PSZ, 512);
}

// ---------------------------------------------------------------------------
// F(4,3) inverse: Y = A^T M A (4x4 from 6x6)
// ---------------------------------------------------------------------------
__device__ __forceinline__ void wino43_inv(const float (&M)[36], float (&Y)[4][4])
{
    float S[4][6];
#pragma unroll
    for (int c = 0; c < 6; ++c) {
        float m0 = M[c], m1 = M[6 + c], m2 = M[12 + c];
        float m3 = M[18 + c], m4 = M[24 + c], m5 = M[30 + c];
        S[0][c] = m0 + m1 + m2 + m3 + m4;
        S[1][c] = m1 - m2 + 2.f * m3 - 2.f * m4;
        S[2][c] = m1 + m2 + 4.f * m3 + 4.f * m4;
        S[3][c] = m1 - m2 + 8.f * m3 - 8.f * m4 + m5;
    }
#pragma unroll
    for (int i = 0; i < 4; ++i) {
        float s0 = S[i][0], s1 = S[i][1], s2 = S[i][2];
        float s3 = S[i][3], s4 = S[i][4], s5 = S[i][5];
        Y[i][0] = s0 + s1 + s2 + s3 + s4;
        Y[i][1] = s1 - s2 + 2.f * s3 - 2.f * s4;
        Y[i][2] = s1 + s2 + 4.f * s3 + 4.f * s4;
        Y[i][3] = s1 - s2 + 8.f * s3 - 8.f * s4 + s5;
    }
}

// qkv inverse; z<2: fused remap -> Q/K bf16 hi/lo; z=2: fp32 y2
__global__ void wino_out_y43(const float* __restrict__ bq, const float* __restrict__ bk,
                             const float* __restrict__ bv)
{
    int blk = blockIdx.x;          // 3072 = 3z * 512co * 2
    int z = blk >> 10;
    int r = blk & 1023;
    int co = r >> 1;
    int m = (r & 1) * 256 + threadIdx.x;
    const float* bias = (z == 0) ? bq : (z == 1) ? bk : bv;
    float M[36];
#pragma unroll
    for (int p = 0; p < 36; ++p)
        M[p] = g_M[(size_t)(z * 36 + p) * PSZ + co * 512 + m];
    float Y[4][4];
    wino43_inv(M, Y);
    float b = bias[co];
    int img = m >> 4, mr = m & 15;
    int ty = mr >> 1, tx = mr & 1;
    if (z == 2) {
        float* dst = g_y2 + ((size_t)img * 512 + co) * 256 + 32 * ty + 4 * tx;
#pragma unroll
        for (int i = 0; i < 4; ++i)
            *(float4*)&dst[8 * i] = make_float4(Y[i][0] + b, Y[i][1] + b,
                                                Y[i][2] + b, Y[i][3] + b);
    } else {
        __nv_bfloat16* oh = z ? g_Kh : g_Qh;
        __nv_bfloat16* ol = z ? g_Kl : g_Ql;
        int hh = img >> 2;
        int nn = (img & 3) * 8 + (co >> 6);
        int d  = (co & 63) * 8 + ty;
        size_t rowo = ((size_t)nn * 512 + d) * 256;
#pragma unroll
        for (int i = 0; i < 4; ++i) {
            int cbase = hh * 32 + 8 * i + 4 * tx;
            uint32_t h0, l0, h1, l1;
            split2(Y[i][0] + b, Y[i][1] + b, h0, l0);
            split2(Y[i][2] + b, Y[i][3] + b, h1, l1);
            *(uint2*)&oh[rowo + cbase] = make_uint2(h0, h1);
            *(uint2*)&ol[rowo + cbase] = make_uint2(l0, l1);
        }
    }
}

__global__ void wino_out_o43(const float* __restrict__ bo, float* __restrict__ out)
{
    int blk = blockIdx.x;          // 1024 = 512co * 2
    int co = blk >> 1;
    int m = (blk & 1) * 256 + threadIdx.x;
    float M[36];
#pragma unroll
    for (int p = 0; p < 36; ++p)
        M[p] = g_M[(size_t)p * PSZ + co * 512 + m];
    float Y[4][4];
    wino43_inv(M, Y);
    float b = bo[co];
    int img = m >> 7, mr = m & 127;
    int ty = mr >> 6, tx = mr & 63;
    float* dst = out + ((size_t)img * 512 + co) * 2048 + (4 * ty) * 256 + 4 * tx;
#pragma unroll
    for (int i = 0; i < 4; ++i)
        *(float4*)&dst[256 * i] = make_float4(Y[i][0] + b, Y[i][1] + b,
                                              Y[i][2] + b, Y[i][3] + b);
}

// ---------------------------------------------------------------------------
// V transpose remap: g_y2 -> Vt bf16 hi/lo [n][c][dk]
// ---------------------------------------------------------------------------
__global__ void remap_V()
{
    int e = blockIdx.x * 256 + threadIdx.x;
    int n = e >> 17, c = (e >> 9) & 255, dk = e & 511;
    int h = c >> 5, r = c & 31;
    float v = g_y2[(h * 4 + (n >> 3)) * 131072 + ((n & 7) * 64 + (dk >> 3)) * 256
                   + (dk & 7) * 32 + r];
    __nv_bfloat16 hh = __float2bfloat16(v);
    g_Vth[e] = hh;
    g_Vtl[e] = __float2bfloat16(v - __bfloat162float(hh));
}

// ---------------------------------------------------------------------------
// attention GEMMs (mbarrier pipeline)
// ---------------------------------------------------------------------------
__global__ __launch_bounds__(256, 2) void gemm_scores(float* __restrict__ attn)
{
    int nb = blockIdx.z;
    gemm_mb(g_Qh + (size_t)nb * 131072, g_Ql + (size_t)nb * 131072,
            g_Kh + (size_t)nb * 131072, g_Kl + (size_t)nb * 131072,
            256, 8, attn + (size_t)nb * 262144, 512);
}

__global__ __launch_bounds__(256, 2) void gemm_nnout()
{
    int nb = blockIdx.z;
    gemm_mb(g_ath + (size_t)nb * 262144, g_atl + (size_t)nb * 262144,
            g_Vth + (size_t)nb * 131072, g_Vtl + (size_t)nb * 131072,
            512, 16, g_On + (size_t)nb * 131072, 256);
}

// ---------------------------------------------------------------------------
// softmax over 512-wide rows, in place; also emit bf16 hi/lo
// ---------------------------------------------------------------------------
__global__ void softmax_rows(float* __restrict__ attn)
{
    size_t base = (size_t)blockIdx.x * 512;
    float* p = attn + base;
    int tid = threadIdx.x;
    float v0 = p[tid], v1 = p[tid + 256];
    float m = fmaxf(v0, v1);
#pragma unroll
    for (int o = 16; o; o >>= 1) m = fmaxf(m, __shfl_xor_sync(~0u, m, o));
    __shared__ float sm[8], ss[8];
    if ((tid & 31) == 0) sm[tid >> 5] = m;
    __syncthreads();
    if (tid < 8) {
        float mm = sm[tid];
#pragma unroll
        for (int o = 4; o; o >>= 1) mm = fmaxf(mm, __shfl_xor_sync(0xffu, mm, o));
        if (tid == 0) sm[0] = mm;
    }
    __syncthreads();
    float M = sm[0];
    float e0 = expf(v0 - M), e1 = expf(v1 - M);
    float s = e0 + e1;
#pragma unroll
    for (int o = 16; o; o >>= 1) s += __shfl_xor_sync(~0u, s, o);
    if ((tid & 31) == 0) ss[tid >> 5] = s;
    __syncthreads();
    if (tid < 8) {
        float t2 = ss[tid];
#pragma unroll
        for (int o = 4; o; o >>= 1) t2 += __shfl_xor_sync(0xffu, t2, o);
        if (tid == 0) ss[0] = t2;
    }
    __syncthreads();
    float inv = 1.f / ss[0];
    float a0 = e0 * inv, a1 = e1 * inv;
    p[tid] = a0;
    p[tid + 256] = a1;
    __nv_bfloat16 h0 = __float2bfloat16(a0), h1 = __float2bfloat16(a1);
    g_ath[base + tid]       = h0;
    g_atl[base + tid]       = __float2bfloat16(a0 - __bfloat162float(h0));
    g_ath[base + tid + 256] = h1;
    g_atl[base + tid + 256] = __float2bfloat16(a1 - __bfloat162float(h1));
}

// ---------------------------------------------------------------------------
// scatter O into conv_o input, fp32 pixel-major [b][pix][ci]
// ---------------------------------------------------------------------------
__global__ void remap_saf()
{
    int e = blockIdx.x * 256 + threadIdx.x;
    int b  = e >> 20;
    int p  = (e >> 9) & 2047;
    int d2 = e & 511;
    int s  = p >> 8;
    int rh = p & 255;
    int r2 = rh >> 3, h2 = rh & 7;
    int n  = b * 8 + s;
    int qd = r2 * 16 + h2 * 2 + (d2 >> 8);
    int rr = (d2 & 255) >> 3;
    int hh = d2 & 7;
    g_saf[e] = g_On[n * 131072 + qd * 256 + hh * 32 + rr];
}

// ---------------------------------------------------------------------------
extern "C" void kernel_launch(void* const* d_in, const int* in_sizes, int n_in,
                              void* d_out, int out_size)
{
    const float* q  = (const float*)d_in[0];
    const float* k  = (const float*)d_in[1];
    const float* v  = (const float*)d_in[2];
    const float* Wq = (const float*)d_in[3];
    const float* bq = (const float*)d_in[4];
    const float* Wk = (const float*)d_in[5];
    const float* bk = (const float*)d_in[6];
    const float* Wv = (const float*)d_in[7];
    const float* bv = (const float*)d_in[8];
    const float* Wo = (const float*)d_in[9];
    const float* bo = (const float*)d_in[10];

    float* y_out    = (float*)d_out;            // (4,512,8,32,8) = 4194304
    float* attn_out = y_out + NELEM;            // (1,32,512,512) = 8388608

    cudaFuncSetAttribute(gemm_wino,     cudaFuncAttributeMaxDynamicSharedMemorySize, SMEM_BYTES);
    cudaFuncSetAttribute(gemm_scores,   cudaFuncAttributeMaxDynamicSharedMemorySize, SMEM_BYTES);
    cudaFuncSetAttribute(gemm_nnout,    cudaFuncAttributeMaxDynamicSharedMemorySize, SMEM_BYTES);
    cudaFuncSetAttribute(wino_in_qkv_f, cudaFuncAttributeMaxDynamicSharedMemorySize, XF_SMEM);

    // launch order: index 3 = gemm_wino (qkv), dominant kernel (profiled)
    prep_wU43<<<1024, 256>>>(Wq, Wk, 0);                             // 0
    prep_wU43<<<1024, 256>>>(Wv, Wo, 2);                             // 1
    wino_in_qkv_f<<<dim3(8, 32, 3), 256, XF_SMEM>>>(q, k, v);        // 2
    gemm_wino<<<dim3(4, 4, 108), 256, SMEM_BYTES>>>(0);              // 3  <- profiled
    wino_out_y43<<<3072, 256>>>(bq, bk, bv);                         // 4
    remap_V<<<NELEM / 256, 256>>>();                                 // 5
    gemm_scores<<<dim3(4, 4, 32), 256, SMEM_BYTES>>>(attn_out);      // 6
    softmax_rows<<<32 * 512, 256>>>(attn_out);                       // 7
    gemm_nnout<<<dim3(2, 4, 32), 256, SMEM_BYTES>>>();               // 8
    remap_saf<<<NELEM / 256, 256>>>();                               // 9
    wino_in_o43<<<512, 256>>>();                                     // 10
    gemm_wino<<<dim3(4, 4, 36), 256, SMEM_BYTES>>>(108);             // 11
    wino_out_o43<<<1024, 256>>>(bo, y_out);                          // 12
}

// round 15
// speedup vs baseline: 3.4558x; 1.0384x over previous
#include <cuda_runtime.h>
#include <cuda_bf16.h>
#include <cstdint>

#define NELEM 4194304          // 32*512*256 == 4*512*2048
#define PSZ   262144           // 512*512 (one U/V/M plane)

// ---------------------------------------------------------------------------
// device scratch
// ---------------------------------------------------------------------------
__device__ float g_saf[NELEM];           // conv_o input fp32 pixel-major [b][pix][ci]
__device__ __nv_bfloat16 g_Uh[144*PSZ];  // wino weights [conv*36+pos][co][ci]
__device__ __nv_bfloat16 g_Ul[144*PSZ];
__device__ __nv_bfloat16 g_Vh[108*PSZ];  // wino inputs  [plane][tile][ci]
__device__ __nv_bfloat16 g_Vl[108*PSZ];
__device__ float g_M[108*PSZ];           // GEMM out     [plane][co][tile]
__device__ float g_y2[NELEM];            // conv(v) output (32,512,256) fp32
__device__ __nv_bfloat16 g_Qh[NELEM], g_Ql[NELEM];   // [n][d][c], c=h*32+r
__device__ __nv_bfloat16 g_Kh[NELEM], g_Kl[NELEM];
__device__ __nv_bfloat16 g_Vth[NELEM], g_Vtl[NELEM]; // transposed: [n][c][dk]
__device__ __nv_bfloat16 g_ath[2*NELEM], g_atl[2*NELEM]; // attn hi/lo

// ---------------------------------------------------------------------------
// helpers
// ---------------------------------------------------------------------------
__device__ __forceinline__ uint32_t smem_u32(const void* p) {
    uint32_t a;
    asm("{ .reg .u64 t; cvta.to.shared.u64 t, %1; cvt.u32.u64 %0, t; }" : "=r"(a) : "l"(p));
    return a;
}
#define SWZ(o) ((o) ^ (((o) >> 3) & 0x70))
#define CPA(dst, src, sz) \
    asm volatile("cp.async.cg.shared.global [%0], [%1], 16, %2;" \
        :: "r"(dst), "l"(src), "r"(sz) : "memory")
#define LDM4(r, addr) \
    asm volatile("ldmatrix.sync.aligned.m8n8.x4.shared.b16 {%0,%1,%2,%3}, [%4];" \
        : "=r"((r)[0]), "=r"((r)[1]), "=r"((r)[2]), "=r"((r)[3]) : "r"(addr))
#define MMA_BF16(d, a, b0, b1) \
    asm volatile("mma.sync.aligned.m16n8k16.row.col.f32.bf16.bf16.f32 " \
        "{%0,%1,%2,%3}, {%4,%5,%6,%7}, {%8,%9}, {%0,%1,%2,%3};" \
        : "+f"((d)[0]), "+f"((d)[1]), "+f"((d)[2]), "+f"((d)[3]) \
        : "r"((a)[0]), "r"((a)[1]), "r"((a)[2]), "r"((a)[3]), "r"(b0), "r"(b1))
#define WAITP(addr, ph) do { \
    asm volatile("{\n\t.reg .pred P;\n\tWL%=:\n\t" \
        "mbarrier.try_wait.parity.acquire.cta.shared::cta.b64 P, [%0], %1, 0x989680;\n\t" \
        "@P bra.uni WD%=;\n\tbra.uni WL%=;\n\tWD%=:\n\t}" \
        :: "r"(addr), "r"(ph) : "memory"); \
} while (0)

#define STAGE 32768u
#define MBAR_BASE 98304u
#define SMEM_BYTES 98368
#define PROW(r) ((uint32_t)((((r) >> 1) << 7) | (((r) & 1) << 6)))

__device__ __forceinline__ void split2(float v0, float v1, uint32_t& hp, uint32_t& lp) {
    __nv_bfloat16 h0 = __float2bfloat16(v0);
    __nv_bfloat16 h1 = __float2bfloat16(v1);
    __nv_bfloat16 l0 = __float2bfloat16(v0 - __bfloat162float(h0));
    __nv_bfloat16 l1 = __float2bfloat16(v1 - __bfloat162float(h1));
    hp = (uint32_t)*(uint16_t*)&h0 | ((uint32_t)*(uint16_t*)&h1 << 16);
    lp = (uint32_t)*(uint16_t*)&l0 | ((uint32_t)*(uint16_t*)&l1 << 16);
}

// ---------------------------------------------------------------------------
// compute one K32 chunk, warp tile 64x32: D += Ah*Bh + Ah*Bl + Al*Bh
// ---------------------------------------------------------------------------
__device__ __forceinline__ void mma_compute32(uint32_t bs, uint32_t a_rowb,
                                              uint32_t b_rowb, float (&acc)[16][4])
{
#pragma unroll
    for (int s = 0; s < 2; ++s) {
        uint32_t ah[4][4], bb[2][4], blf[2][4];
#pragma unroll
        for (int i = 0; i < 4; ++i)
            LDM4(ah[i], bs + SWZ(a_rowb + i * 1024 + s * 32));
#pragma unroll
        for (int j = 0; j < 2; ++j)
            LDM4(bb[j], bs + 16384u + SWZ(b_rowb + j * 1024 + s * 32));
#pragma unroll
        for (int i = 0; i < 4; ++i)
#pragma unroll
            for (int jj = 0; jj < 4; ++jj)
                MMA_BF16(acc[i * 4 + jj], ah[i],
                         bb[jj >> 1][(jj & 1) * 2], bb[jj >> 1][(jj & 1) * 2 + 1]);
#pragma unroll
        for (int j = 0; j < 2; ++j)
            LDM4(blf[j], bs + 24576u + SWZ(b_rowb + j * 1024 + s * 32));
#pragma unroll
        for (int i = 0; i < 4; ++i)
#pragma unroll
            for (int jj = 0; jj < 4; ++jj)
                MMA_BF16(acc[i * 4 + jj], ah[i],
                         blf[jj >> 1][(jj & 1) * 2], blf[jj >> 1][(jj & 1) * 2 + 1]);
#pragma unroll
        for (int i = 0; i < 4; ++i)
            LDM4(ah[i], bs + 8192u + SWZ(a_rowb + i * 1024 + s * 32));
#pragma unroll
        for (int i = 0; i < 4; ++i)
#pragma unroll
            for (int jj = 0; jj < 4; ++jj)
                MMA_BF16(acc[i * 4 + jj], ah[i],
                         bb[jj >> 1][(jj & 1) * 2], bb[jj >> 1][(jj & 1) * 2 + 1]);
    }
}

// ---------------------------------------------------------------------------
// pipeline state shared by the GEMM bodies
// ---------------------------------------------------------------------------
struct PipeCtx {
    uint32_t sb, stb, a_rowb, b_rowb;
    const char *srcA_h, *srcA_l, *srcB_h, *srcB_l;
    int ps, pph, cs, cph;
};

__device__ __forceinline__ void pipe_init(PipeCtx& P, uint32_t sb, int tid,
    const __nv_bfloat16* Ah, const __nv_bfloat16* Al,
    const __nv_bfloat16* Bh, const __nv_bfloat16* Bl,
    int m0, int n0, int Kdim)
{
    int wid = tid >> 5, lane = tid & 31;
    int wm = wid & 1, wn = wid >> 1;
    int lr = tid >> 1, lh = tid & 1;
    P.sb = sb;
    P.stb = PROW(lr) + lh * 32u;
    P.srcA_h = (const char*)(Ah + (size_t)(m0 + lr) * Kdim + lh * 16);
    P.srcA_l = (const char*)(Al + (size_t)(m0 + lr) * Kdim + lh * 16);
    P.srcB_h = (const char*)(Bh + (size_t)(n0 + lr) * Kdim + lh * 16);
    P.srcB_l = (const char*)(Bl + (size_t)(n0 + lr) * Kdim + lh * 16);
    int arow = wm * 64 + (lane & 15);
    P.a_rowb = PROW(arow) + ((lane & 16) ? 16u : 0u);
    int brow = wn * 32 + (lane & 7) + ((lane & 16) ? 8 : 0);
    P.b_rowb = PROW(brow) + ((lane & 8) ? 16u : 0u);
    if (tid == 0) {
#pragma unroll
        for (int s = 0; s < 3; ++s) {
            asm volatile("mbarrier.init.shared.b64 [%0], %1;"
                         :: "r"(sb + MBAR_BASE + s * 16u), "r"(256) : "memory");
            asm volatile("mbarrier.init.shared.b64 [%0], %1;"
                         :: "r"(sb + MBAR_BASE + s * 16u + 8u), "r"(256) : "memory");
        }
    }
    __syncthreads();
    P.ps = 0; P.pph = 1; P.cs = 0; P.cph = 0;
}

__device__ __forceinline__ void pipe_produce(PipeCtx& P, int itn)
{
    uint32_t fmb = P.sb + MBAR_BASE + (uint32_t)P.ps * 16u;
    WAITP(fmb + 8u, P.pph);
    int cb = itn * 64;
    uint32_t bs = P.sb + (uint32_t)P.ps * STAGE;
    uint32_t s0 = SWZ(P.stb), s1 = SWZ(P.stb + 16u);
    CPA(bs + s0,          P.srcA_h + cb,      16u);
    CPA(bs + s1,          P.srcA_h + cb + 16, 16u);
    CPA(bs + 8192u + s0,  P.srcA_l + cb,      16u);
    CPA(bs + 8192u + s1,  P.srcA_l + cb + 16, 16u);
    CPA(bs + 16384u + s0, P.srcB_h + cb,      16u);
    CPA(bs + 16384u + s1, P.srcB_h + cb + 16, 16u);
    CPA(bs + 24576u + s0, P.srcB_l + cb,      16u);
    CPA(bs + 24576u + s1, P.srcB_l + cb + 16, 16u);
    asm volatile("cp.async.mbarrier.arrive.noinc.shared::cta.b64 [%0];"
                 :: "r"(fmb) : "memory");
    if (++P.ps == 3) { P.ps = 0; P.pph ^= 1; }
}

__device__ __forceinline__ void pipe_mainloop(PipeCtx& P, int nchunk, float (&acc)[16][4])
{
    pipe_produce(P, 0);
    pipe_produce(P, 1);
    for (int it = 0; it < nchunk; ++it) {
        if (it + 2 < nchunk) pipe_produce(P, it + 2);
        uint32_t fmb = P.sb + MBAR_BASE + (uint32_t)P.cs * 16u;
        WAITP(fmb, P.cph);
        mma_compute32(P.sb + (uint32_t)P.cs * STAGE, P.a_rowb, P.b_rowb, acc);
        asm volatile("mbarrier.arrive.shared::cta.b64 _, [%0];"
                     :: "r"(fmb + 8u) : "memory");
        if (++P.cs == 3) { P.cs = 0; P.cph ^= 1; }
    }
}

// ---------------------------------------------------------------------------
// mbarrier-pipelined GEMM with direct row-major epilogue
// ---------------------------------------------------------------------------
__device__ __forceinline__ void gemm_mb(
    const __nv_bfloat16* __restrict__ Ah, const __nv_bfloat16* __restrict__ Al,
    const __nv_bfloat16* __restrict__ Bh, const __nv_bfloat16* __restrict__ Bl,
    int Kdim, int nchunk, float* __restrict__ C, int ldc)
{
    extern __shared__ char smem[];
    uint32_t sb = smem_u32(smem);
    int tid = threadIdx.x, wid = tid >> 5, lane = tid & 31;
    int m0 = blockIdx.y * 128, n0 = blockIdx.x * 128;
    int wm = wid & 1, wn = wid >> 1;

    PipeCtx P;
    pipe_init(P, sb, tid, Ah, Al, Bh, Bl, m0, n0, Kdim);

    float acc[16][4];
#pragma unroll
    for (int i = 0; i < 16; ++i)
#pragma unroll
        for (int j = 0; j < 4; ++j) acc[i][j] = 0.f;

    pipe_mainloop(P, nchunk, acc);

#pragma unroll
    for (int i = 0; i < 4; ++i) {
        int row = m0 + wm * 64 + i * 16 + (lane >> 2);
#pragma unroll
        for (int jj = 0; jj < 4; ++jj) {
            int col = n0 + wn * 32 + jj * 8 + (lane & 3) * 2;
            float* d = acc[i * 4 + jj];
            *(float2*)&C[(size_t)row * ldc + col]       = make_float2(d[0], d[1]);
            *(float2*)&C[(size_t)(row + 8) * ldc + col] = make_float2(d[2], d[3]);
        }
    }
}

// ---------------------------------------------------------------------------
// F(4,3) weight transform: u = G w G^T (6x6), ci-pair, bf16 hi/lo
// ---------------------------------------------------------------------------
__global__ void prep_wU43(const float* __restrict__ Wa, const float* __restrict__ Wb,
                          int cbase)
{
    int g = blockIdx.x * 256 + threadIdx.x;
    int conv = g >> 17;
    int r = g & 131071;
    int co = r >> 8, ci = (r & 255) * 2;
    const float* W = conv ? Wb : Wa;
    const float* w = W + (size_t)co * 4608 + ci * 9;
    const float c6 = 1.f / 6.f, c12 = 1.f / 12.f, c24 = 1.f / 24.f;
    float TA[6][3], TB[6][3];
#pragma unroll
    for (int k = 0; k < 3; ++k) {
        float a = w[k], b = w[3 + k], c = w[6 + k];
        TA[0][k] = 0.25f * a;
        TA[1][k] = -c6 * (a + b + c);
        TA[2][k] = -c6 * (a - b + c);
        TA[3][k] = c24 * a + c12 * b + c6 * c;
        TA[4][k] = c24 * a - c12 * b + c6 * c;
        TA[5][k] = c;
        float a1 = w[9 + k], b1 = w[12 + k], c1 = w[15 + k];
        TB[0][k] = 0.25f * a1;
        TB[1][k] = -c6 * (a1 + b1 + c1);
        TB[2][k] = -c6 * (a1 - b1 + c1);
        TB[3][k] = c24 * a1 + c12 * b1 + c6 * c1;
        TB[4][k] = c24 * a1 - c12 * b1 + c6 * c1;
        TB[5][k] = c1;
    }
#pragma unroll
    for (int i = 0; i < 6; ++i) {
        float a = TA[i][0], b = TA[i][1], c = TA[i][2];
        float uA[6] = {0.25f * a, -c6 * (a + b + c), -c6 * (a - b + c),
                       c24 * a + c12 * b + c6 * c, c24 * a - c12 * b + c6 * c, c};
        float a1 = TB[i][0], b1 = TB[i][1], c1 = TB[i][2];
        float uB[6] = {0.25f * a1, -c6 * (a1 + b1 + c1), -c6 * (a1 - b1 + c1),
                       c24 * a1 + c12 * b1 + c6 * c1, c24 * a1 - c12 * b1 + c6 * c1, c1};
#pragma unroll
        for (int j = 0; j < 6; ++j) {
            size_t o = ((size_t)((cbase + conv) * 36 + i * 6 + j) * 512 + co) * 512 + ci;
            uint32_t hp, lp;
            split2(uA[j], uB[j], hp, lp);
            *(uint32_t*)&g_Uh[o] = hp;
            *(uint32_t*)&g_Ul[o] = lp;
        }
    }
}

// ---------------------------------------------------------------------------
// fused transpose + F(4,3) input transform for q/k/v
// ---------------------------------------------------------------------------
#define XF_SMEM (256 * 65 * 4)
__global__ void wino_in_qkv_f(const float* __restrict__ q, const float* __restrict__ k,
                              const float* __restrict__ v)
{
    extern __shared__ float sx[];     // [pix][ci] stride 65
    int cig = blockIdx.x;
    int img = blockIdx.y;
    int z   = blockIdx.z;
    int tid = threadIdx.x;
    const float* base = (z == 0) ? q : (z == 1) ? k : v;
    const float* src = base + (size_t)img * 131072 + (size_t)cig * 64 * 256;
    for (int r = 0; r < 64; ++r)
        sx[tid * 65 + r] = src[(size_t)r * 256 + tid];
    __syncthreads();

#pragma unroll
    for (int item2 = 0; item2 < 2; ++item2) {
        int item = item2 * 256 + tid;
        int mloc = item >> 5, cip = item & 31;
        int ty = mloc >> 1, tx = mloc & 1;
        int y0 = 4 * ty - 1, x0 = 4 * tx - 1;
        int cb = 2 * cip;
        int m = img * 16 + mloc;
        int ci = cig * 64 + cb;

        float2 T[6][6];
#pragma unroll
        for (int c = 0; c < 6; ++c) {
            int x = x0 + c;
            float2 X[6];
#pragma unroll
            for (int r = 0; r < 6; ++r) {
                int y = y0 + r;
                bool ok = ((unsigned)y < 32u) && ((unsigned)x < 8u);
                if (ok) {
                    int pix = y * 8 + x;
                    X[r] = make_float2(sx[pix * 65 + cb], sx[pix * 65 + cb + 1]);
                } else X[r] = make_float2(0.f, 0.f);
            }
            T[0][c] = make_float2(4.f*X[0].x - 5.f*X[2].x + X[4].x,
                                  4.f*X[0].y - 5.f*X[2].y + X[4].y);
            T[1][c] = make_float2(-4.f*X[1].x - 4.f*X[2].x + X[3].x + X[4].x,
                                  -4.f*X[1].y - 4.f*X[2].y + X[3].y + X[4].y);
            T[2][c] = make_float2( 4.f*X[1].x - 4.f*X[2].x - X[3].x + X[4].x,
                                   4.f*X[1].y - 4.f*X[2].y - X[3].y + X[4].y);
            T[3][c] = make_float2(-2.f*X[1].x - X[2].x + 2.f*X[3].x + X[4].x,
                                  -2.f*X[1].y - X[2].y + 2.f*X[3].y + X[4].y);
            T[4][c] = make_float2( 2.f*X[1].x - X[2].x - 2.f*X[3].x + X[4].x,
                                   2.f*X[1].y - X[2].y - 2.f*X[3].y + X[4].y);
            T[5][c] = make_float2( 4.f*X[1].x - 5.f*X[3].x + X[5].x,
                                   4.f*X[1].y - 5.f*X[3].y + X[5].y);
        }
#pragma unroll
        for (int i = 0; i < 6; ++i) {
            float2 t0 = T[i][0], t1 = T[i][1], t2 = T[i][2];
            float2 t3 = T[i][3], t4 = T[i][4], t5 = T[i][5];
            float2 d[6];
            d[0] = make_float2(4.f*t0.x - 5.f*t2.x + t4.x, 4.f*t0.y - 5.f*t2.y + t4.y);
            d[1] = make_float2(-4.f*t1.x - 4.f*t2.x + t3.x + t4.x,
                               -4.f*t1.y - 4.f*t2.y + t3.y + t4.y);
            d[2] = make_float2( 4.f*t1.x - 4.f*t2.x - t3.x + t4.x,
                                4.f*t1.y - 4.f*t2.y - t3.y + t4.y);
            d[3] = make_float2(-2.f*t1.x - t2.x + 2.f*t3.x + t4.x,
                               -2.f*t1.y - t2.y + 2.f*t3.y + t4.y);
            d[4] = make_float2( 2.f*t1.x - t2.x - 2.f*t3.x + t4.x,
                                2.f*t1.y - t2.y - 2.f*t3.y + t4.y);
            d[5] = make_float2( 4.f*t1.x - 5.f*t3.x + t5.x,
                                4.f*t1.y - 5.f*t3.y + t5.y);
#pragma unroll
            for (int j = 0; j < 6; ++j) {
                size_t o = ((size_t)(z * 36 + i * 6 + j) * 512 + m) * 512 + ci;
                uint32_t hp, lp;
                split2(d[j].x, d[j].y, hp, lp);
                *(uint32_t*)&g_Vh[o] = hp;
                *(uint32_t*)&g_Vl[o] = lp;
            }
        }
    }
}

// ---------------------------------------------------------------------------
// F(4,3) input transform from g_saf (conv_o path)
// ---------------------------------------------------------------------------
__global__ void wino_in_o43()
{
    int e = blockIdx.x * 256 + threadIdx.x;
    int m = e >> 8, ci = (e & 255) * 2;
    int img = m >> 7, mr = m & 127;
    int ty = mr >> 6, tx = mr & 63;
    const float* src = g_saf + (size_t)img * 1048576 + ci;
    int y0 = 4 * ty - 1, x0 = 4 * tx - 1;
    float2 T[6][6];
#pragma unroll
    for (int c = 0; c < 6; ++c) {
        int x = x0 + c;
        float2 X[6];
#pragma unroll
        for (int r = 0; r < 6; ++r) {
            int y = y0 + r;
            bool ok = ((unsigned)y < 8u) && ((unsigned)x < 256u);
            X[r] = ok ? *(const float2*)&src[(size_t)(y * 256 + x) * 512]
                      : make_float2(0.f, 0.f);
        }
        T[0][c] = make_float2(4.f*X[0].x - 5.f*X[2].x + X[4].x,
                              4.f*X[0].y - 5.f*X[2].y + X[4].y);
        T[1][c] = make_float2(-4.f*X[1].x - 4.f*X[2].x + X[3].x + X[4].x,
                              -4.f*X[1].y - 4.f*X[2].y + X[3].y + X[4].y);
        T[2][c] = make_float2( 4.f*X[1].x - 4.f*X[2].x - X[3].x + X[4].x,
                               4.f*X[1].y - 4.f*X[2].y - X[3].y + X[4].y);
        T[3][c] = make_float2(-2.f*X[1].x - X[2].x + 2.f*X[3].x + X[4].x,
                              -2.f*X[1].y - X[2].y + 2.f*X[3].y + X[4].y);
        T[4][c] = make_float2( 2.f*X[1].x - X[2].x - 2.f*X[3].x + X[4].x,
                               2.f*X[1].y - X[2].y - 2.f*X[3].y + X[4].y);
        T[5][c] = make_float2( 4.f*X[1].x - 5.f*X[3].x + X[5].x,
                               4.f*X[1].y - 5.f*X[3].y + X[5].y);
    }
#pragma unroll
    for (int i = 0; i < 6; ++i) {
        float2 t0 = T[i][0], t1 = T[i][1], t2 = T[i][2];
        float2 t3 = T[i][3], t4 = T[i][4], t5 = T[i][5];
        float2 d[6];
        d[0] = make_float2(4.f*t0.x - 5.f*t2.x + t4.x, 4.f*t0.y - 5.f*t2.y + t4.y);
        d[1] = make_float2(-4.f*t1.x - 4.f*t2.x + t3.x + t4.x,
                           -4.f*t1.y - 4.f*t2.y + t3.y + t4.y);
        d[2] = make_float2( 4.f*t1.x - 4.f*t2.x - t3.x + t4.x,
                            4.f*t1.y - 4.f*t2.y - t3.y + t4.y);
        d[3] = make_float2(-2.f*t1.x - t2.x + 2.f*t3.x + t4.x,
                           -2.f*t1.y - t2.y + 2.f*t3.y + t4.y);
        d[4] = make_float2( 2.f*t1.x - t2.x - 2.f*t3.x + t4.x,
                            2.f*t1.y - t2.y - 2.f*t3.y + t4.y);
        d[5] = make_float2( 4.f*t1.x - 5.f*t3.x + t5.x,
                            4.f*t1.y - 5.f*t3.y + t5.y);
#pragma unroll
        for (int j = 0; j < 6; ++j) {
            size_t o = ((size_t)(i * 6 + j) * 512 + m) * 512 + ci;
            uint32_t hp, lp;
            split2(d[j].x, d[j].y, hp, lp);
            *(uint32_t*)&g_Vh[o] = hp;
            *(uint32_t*)&g_Vl[o] = lp;
        }
    }
}

// ---------------------------------------------------------------------------
// Winograd GEMM: per plane, C[co][tile] = U[co][ci] . V[tile][ci]^T
// ---------------------------------------------------------------------------
__global__ __launch_bounds__(256, 2) void gemm_wino(int ubase)
{
    int zp = blockIdx.z;
    gemm_mb(g_Uh + (size_t)(ubase + zp) * PSZ, g_Ul + (size_t)(ubase + zp) * PSZ,
            g_Vh + (size_t)zp * PSZ, g_Vl + (size_t)zp * PSZ,
            512, 16, g_M + (size_t)zp * PSZ, 512);
}

// ---------------------------------------------------------------------------
// F(4,3) inverse: Y = A^T M A (4x4 from 6x6)
// ---------------------------------------------------------------------------
__device__ __forceinline__ void wino43_inv(const float (&M)[36], float (&Y)[4][4])
{
    float S[4][6];
#pragma unroll
    for (int c = 0; c < 6; ++c) {
        float m0 = M[c], m1 = M[6 + c], m2 = M[12 + c];
        float m3 = M[18 + c], m4 = M[24 + c], m5 = M[30 + c];
        S[0][c] = m0 + m1 + m2 + m3 + m4;
        S[1][c] = m1 - m2 + 2.f * m3 - 2.f * m4;
        S[2][c] = m1 + m2 + 4.f * m3 + 4.f * m4;
        S[3][c] = m1 - m2 + 8.f * m3 - 8.f * m4 + m5;
    }
#pragma unroll
    for (int i = 0; i < 4; ++i) {
        float s0 = S[i][0], s1 = S[i][1], s2 = S[i][2];
        float s3 = S[i][3], s4 = S[i][4], s5 = S[i][5];
        Y[i][0] = s0 + s1 + s2 + s3 + s4;
        Y[i][1] = s1 - s2 + 2.f * s3 - 2.f * s4;
        Y[i][2] = s1 + s2 + 4.f * s3 + 4.f * s4;
        Y[i][3] = s1 - s2 + 8.f * s3 - 8.f * s4 + s5;
    }
}

// qkv inverse; z<2: fused remap -> Q/K bf16 hi/lo; z=2: fp32 y2
__global__ void wino_out_y43(const float* __restrict__ bq, const float* __restrict__ bk,
                             const float* __restrict__ bv)
{
    int blk = blockIdx.x;          // 3072 = 3z * 512co * 2
    int z = blk >> 10;
    int r = blk & 1023;
    int co = r >> 1;
    int m = (r & 1) * 256 + threadIdx.x;
    const float* bias = (z == 0) ? bq : (z == 1) ? bk : bv;
    float M[36];
#pragma unroll
    for (int p = 0; p < 36; ++p)
        M[p] = g_M[(size_t)(z * 36 + p) * PSZ + co * 512 + m];
    float Y[4][4];
    wino43_inv(M, Y);
    float b = bias[co];
    int img = m >> 4, mr = m & 15;
    int ty = mr >> 1, tx = mr & 1;
    if (z == 2) {
        float* dst = g_y2 + ((size_t)img * 512 + co) * 256 + 32 * ty + 4 * tx;
#pragma unroll
        for (int i = 0; i < 4; ++i)
            *(float4*)&dst[8 * i] = make_float4(Y[i][0] + b, Y[i][1] + b,
                                                Y[i][2] + b, Y[i][3] + b);
    } else {
        __nv_bfloat16* oh = z ? g_Kh : g_Qh;
        __nv_bfloat16* ol = z ? g_Kl : g_Ql;
        int hh = img >> 2;
        int nn = (img & 3) * 8 + (co >> 6);
        int d  = (co & 63) * 8 + ty;
        size_t rowo = ((size_t)nn * 512 + d) * 256;
#pragma unroll
        for (int i = 0; i < 4; ++i) {
            int cbase = hh * 32 + 8 * i + 4 * tx;
            uint32_t h0, l0, h1, l1;
            split2(Y[i][0] + b, Y[i][1] + b, h0, l0);
            split2(Y[i][2] + b, Y[i][3] + b, h1, l1);
            *(uint2*)&oh[rowo + cbase] = make_uint2(h0, h1);
            *(uint2*)&ol[rowo + cbase] = make_uint2(l0, l1);
        }
    }
}

__global__ void wino_out_o43(const float* __restrict__ bo, float* __restrict__ out)
{
    int blk = blockIdx.x;          // 1024 = 512co * 2
    int co = blk >> 1;
    int m = (blk & 1) * 256 + threadIdx.x;
    float M[36];
#pragma unroll
    for (int p = 0; p < 36; ++p)
        M[p] = g_M[(size_t)p * PSZ + co * 512 + m];
    float Y[4][4];
    wino43_inv(M, Y);
    float b = bo[co];
    int img = m >> 7, mr = m & 127;
    int ty = mr >> 6, tx = mr & 63;
    float* dst = out + ((size_t)img * 512 + co) * 2048 + (4 * ty) * 256 + 4 * tx;
#pragma unroll
    for (int i = 0; i < 4; ++i)
        *(float4*)&dst[256 * i] = make_float4(Y[i][0] + b, Y[i][1] + b,
                                              Y[i][2] + b, Y[i][3] + b);
}

// ---------------------------------------------------------------------------
// smem-tiled V transpose: g_y2 -> Vt bf16 hi/lo [n][c][dk].
// CTA = (img2, nlo): loads 64 rows x 256 pix coalesced, emits uint4 stores.
// ---------------------------------------------------------------------------
#define VT_SMEM (64 * 257 * 4)
__global__ void remap_V_t()
{
    extern __shared__ float sy[];         // [co2local][pix] stride 257
    int img2 = blockIdx.x & 31;
    int nlo  = blockIdx.x >> 5;
    int tid = threadIdx.x;
    const float* src = g_y2 + (size_t)img2 * 131072 + (size_t)nlo * 64 * 256;
    for (int rw = 0; rw < 64; ++rw)
        sy[rw * 257 + tid] = src[(size_t)rw * 256 + tid];
    __syncthreads();

    int h = img2 >> 2, nhi = img2 & 3;
    int n = nhi * 8 + nlo;
    int dkhi = tid & 63, rg = tid >> 6;
#pragma unroll
    for (int it = 0; it < 8; ++it) {
        int r = it * 4 + rg;
        int c = h * 32 + r;
        uint32_t hp[4], lp[4];
#pragma unroll
        for (int qd = 0; qd < 4; ++qd) {
            float v0 = sy[dkhi * 257 + (2 * qd) * 32 + r];
            float v1 = sy[dkhi * 257 + (2 * qd + 1) * 32 + r];
            split2(v0, v1, hp[qd], lp[qd]);
        }
        size_t o = ((size_t)n * 256 + c) * 512 + dkhi * 8;
        *(uint4*)&g_Vth[o] = make_uint4(hp[0], hp[1], hp[2], hp[3]);
        *(uint4*)&g_Vtl[o] = make_uint4(lp[0], lp[1], lp[2], lp[3]);
    }
}

// ---------------------------------------------------------------------------
// attention GEMMs
// ---------------------------------------------------------------------------
__global__ __launch_bounds__(256, 2) void gemm_scores(float* __restrict__ attn)
{
    int nb = blockIdx.z;
    gemm_mb(g_Qh + (size_t)nb * 131072, g_Ql + (size_t)nb * 131072,
            g_Kh + (size_t)nb * 131072, g_Kl + (size_t)nb * 131072,
            256, 8, attn + (size_t)nb * 262144, 512);
}

// gemm_nnout with fused saf-scatter epilogue (replaces g_On + remap_saf)
__global__ __launch_bounds__(256, 2) void gemm_nnout_saf()
{
    extern __shared__ char smem[];
    uint32_t sb = smem_u32(smem);
    int tid = threadIdx.x, wid = tid >> 5, lane = tid & 31;
    int nb = blockIdx.z;
    int m0 = blockIdx.y * 128, n0 = blockIdx.x * 128;
    int wm = wid & 1, wn = wid >> 1;

    PipeCtx P;
    pipe_init(P, sb, tid,
              g_ath + (size_t)nb * 262144, g_atl + (size_t)nb * 262144,
              g_Vth + (size_t)nb * 131072, g_Vtl + (size_t)nb * 131072,
              m0, n0, 512);

    float acc[16][4];
#pragma unroll
    for (int i = 0; i < 16; ++i)
#pragma unroll
        for (int j = 0; j < 4; ++j) acc[i][j] = 0.f;

    pipe_mainloop(P, 16, acc);

    // stage C tile (128 x 130) then scatter to g_saf layout
    __syncthreads();
    float* sf = (float*)smem;
#pragma unroll
    for (int i = 0; i < 4; ++i) {
        int row = wm * 64 + i * 16 + (lane >> 2);
#pragma unroll
        for (int jj = 0; jj < 4; ++jj) {
            int col = wn * 32 + jj * 8 + (lane & 3) * 2;
            float* d = acc[i * 4 + jj];
            *(float2*)&sf[row * 130 + col]       = make_float2(d[0], d[1]);
            *(float2*)&sf[(row + 8) * 130 + col] = make_float2(d[2], d[3]);
        }
    }
    __syncthreads();

    int b = nb >> 3, s = nb & 7;
    int rr = tid & 31, rg = tid >> 5;
    int hh0 = n0 >> 5;
    float* sab = g_saf + (size_t)b * 1048576;
#pragma unroll
    for (int it = 0; it < 16; ++it) {
        int row = it * 8 + rg;
        int qd = m0 + row;
        int p = s * 256 + (qd >> 4) * 8 + ((qd >> 1) & 7);
        int d2 = (qd & 1) * 256 + rr * 8 + hh0;
        float4 v = make_float4(sf[row * 130 + rr],       sf[row * 130 + 32 + rr],
                               sf[row * 130 + 64 + rr],  sf[row * 130 + 96 + rr]);
        *(float4*)&sab[(size_t)p * 512 + d2] = v;
    }
}

// ---------------------------------------------------------------------------
// softmax over 512-wide rows, in place; also emit bf16 hi/lo
// ---------------------------------------------------------------------------
__global__ void softmax_rows(float* __restrict__ attn)
{
    size_t base = (size_t)blockIdx.x * 512;
    float* p = attn + base;
    int tid = threadIdx.x;
    float v0 = p[tid], v1 = p[tid + 256];
    float m = fmaxf(v0, v1);
#pragma unroll
    for (int o = 16; o; o >>= 1) m = fmaxf(m, __shfl_xor_sync(~0u, m, o));
    __shared__ float sm[8], ss[8];
    if ((tid & 31) == 0) sm[tid >> 5] = m;
    __syncthreads();
    if (tid < 8) {
        float mm = sm[tid];
#pragma unroll
        for (int o = 4; o; o >>= 1) mm = fmaxf(mm, __shfl_xor_sync(0xffu, mm, o));
        if (tid == 0) sm[0] = mm;
    }
    __syncthreads();
    float M = sm[0];
    float e0 = expf(v0 - M), e1 = expf(v1 - M);
    float s = e0 + e1;
#pragma unroll
    for (int o = 16; o; o >>= 1) s += __shfl_xor_sync(~0u, s, o);
    if ((tid & 31) == 0) ss[tid >> 5] = s;
    __syncthreads();
    if (tid < 8) {
        float t2 = ss[tid];
#pragma unroll
        for (int o = 4; o; o >>= 1) t2 += __shfl_xor_sync(0xffu, t2, o);
        if (tid == 0) ss[0] = t2;
    }
    __syncthreads();
    float inv = 1.f / ss[0];
    float a0 = e0 * inv, a1 = e1 * inv;
    p[tid] = a0;
    p[tid + 256] = a1;
    __nv_bfloat16 h0 = __float2bfloat16(a0), h1 = __float2bfloat16(a1);
    g_ath[base + tid]       = h0;
    g_atl[base + tid]       = __float2bfloat16(a0 - __bfloat162float(h0));
    g_ath[base + tid + 256] = h1;
    g_atl[base + tid + 256] = __float2bfloat16(a1 - __bfloat162float(h1));
}

// ---------------------------------------------------------------------------
extern "C" void kernel_launch(void* const* d_in, const int* in_sizes, int n_in,
                              void* d_out, int out_size)
{
    const float* q  = (const float*)d_in[0];
    const float* k  = (const float*)d_in[1];
    const float* v  = (const float*)d_in[2];
    const float* Wq = (const float*)d_in[3];
    const float* bq = (const float*)d_in[4];
    const float* Wk = (const float*)d_in[5];
    const float* bk = (const float*)d_in[6];
    const float* Wv = (const float*)d_in[7];
    const float* bv = (const float*)d_in[8];
    const float* Wo = (const float*)d_in[9];
    const float* bo = (const float*)d_in[10];

    float* y_out    = (float*)d_out;            // (4,512,8,32,8) = 4194304
    float* attn_out = y_out + NELEM;            // (1,32,512,512) = 8388608

    cudaFuncSetAttribute(gemm_wino,      cudaFuncAttributeMaxDynamicSharedMemorySize, SMEM_BYTES);
    cudaFuncSetAttribute(gemm_scores,    cudaFuncAttributeMaxDynamicSharedMemorySize, SMEM_BYTES);
    cudaFuncSetAttribute(gemm_nnout_saf, cudaFuncAttributeMaxDynamicSharedMemorySize, SMEM_BYTES);
    cudaFuncSetAttribute(wino_in_qkv_f,  cudaFuncAttributeMaxDynamicSharedMemorySize, XF_SMEM);
    cudaFuncSetAttribute(remap_V_t,      cudaFuncAttributeMaxDynamicSharedMemorySize, VT_SMEM);

    // launch order: index 3 = gemm_wino (qkv), dominant kernel (profiled)
    prep_wU43<<<1024, 256>>>(Wq, Wk, 0);                             // 0
    prep_wU43<<<1024, 256>>>(Wv, Wo, 2);                             // 1
    wino_in_qkv_f<<<dim3(8, 32, 3), 256, XF_SMEM>>>(q, k, v);        // 2
    gemm_wino<<<dim3(4, 4, 108), 256, SMEM_BYTES>>>(0);              // 3  <- profiled
    wino_out_y43<<<3072, 256>>>(bq, bk, bv);                         // 4
    remap_V_t<<<256, 256, VT_SMEM>>>();                              // 5
    gemm_scores<<<dim3(4, 4, 32), 256, SMEM_BYTES>>>(attn_out);      // 6
    softmax_rows<<<32 * 512, 256>>>(attn_out);                       // 7
    gemm_nnout_saf<<<dim3(2, 4, 32), 256, SMEM_BYTES>>>();           // 8
    wino_in_o43<<<512, 256>>>();                                     // 9
    gemm_wino<<<dim3(4, 4, 36), 256, SMEM_BYTES>>>(108);             // 10
    wino_out_o43<<<1024, 256>>>(bo, y_out);                          // 11
}

// round 16
// speedup vs baseline: 3.5100x; 1.0157x over previous
#include <cuda_runtime.h>
#include <cuda_bf16.h>
#include <cstdint>

#define NELEM 4194304          // 32*512*256 == 4*512*2048
#define PSZ   262144           // 512*512 (one U/V/M plane)

// ---------------------------------------------------------------------------
// device scratch
// ---------------------------------------------------------------------------
__device__ float g_saf[NELEM];           // conv_o input fp32 pixel-major [b][pix][ci]
__device__ __nv_bfloat16 g_Uh[144*PSZ];  // wino weights [conv*36+pos][co][ci]
__device__ __nv_bfloat16 g_Ul[144*PSZ];
__device__ __nv_bfloat16 g_Vh[108*PSZ];  // wino inputs  [plane][tile][ci]
__device__ __nv_bfloat16 g_Vl[108*PSZ];
__device__ float g_M[108*PSZ];           // GEMM out     [plane][co][tile]
__device__ float g_y2[NELEM];            // conv(v) output (32,512,256) fp32
__device__ __nv_bfloat16 g_Qh[NELEM], g_Ql[NELEM];   // [n][d][c], c=h*32+r
__device__ __nv_bfloat16 g_Kh[NELEM], g_Kl[NELEM];
__device__ __nv_bfloat16 g_Vth[NELEM], g_Vtl[NELEM]; // transposed: [n][c][dk]
__device__ __nv_bfloat16 g_ath[2*NELEM], g_atl[2*NELEM]; // attn hi/lo

// ---------------------------------------------------------------------------
// helpers
// ---------------------------------------------------------------------------
__device__ __forceinline__ uint32_t smem_u32(const void* p) {
    uint32_t a;
    asm("{ .reg .u64 t; cvta.to.shared.u64 t, %1; cvt.u32.u64 %0, t; }" : "=r"(a) : "l"(p));
    return a;
}
#define SWZ(o) ((o) ^ (((o) >> 3) & 0x70))
#define CPA(dst, src, sz) \
    asm volatile("cp.async.cg.shared.global [%0], [%1], 16, %2;" \
        :: "r"(dst), "l"(src), "r"(sz) : "memory")
#define LDM4(r, addr) \
    asm volatile("ldmatrix.sync.aligned.m8n8.x4.shared.b16 {%0,%1,%2,%3}, [%4];" \
        : "=r"((r)[0]), "=r"((r)[1]), "=r"((r)[2]), "=r"((r)[3]) : "r"(addr))
#define MMA_BF16(d, a, b0, b1) \
    asm volatile("mma.sync.aligned.m16n8k16.row.col.f32.bf16.bf16.f32 " \
        "{%0,%1,%2,%3}, {%4,%5,%6,%7}, {%8,%9}, {%0,%1,%2,%3};" \
        : "+f"((d)[0]), "+f"((d)[1]), "+f"((d)[2]), "+f"((d)[3]) \
        : "r"((a)[0]), "r"((a)[1]), "r"((a)[2]), "r"((a)[3]), "r"(b0), "r"(b1))
#define WAITP(addr, ph) do { \
    asm volatile("{\n\t.reg .pred P;\n\tWL%=:\n\t" \
        "mbarrier.try_wait.parity.acquire.cta.shared::cta.b64 P, [%0], %1, 0x989680;\n\t" \
        "@P bra.uni WD%=;\n\tbra.uni WL%=;\n\tWD%=:\n\t}" \
        :: "r"(addr), "r"(ph) : "memory"); \
} while (0)

#define STAGE 32768u
#define MBAR_BASE 98304u
#define SMEM_BYTES 98368
#define PROW(r) ((uint32_t)((((r) >> 1) << 7) | (((r) & 1) << 6)))

__device__ __forceinline__ void split2(float v0, float v1, uint32_t& hp, uint32_t& lp) {
    __nv_bfloat16 h0 = __float2bfloat16(v0);
    __nv_bfloat16 h1 = __float2bfloat16(v1);
    __nv_bfloat16 l0 = __float2bfloat16(v0 - __bfloat162float(h0));
    __nv_bfloat16 l1 = __float2bfloat16(v1 - __bfloat162float(h1));
    hp = (uint32_t)*(uint16_t*)&h0 | ((uint32_t)*(uint16_t*)&h1 << 16);
    lp = (uint32_t)*(uint16_t*)&l0 | ((uint32_t)*(uint16_t*)&l1 << 16);
}

// ---------------------------------------------------------------------------
// compute one K32 chunk, warp tile 64x32: D += Ah*Bh + Ah*Bl + Al*Bh
// ---------------------------------------------------------------------------
__device__ __forceinline__ void mma_compute32(uint32_t bs, uint32_t a_rowb,
                                              uint32_t b_rowb, float (&acc)[16][4])
{
#pragma unroll
    for (int s = 0; s < 2; ++s) {
        uint32_t ah[4][4], bb[2][4], blf[2][4];
#pragma unroll
        for (int i = 0; i < 4; ++i)
            LDM4(ah[i], bs + SWZ(a_rowb + i * 1024 + s * 32));
#pragma unroll
        for (int j = 0; j < 2; ++j)
            LDM4(bb[j], bs + 16384u + SWZ(b_rowb + j * 1024 + s * 32));
#pragma unroll
        for (int i = 0; i < 4; ++i)
#pragma unroll
            for (int jj = 0; jj < 4; ++jj)
                MMA_BF16(acc[i * 4 + jj], ah[i],
                         bb[jj >> 1][(jj & 1) * 2], bb[jj >> 1][(jj & 1) * 2 + 1]);
#pragma unroll
        for (int j = 0; j < 2; ++j)
            LDM4(blf[j], bs + 24576u + SWZ(b_rowb + j * 1024 + s * 32));
#pragma unroll
        for (int i = 0; i < 4; ++i)
#pragma unroll
            for (int jj = 0; jj < 4; ++jj)
                MMA_BF16(acc[i * 4 + jj], ah[i],
                         blf[jj >> 1][(jj & 1) * 2], blf[jj >> 1][(jj & 1) * 2 + 1]);
#pragma unroll
        for (int i = 0; i < 4; ++i)
            LDM4(ah[i], bs + 8192u + SWZ(a_rowb + i * 1024 + s * 32));
#pragma unroll
        for (int i = 0; i < 4; ++i)
#pragma unroll
            for (int jj = 0; jj < 4; ++jj)
                MMA_BF16(acc[i * 4 + jj], ah[i],
                         bb[jj >> 1][(jj & 1) * 2], bb[jj >> 1][(jj & 1) * 2 + 1]);
    }
}

// ---------------------------------------------------------------------------
// pipeline state shared by the GEMM bodies
// ---------------------------------------------------------------------------
struct PipeCtx {
    uint32_t sb, stb, a_rowb, b_rowb;
    const char *srcA_h, *srcA_l, *srcB_h, *srcB_l;
    int ps, pph, cs, cph;
};

__device__ __forceinline__ void pipe_init(PipeCtx& P, uint32_t sb, int tid,
    const __nv_bfloat16* Ah, const __nv_bfloat16* Al,
    const __nv_bfloat16* Bh, const __nv_bfloat16* Bl,
    int m0, int n0, int Kdim)
{
    int wid = tid >> 5, lane = tid & 31;
    int wm = wid & 1, wn = wid >> 1;
    int lr = tid >> 1, lh = tid & 1;
    P.sb = sb;
    P.stb = PROW(lr) + lh * 32u;
    P.srcA_h = (const char*)(Ah + (size_t)(m0 + lr) * Kdim + lh * 16);
    P.srcA_l = (const char*)(Al + (size_t)(m0 + lr) * Kdim + lh * 16);
    P.srcB_h = (const char*)(Bh + (size_t)(n0 + lr) * Kdim + lh * 16);
    P.srcB_l = (const char*)(Bl + (size_t)(n0 + lr) * Kdim + lh * 16);
    int arow = wm * 64 + (lane & 15);
    P.a_rowb = PROW(arow) + ((lane & 16) ? 16u : 0u);
    int brow = wn * 32 + (lane & 7) + ((lane & 16) ? 8 : 0);
    P.b_rowb = PROW(brow) + ((lane & 8) ? 16u : 0u);
    if (tid == 0) {
#pragma unroll
        for (int s = 0; s < 3; ++s) {
            asm volatile("mbarrier.init.shared.b64 [%0], %1;"
                         :: "r"(sb + MBAR_BASE + s * 16u), "r"(256) : "memory");
            asm volatile("mbarrier.init.shared.b64 [%0], %1;"
                         :: "r"(sb + MBAR_BASE + s * 16u + 8u), "r"(256) : "memory");
        }
    }
    __syncthreads();
    P.ps = 0; P.pph = 1; P.cs = 0; P.cph = 0;
}

__device__ __forceinline__ void pipe_produce(PipeCtx& P, int itn)
{
    uint32_t fmb = P.sb + MBAR_BASE + (uint32_t)P.ps * 16u;
    WAITP(fmb + 8u, P.pph);
    int cb = itn * 64;
    uint32_t bs = P.sb + (uint32_t)P.ps * STAGE;
    uint32_t s0 = SWZ(P.stb), s1 = SWZ(P.stb + 16u);
    CPA(bs + s0,          P.srcA_h + cb,      16u);
    CPA(bs + s1,          P.srcA_h + cb + 16, 16u);
    CPA(bs + 8192u + s0,  P.srcA_l + cb,      16u);
    CPA(bs + 8192u + s1,  P.srcA_l + cb + 16, 16u);
    CPA(bs + 16384u + s0, P.srcB_h + cb,      16u);
    CPA(bs + 16384u + s1, P.srcB_h + cb + 16, 16u);
    CPA(bs + 24576u + s0, P.srcB_l + cb,      16u);
    CPA(bs + 24576u + s1, P.srcB_l + cb + 16, 16u);
    asm volatile("cp.async.mbarrier.arrive.noinc.shared::cta.b64 [%0];"
                 :: "r"(fmb) : "memory");
    if (++P.ps == 3) { P.ps = 0; P.pph ^= 1; }
}

__device__ __forceinline__ void pipe_mainloop(PipeCtx& P, int nchunk, float (&acc)[16][4])
{
    pipe_produce(P, 0);
    pipe_produce(P, 1);
    for (int it = 0; it < nchunk; ++it) {
        if (it + 2 < nchunk) pipe_produce(P, it + 2);
        uint32_t fmb = P.sb + MBAR_BASE + (uint32_t)P.cs * 16u;
        WAITP(fmb, P.cph);
        mma_compute32(P.sb + (uint32_t)P.cs * STAGE, P.a_rowb, P.b_rowb, acc);
        asm volatile("mbarrier.arrive.shared::cta.b64 _, [%0];"
                     :: "r"(fmb + 8u) : "memory");
        if (++P.cs == 3) { P.cs = 0; P.cph ^= 1; }
    }
}

// ---------------------------------------------------------------------------
// mbarrier-pipelined GEMM with direct row-major epilogue
// ---------------------------------------------------------------------------
__device__ __forceinline__ void gemm_mb(
    const __nv_bfloat16* __restrict__ Ah, const __nv_bfloat16* __restrict__ Al,
    const __nv_bfloat16* __restrict__ Bh, const __nv_bfloat16* __restrict__ Bl,
    int Kdim, int nchunk, float* __restrict__ C, int ldc)
{
    extern __shared__ char smem[];
    uint32_t sb = smem_u32(smem);
    int tid = threadIdx.x, wid = tid >> 5, lane = tid & 31;
    int m0 = blockIdx.y * 128, n0 = blockIdx.x * 128;
    int wm = wid & 1, wn = wid >> 1;

    PipeCtx P;
    pipe_init(P, sb, tid, Ah, Al, Bh, Bl, m0, n0, Kdim);

    float acc[16][4];
#pragma unroll
    for (int i = 0; i < 16; ++i)
#pragma unroll
        for (int j = 0; j < 4; ++j) acc[i][j] = 0.f;

    pipe_mainloop(P, nchunk, acc);

#pragma unroll
    for (int i = 0; i < 4; ++i) {
        int row = m0 + wm * 64 + i * 16 + (lane >> 2);
#pragma unroll
        for (int jj = 0; jj < 4; ++jj) {
            int col = n0 + wn * 32 + jj * 8 + (lane & 3) * 2;
            float* d = acc[i * 4 + jj];
            *(float2*)&C[(size_t)row * ldc + col]       = make_float2(d[0], d[1]);
            *(float2*)&C[(size_t)(row + 8) * ldc + col] = make_float2(d[2], d[3]);
        }
    }
}

// ---------------------------------------------------------------------------
// F(4,3) weight transform, all 4 convs in one launch
// ---------------------------------------------------------------------------
__global__ void prep_wU43(const float* __restrict__ Wq, const float* __restrict__ Wk,
                          const float* __restrict__ Wv, const float* __restrict__ Wo)
{
    int g = blockIdx.x * 256 + threadIdx.x;     // 4conv * 512co * 256cip
    int conv = g >> 17;
    int r = g & 131071;
    int co = r >> 8, ci = (r & 255) * 2;
    const float* W = (conv == 0) ? Wq : (conv == 1) ? Wk : (conv == 2) ? Wv : Wo;
    const float* w = W + (size_t)co * 4608 + ci * 9;
    const float c6 = 1.f / 6.f, c12 = 1.f / 12.f, c24 = 1.f / 24.f;
    float TA[6][3], TB[6][3];
#pragma unroll
    for (int k = 0; k < 3; ++k) {
        float a = w[k], b = w[3 + k], c = w[6 + k];
        TA[0][k] = 0.25f * a;
        TA[1][k] = -c6 * (a + b + c);
        TA[2][k] = -c6 * (a - b + c);
        TA[3][k] = c24 * a + c12 * b + c6 * c;
        TA[4][k] = c24 * a - c12 * b + c6 * c;
        TA[5][k] = c;
        float a1 = w[9 + k], b1 = w[12 + k], c1 = w[15 + k];
        TB[0][k] = 0.25f * a1;
        TB[1][k] = -c6 * (a1 + b1 + c1);
        TB[2][k] = -c6 * (a1 - b1 + c1);
        TB[3][k] = c24 * a1 + c12 * b1 + c6 * c1;
        TB[4][k] = c24 * a1 - c12 * b1 + c6 * c1;
        TB[5][k] = c1;
    }
#pragma unroll
    for (int i = 0; i < 6; ++i) {
        float a = TA[i][0], b = TA[i][1], c = TA[i][2];
        float uA[6] = {0.25f * a, -c6 * (a + b + c), -c6 * (a - b + c),
                       c24 * a + c12 * b + c6 * c, c24 * a - c12 * b + c6 * c, c};
        float a1 = TB[i][0], b1 = TB[i][1], c1 = TB[i][2];
        float uB[6] = {0.25f * a1, -c6 * (a1 + b1 + c1), -c6 * (a1 - b1 + c1),
                       c24 * a1 + c12 * b1 + c6 * c1, c24 * a1 - c12 * b1 + c6 * c1, c1};
#pragma unroll
        for (int j = 0; j < 6; ++j) {
            size_t o = ((size_t)(conv * 36 + i * 6 + j) * 512 + co) * 512 + ci;
            uint32_t hp, lp;
            split2(uA[j], uB[j], hp, lp);
            *(uint32_t*)&g_Uh[o] = hp;
            *(uint32_t*)&g_Ul[o] = lp;
        }
    }
}

// ---------------------------------------------------------------------------
// fused transpose + F(4,3) input transform for q/k/v
// ---------------------------------------------------------------------------
#define XF_SMEM (256 * 65 * 4)
__global__ void wino_in_qkv_f(const float* __restrict__ q, const float* __restrict__ k,
                              const float* __restrict__ v)
{
    extern __shared__ float sx[];     // [pix][ci] stride 65
    int cig = blockIdx.x;
    int img = blockIdx.y;
    int z   = blockIdx.z;
    int tid = threadIdx.x;
    const float* base = (z == 0) ? q : (z == 1) ? k : v;
    const float* src = base + (size_t)img * 131072 + (size_t)cig * 64 * 256;
    for (int r = 0; r < 64; ++r)
        sx[tid * 65 + r] = src[(size_t)r * 256 + tid];
    __syncthreads();

#pragma unroll
    for (int item2 = 0; item2 < 2; ++item2) {
        int item = item2 * 256 + tid;
        int mloc = item >> 5, cip = item & 31;
        int ty = mloc >> 1, tx = mloc & 1;
        int y0 = 4 * ty - 1, x0 = 4 * tx - 1;
        int cb = 2 * cip;
        int m = img * 16 + mloc;
        int ci = cig * 64 + cb;

        float2 T[6][6];
#pragma unroll
        for (int c = 0; c < 6; ++c) {
            int x = x0 + c;
            float2 X[6];
#pragma unroll
            for (int r = 0; r < 6; ++r) {
                int y = y0 + r;
                bool ok = ((unsigned)y < 32u) && ((unsigned)x < 8u);
                if (ok) {
                    int pix = y * 8 + x;
                    X[r] = make_float2(sx[pix * 65 + cb], sx[pix * 65 + cb + 1]);
                } else X[r] = make_float2(0.f, 0.f);
            }
            T[0][c] = make_float2(4.f*X[0].x - 5.f*X[2].x + X[4].x,
                                  4.f*X[0].y - 5.f*X[2].y + X[4].y);
            T[1][c] = make_float2(-4.f*X[1].x - 4.f*X[2].x + X[3].x + X[4].x,
                                  -4.f*X[1].y - 4.f*X[2].y + X[3].y + X[4].y);
            T[2][c] = make_float2( 4.f*X[1].x - 4.f*X[2].x - X[3].x + X[4].x,
                                   4.f*X[1].y - 4.f*X[2].y - X[3].y + X[4].y);
            T[3][c] = make_float2(-2.f*X[1].x - X[2].x + 2.f*X[3].x + X[4].x,
                                  -2.f*X[1].y - X[2].y + 2.f*X[3].y + X[4].y);
            T[4][c] = make_float2( 2.f*X[1].x - X[2].x - 2.f*X[3].x + X[4].x,
                                   2.f*X[1].y - X[2].y - 2.f*X[3].y + X[4].y);
            T[5][c] = make_float2( 4.f*X[1].x - 5.f*X[3].x + X[5].x,
                                   4.f*X[1].y - 5.f*X[3].y + X[5].y);
        }
#pragma unroll
        for (int i = 0; i < 6; ++i) {
            float2 t0 = T[i][0], t1 = T[i][1], t2 = T[i][2];
            float2 t3 = T[i][3], t4 = T[i][4], t5 = T[i][5];
            float2 d[6];
            d[0] = make_float2(4.f*t0.x - 5.f*t2.x + t4.x, 4.f*t0.y - 5.f*t2.y + t4.y);
            d[1] = make_float2(-4.f*t1.x - 4.f*t2.x + t3.x + t4.x,
                               -4.f*t1.y - 4.f*t2.y + t3.y + t4.y);
            d[2] = make_float2( 4.f*t1.x - 4.f*t2.x - t3.x + t4.x,
                                4.f*t1.y - 4.f*t2.y - t3.y + t4.y);
            d[3] = make_float2(-2.f*t1.x - t2.x + 2.f*t3.x + t4.x,
                               -2.f*t1.y - t2.y + 2.f*t3.y + t4.y);
            d[4] = make_float2( 2.f*t1.x - t2.x - 2.f*t3.x + t4.x,
                                2.f*t1.y - t2.y - 2.f*t3.y + t4.y);
            d[5] = make_float2( 4.f*t1.x - 5.f*t3.x + t5.x,
                                4.f*t1.y - 5.f*t3.y + t5.y);
#pragma unroll
            for (int j = 0; j < 6; ++j) {
                size_t o = ((size_t)(z * 36 + i * 6 + j) * 512 + m) * 512 + ci;
                uint32_t hp, lp;
                split2(d[j].x, d[j].y, hp, lp);
                *(uint32_t*)&g_Vh[o] = hp;
                *(uint32_t*)&g_Vl[o] = lp;
            }
        }
    }
}

// ---------------------------------------------------------------------------
// F(4,3) input transform from g_saf (conv_o path)
// ---------------------------------------------------------------------------
__global__ void wino_in_o43()
{
    int e = blockIdx.x * 256 + threadIdx.x;
    int m = e >> 8, ci = (e & 255) * 2;
    int img = m >> 7, mr = m & 127;
    int ty = mr >> 6, tx = mr & 63;
    const float* src = g_saf + (size_t)img * 1048576 + ci;
    int y0 = 4 * ty - 1, x0 = 4 * tx - 1;
    float2 T[6][6];
#pragma unroll
    for (int c = 0; c < 6; ++c) {
        int x = x0 + c;
        float2 X[6];
#pragma unroll
        for (int r = 0; r < 6; ++r) {
            int y = y0 + r;
            bool ok = ((unsigned)y < 8u) && ((unsigned)x < 256u);
            X[r] = ok ? *(const float2*)&src[(size_t)(y * 256 + x) * 512]
                      : make_float2(0.f, 0.f);
        }
        T[0][c] = make_float2(4.f*X[0].x - 5.f*X[2].x + X[4].x,
                              4.f*X[0].y - 5.f*X[2].y + X[4].y);
        T[1][c] = make_float2(-4.f*X[1].x - 4.f*X[2].x + X[3].x + X[4].x,
                              -4.f*X[1].y - 4.f*X[2].y + X[3].y + X[4].y);
        T[2][c] = make_float2( 4.f*X[1].x - 4.f*X[2].x - X[3].x + X[4].x,
                               4.f*X[1].y - 4.f*X[2].y - X[3].y + X[4].y);
        T[3][c] = make_float2(-2.f*X[1].x - X[2].x + 2.f*X[3].x + X[4].x,
                              -2.f*X[1].y - X[2].y + 2.f*X[3].y + X[4].y);
        T[4][c] = make_float2( 2.f*X[1].x - X[2].x - 2.f*X[3].x + X[4].x,
                               2.f*X[1].y - X[2].y - 2.f*X[3].y + X[4].y);
        T[5][c] = make_float2( 4.f*X[1].x - 5.f*X[3].x + X[5].x,
                               4.f*X[1].y - 5.f*X[3].y + X[5].y);
    }
#pragma unroll
    for (int i = 0; i < 6; ++i) {
        float2 t0 = T[i][0], t1 = T[i][1], t2 = T[i][2];
        float2 t3 = T[i][3], t4 = T[i][4], t5 = T[i][5];
        float2 d[6];
        d[0] = make_float2(4.f*t0.x - 5.f*t2.x + t4.x, 4.f*t0.y - 5.f*t2.y + t4.y);
        d[1] = make_float2(-4.f*t1.x - 4.f*t2.x + t3.x + t4.x,
                           -4.f*t1.y - 4.f*t2.y + t3.y + t4.y);
        d[2] = make_float2( 4.f*t1.x - 4.f*t2.x - t3.x + t4.x,
                            4.f*t1.y - 4.f*t2.y - t3.y + t4.y);
        d[3] = make_float2(-2.f*t1.x - t2.x + 2.f*t3.x + t4.x,
                           -2.f*t1.y - t2.y + 2.f*t3.y + t4.y);
        d[4] = make_float2( 2.f*t1.x - t2.x - 2.f*t3.x + t4.x,
                            2.f*t1.y - t2.y - 2.f*t3.y + t4.y);
        d[5] = make_float2( 4.f*t1.x - 5.f*t3.x + t5.x,
                            4.f*t1.y - 5.f*t3.y + t5.y);
#pragma unroll
        for (int j = 0; j < 6; ++j) {
            size_t o = ((size_t)(i * 6 + j) * 512 + m) * 512 + ci;
            uint32_t hp, lp;
            split2(d[j].x, d[j].y, hp, lp);
            *(uint32_t*)&g_Vh[o] = hp;
            *(uint32_t*)&g_Vl[o] = lp;
        }
    }
}

// ---------------------------------------------------------------------------
// Winograd GEMM: per plane, C[co][tile] = U[co][ci] . V[tile][ci]^T
// ---------------------------------------------------------------------------
__global__ __launch_bounds__(256, 2) void gemm_wino(int ubase)
{
    int zp = blockIdx.z;
    gemm_mb(g_Uh + (size_t)(ubase + zp) * PSZ, g_Ul + (size_t)(ubase + zp) * PSZ,
            g_Vh + (size_t)zp * PSZ, g_Vl + (size_t)zp * PSZ,
            512, 16, g_M + (size_t)zp * PSZ, 512);
}

// ---------------------------------------------------------------------------
// F(4,3) inverse: Y = A^T M A (4x4 from 6x6)
// ---------------------------------------------------------------------------
__device__ __forceinline__ void wino43_inv(const float (&M)[36], float (&Y)[4][4])
{
    float S[4][6];
#pragma unroll
    for (int c = 0; c < 6; ++c) {
        float m0 = M[c], m1 = M[6 + c], m2 = M[12 + c];
        float m3 = M[18 + c], m4 = M[24 + c], m5 = M[30 + c];
        S[0][c] = m0 + m1 + m2 + m3 + m4;
        S[1][c] = m1 - m2 + 2.f * m3 - 2.f * m4;
        S[2][c] = m1 + m2 + 4.f * m3 + 4.f * m4;
        S[3][c] = m1 - m2 + 8.f * m3 - 8.f * m4 + m5;
    }
#pragma unroll
    for (int i = 0; i < 4; ++i) {
        float s0 = S[i][0], s1 = S[i][1], s2 = S[i][2];
        float s3 = S[i][3], s4 = S[i][4], s5 = S[i][5];
        Y[i][0] = s0 + s1 + s2 + s3 + s4;
        Y[i][1] = s1 - s2 + 2.f * s3 - 2.f * s4;
        Y[i][2] = s1 + s2 + 4.f * s3 + 4.f * s4;
        Y[i][3] = s1 - s2 + 8.f * s3 - 8.f * s4 + s5;
    }
}

// qkv inverse; z<2: fused remap -> Q/K bf16 hi/lo; z=2: fp32 y2
__global__ void wino_out_y43(const float* __restrict__ bq, const float* __restrict__ bk,
                             const float* __restrict__ bv)
{
    int blk = blockIdx.x;          // 3072 = 3z * 512co * 2
    int z = blk >> 10;
    int r = blk & 1023;
    int co = r >> 1;
    int m = (r & 1) * 256 + threadIdx.x;
    const float* bias = (z == 0) ? bq : (z == 1) ? bk : bv;
    float M[36];
#pragma unroll
    for (int p = 0; p < 36; ++p)
        M[p] = g_M[(size_t)(z * 36 + p) * PSZ + co * 512 + m];
    float Y[4][4];
    wino43_inv(M, Y);
    float b = bias[co];
    int img = m >> 4, mr = m & 15;
    int ty = mr >> 1, tx = mr & 1;
    if (z == 2) {
        float* dst = g_y2 + ((size_t)img * 512 + co) * 256 + 32 * ty + 4 * tx;
#pragma unroll
        for (int i = 0; i < 4; ++i)
            *(float4*)&dst[8 * i] = make_float4(Y[i][0] + b, Y[i][1] + b,
                                                Y[i][2] + b, Y[i][3] + b);
    } else {
        __nv_bfloat16* oh = z ? g_Kh : g_Qh;
        __nv_bfloat16* ol = z ? g_Kl : g_Ql;
        int hh = img >> 2;
        int nn = (img & 3) * 8 + (co >> 6);
        int d  = (co & 63) * 8 + ty;
        size_t rowo = ((size_t)nn * 512 + d) * 256;
#pragma unroll
        for (int i = 0; i < 4; ++i) {
            int cbase = hh * 32 + 8 * i + 4 * tx;
            uint32_t h0, l0, h1, l1;
            split2(Y[i][0] + b, Y[i][1] + b, h0, l0);
            split2(Y[i][2] + b, Y[i][3] + b, h1, l1);
            *(uint2*)&oh[rowo + cbase] = make_uint2(h0, h1);
            *(uint2*)&ol[rowo + cbase] = make_uint2(l0, l1);
        }
    }
}

__global__ void wino_out_o43(const float* __restrict__ bo, float* __restrict__ out)
{
    int blk = blockIdx.x;          // 1024 = 512co * 2
    int co = blk >> 1;
    int m = (blk & 1) * 256 + threadIdx.x;
    float M[36];
#pragma unroll
    for (int p = 0; p < 36; ++p)
        M[p] = g_M[(size_t)p * PSZ + co * 512 + m];
    float Y[4][4];
    wino43_inv(M, Y);
    float b = bo[co];
    int img = m >> 7, mr = m & 127;
    int ty = mr >> 6, tx = mr & 63;
    float* dst = out + ((size_t)img * 512 + co) * 2048 + (4 * ty) * 256 + 4 * tx;
#pragma unroll
    for (int i = 0; i < 4; ++i)
        *(float4*)&dst[256 * i] = make_float4(Y[i][0] + b, Y[i][1] + b,
                                              Y[i][2] + b, Y[i][3] + b);
}

// ---------------------------------------------------------------------------
// smem-tiled V transpose: g_y2 -> Vt bf16 hi/lo [n][c][dk]
// ---------------------------------------------------------------------------
#define VT_SMEM (64 * 257 * 4)
__global__ void remap_V_t()
{
    extern __shared__ float sy[];         // [co2local][pix] stride 257
    int img2 = blockIdx.x & 31;
    int nlo  = blockIdx.x >> 5;
    int tid = threadIdx.x;
    const float* src = g_y2 + (size_t)img2 * 131072 + (size_t)nlo * 64 * 256;
    for (int rw = 0; rw < 64; ++rw)
        sy[rw * 257 + tid] = src[(size_t)rw * 256 + tid];
    __syncthreads();

    int h = img2 >> 2, nhi = img2 & 3;
    int n = nhi * 8 + nlo;
    int dkhi = tid & 63, rg = tid >> 6;
#pragma unroll
    for (int it = 0; it < 8; ++it) {
        int r = it * 4 + rg;
        int c = h * 32 + r;
        uint32_t hp[4], lp[4];
#pragma unroll
        for (int qd = 0; qd < 4; ++qd) {
            float v0 = sy[dkhi * 257 + (2 * qd) * 32 + r];
            float v1 = sy[dkhi * 257 + (2 * qd + 1) * 32 + r];
            split2(v0, v1, hp[qd], lp[qd]);
        }
        size_t o = ((size_t)n * 256 + c) * 512 + dkhi * 8;
        *(uint4*)&g_Vth[o] = make_uint4(hp[0], hp[1], hp[2], hp[3]);
        *(uint4*)&g_Vtl[o] = make_uint4(lp[0], lp[1], lp[2], lp[3]);
    }
}

// ---------------------------------------------------------------------------
// attention GEMMs
// ---------------------------------------------------------------------------
__global__ __launch_bounds__(256, 2) void gemm_scores(float* __restrict__ attn)
{
    int nb = blockIdx.z;
    gemm_mb(g_Qh + (size_t)nb * 131072, g_Ql + (size_t)nb * 131072,
            g_Kh + (size_t)nb * 131072, g_Kl + (size_t)nb * 131072,
            256, 8, attn + (size_t)nb * 262144, 512);
}

// gemm_nnout with fused saf-scatter epilogue
__global__ __launch_bounds__(256, 2) void gemm_nnout_saf()
{
    extern __shared__ char smem[];
    uint32_t sb = smem_u32(smem);
    int tid = threadIdx.x, wid = tid >> 5, lane = tid & 31;
    int nb = blockIdx.z;
    int m0 = blockIdx.y * 128, n0 = blockIdx.x * 128;
    int wm = wid & 1, wn = wid >> 1;

    PipeCtx P;
    pipe_init(P, sb, tid,
              g_ath + (size_t)nb * 262144, g_atl + (size_t)nb * 262144,
              g_Vth + (size_t)nb * 131072, g_Vtl + (size_t)nb * 131072,
              m0, n0, 512);

    float acc[16][4];
#pragma unroll
    for (int i = 0; i < 16; ++i)
#pragma unroll
        for (int j = 0; j < 4; ++j) acc[i][j] = 0.f;

    pipe_mainloop(P, 16, acc);

    __syncthreads();
    float* sf = (float*)smem;
#pragma unroll
    for (int i = 0; i < 4; ++i) {
        int row = wm * 64 + i * 16 + (lane >> 2);
#pragma unroll
        for (int jj = 0; jj < 4; ++jj) {
            int col = wn * 32 + jj * 8 + (lane & 3) * 2;
            float* d = acc[i * 4 + jj];
            *(float2*)&sf[row * 130 + col]       = make_float2(d[0], d[1]);
            *(float2*)&sf[(row + 8) * 130 + col] = make_float2(d[2], d[3]);
        }
    }
    __syncthreads();

    int b = nb >> 3, s = nb & 7;
    int rr = tid & 31, rg = tid >> 5;
    int hh0 = n0 >> 5;
    float* sab = g_saf + (size_t)b * 1048576;
#pragma unroll
    for (int it = 0; it < 16; ++it) {
        int row = it * 8 + rg;
        int qd = m0 + row;
        int p = s * 256 + (qd >> 4) * 8 + ((qd >> 1) & 7);
        int d2 = (qd & 1) * 256 + rr * 8 + hh0;
        float4 v = make_float4(sf[row * 130 + rr],       sf[row * 130 + 32 + rr],
                               sf[row * 130 + 64 + rr],  sf[row * 130 + 96 + rr]);
        *(float4*)&sab[(size_t)p * 512 + d2] = v;
    }
}

// ---------------------------------------------------------------------------
// softmax: one 512-wide row per 128-thread block, float4 path
// ---------------------------------------------------------------------------
__global__ void softmax_rows(float* __restrict__ attn)
{
    size_t base = (size_t)blockIdx.x * 512;
    float* p = attn + base;
    int tid = threadIdx.x;                 // 0..127
    int wid = tid >> 5, lane = tid & 31;
    float4 v = *(float4*)&p[tid * 4];
    float m = fmaxf(fmaxf(v.x, v.y), fmaxf(v.z, v.w));
#pragma unroll
    for (int o = 16; o; o >>= 1) m = fmaxf(m, __shfl_xor_sync(~0u, m, o));
    __shared__ float sm[4], ss[4];
    if (lane == 0) sm[wid] = m;
    __syncthreads();
    float M = fmaxf(fmaxf(sm[0], sm[1]), fmaxf(sm[2], sm[3]));
    float4 e = make_float4(expf(v.x - M), expf(v.y - M), expf(v.z - M), expf(v.w - M));
    float s = e.x + e.y + e.z + e.w;
#pragma unroll
    for (int o = 16; o; o >>= 1) s += __shfl_xor_sync(~0u, s, o);
    if (lane == 0) ss[wid] = s;
    __syncthreads();
    float inv = 1.f / (ss[0] + ss[1] + ss[2] + ss[3]);
    float4 a = make_float4(e.x * inv, e.y * inv, e.z * inv, e.w * inv);
    *(float4*)&p[tid * 4] = a;
    uint32_t h0, l0, h1, l1;
    split2(a.x, a.y, h0, l0);
    split2(a.z, a.w, h1, l1);
    *(uint2*)&g_ath[base + tid * 4] = make_uint2(h0, h1);
    *(uint2*)&g_atl[base + tid * 4] = make_uint2(l0, l1);
}

// ---------------------------------------------------------------------------
extern "C" void kernel_launch(void* const* d_in, const int* in_sizes, int n_in,
                              void* d_out, int out_size)
{
    const float* q  = (const float*)d_in[0];
    const float* k  = (const float*)d_in[1];
    const float* v  = (const float*)d_in[2];
    const float* Wq = (const float*)d_in[3];
    const float* bq = (const float*)d_in[4];
    const float* Wk = (const float*)d_in[5];
    const float* bk = (const float*)d_in[6];
    const float* Wv = (const float*)d_in[7];
    const float* bv = (const float*)d_in[8];
    const float* Wo = (const float*)d_in[9];
    const float* bo = (const float*)d_in[10];

    float* y_out    = (float*)d_out;            // (4,512,8,32,8) = 4194304
    float* attn_out = y_out + NELEM;            // (1,32,512,512) = 8388608

    cudaFuncSetAttribute(gemm_wino,      cudaFuncAttributeMaxDynamicSharedMemorySize, SMEM_BYTES);
    cudaFuncSetAttribute(gemm_scores,    cudaFuncAttributeMaxDynamicSharedMemorySize, SMEM_BYTES);
    cudaFuncSetAttribute(gemm_nnout_saf, cudaFuncAttributeMaxDynamicSharedMemorySize, SMEM_BYTES);
    cudaFuncSetAttribute(wino_in_qkv_f,  cudaFuncAttributeMaxDynamicSharedMemorySize, XF_SMEM);
    cudaFuncSetAttribute(remap_V_t,      cudaFuncAttributeMaxDynamicSharedMemorySize, VT_SMEM);

    // launch order: index 3 = wino_out_y43 (never profiled before)
    prep_wU43<<<2048, 256>>>(Wq, Wk, Wv, Wo);                        // 0
    wino_in_qkv_f<<<dim3(8, 32, 3), 256, XF_SMEM>>>(q, k, v);        // 1
    gemm_wino<<<dim3(4, 4, 108), 256, SMEM_BYTES>>>(0);              // 2
    wino_out_y43<<<3072, 256>>>(bq, bk, bv);                         // 3  <- profiled
    remap_V_t<<<256, 256, VT_SMEM>>>();                              // 4
    gemm_scores<<<dim3(4, 4, 32), 256, SMEM_BYTES>>>(attn_out);      // 5
    softmax_rows<<<32 * 512, 128>>>(attn_out);                       // 6
    gemm_nnout_saf<<<dim3(2, 4, 32), 256, SMEM_BYTES>>>();           // 7
    wino_in_o43<<<512, 256>>>();                                     // 8
    gemm_wino<<<dim3(4, 4, 36), 256, SMEM_BYTES>>>(108);             // 9
    wino_out_o43<<<1024, 256>>>(bo, y_out);                          // 10
}